// round 7
// baseline (speedup 1.0000x reference)
#include <cuda_runtime.h>
#include <cuda_bf16.h>
#include <math.h>
#include <stdint.h>

// ---------------------------------------------------------------------------
// Problem constants
// ---------------------------------------------------------------------------
namespace {
constexpr int nB = 2, nS = 2048, nH = 2048, nNH = 16, nNKV = 4, nDH = 128;
constexpr int nE = 8, nMI = 1408;
constexpr int nT = nB * nS;          // 4096 tokens
constexpr int GR = nT * 2;           // 8192 gathered (token, expert) rows
constexpr int MAXTILE = 72;          // ceil(8192/128) + 8 experts padding
constexpr float RMS_EPS = 1e-6f;
constexpr float QK_SCALE = 0.088388347648318447f;  // 1/sqrt(128)
// GEMM smem: 2 bufs x (A 128x36 + B 256x36) floats
constexpr int GA0 = 0, GA1 = 4608, GB0 = 9216, GB1 = 18432;
constexpr int SMEM_FLOATS = 27648;
constexpr int SMEM_BYTES = SMEM_FLOATS * 4;        // 110592

// flash attention smem layout (float indices)
constexpr int FA_QS = 0;                 // Q  [128][132]
constexpr int FA_KS = 16896;             // K  [64][132]
constexpr int FA_VS = 25344;             // V  2 x [64][136]
constexpr int FA_PS = 42752;             // P  [128][68]
constexpr int FA_RM = 51456;             // rowmax exchange [128][2]
constexpr int FA_RL = 51712;             // rowsum exchange [128][2]
constexpr int FA_FLOATS = 51968;
constexpr int FA_BYTES = FA_FLOATS * 4;  // 207872
}

// ---------------------------------------------------------------------------
// Scratch (device globals)
// ---------------------------------------------------------------------------
__device__ float g_xn    [(size_t)nT * nH];   // rmsnorm1 out; later: unrounded rmsnorm2 out
__device__ float g_q     [(size_t)nT * nNH * nDH];
__device__ float g_k     [(size_t)nT * nNKV * nDH];
__device__ float g_v     [(size_t)nT * nNKV * nDH];
__device__ float g_attn  [(size_t)nT * nH];
__device__ float g_hidden[(size_t)nT * nH];
__device__ float g_x2    [(size_t)nT * nH];
__device__ int   g_topi  [nT * 2];
__device__ float g_topw  [nT * 2];
__device__ int   g_counts[nE];
__device__ int   g_fill  [nE];
__device__ int   g_coff  [nE + 1];
__device__ int   g_tileE [MAXTILE];
__device__ int   g_tileR0[MAXTILE];
__device__ int   g_toklist[GR];
__device__ int   g_slot  [nT * 2];
__device__ float g_gbuf  [(size_t)GR * nMI];
__device__ float g_ubuf  [(size_t)GR * nMI];
__device__ float g_part  [(size_t)GR * nH];
// transposed weights [N][K] K-major (tf32-rounded)
__device__ float g_wqT [(size_t)(nNH * nDH) * nH];
__device__ float g_wkT [(size_t)(nNKV * nDH) * nH];
__device__ float g_wvT [(size_t)(nNKV * nDH) * nH];
__device__ float g_woT [(size_t)nH * nH];
__device__ float g_gwT [(size_t)nE * nMI * nH];
__device__ float g_uwT [(size_t)nE * nMI * nH];
__device__ float g_dwT [(size_t)nE * nH * nMI];

// ---------------------------------------------------------------------------
// Helpers
// ---------------------------------------------------------------------------
__device__ __forceinline__ uint32_t smem_to_u32(const void* p) {
    uint32_t a;
    asm("{ .reg .u64 t; cvta.to.shared.u64 t, %1; cvt.u32.u64 %0, t; }" : "=r"(a) : "l"(p));
    return a;
}
__device__ __forceinline__ float rntf(float x) {
    uint32_t r;
    asm("cvt.rna.tf32.f32 %0, %1;" : "=r"(r) : "f"(x));
    return __uint_as_float(r);
}
__device__ __forceinline__ void mma_tf32(float* d, const uint32_t* a, const uint32_t* b) {
    asm volatile("mma.sync.aligned.m16n8k8.row.col.f32.tf32.tf32.f32 "
        "{%0,%1,%2,%3}, {%4,%5,%6,%7}, {%8,%9}, {%0,%1,%2,%3};"
        : "+f"(d[0]), "+f"(d[1]), "+f"(d[2]), "+f"(d[3])
        : "r"(a[0]), "r"(a[1]), "r"(a[2]), "r"(a[3]), "r"(b[0]), "r"(b[1]));
}
__device__ __forceinline__ float warpSum(float v) {
    #pragma unroll
    for (int o = 16; o; o >>= 1) v += __shfl_xor_sync(0xffffffffu, v, o);
    return v;
}

// ---------------------------------------------------------------------------
// tf32 mma.sync GEMM: inputs PRE-ROUNDED to tf32 grid; no cvt inside.
// C[M,N] = alpha * A[M,K](K-major) x B[N,K](K-major) (+res)
// CTA tile 128x256, K-chunks of 32, 256 threads (8 warps 2m x 4n, warp 64x64).
// ---------------------------------------------------------------------------
struct GArgs {
    const float* A; const float* B; float* C; const float* res;
    long long lda, ldb, ldc;
    int M, N, K;
    float alpha;
    int mode;   // 0 normal, 1 moe gather-A, 2 moe no-gather
    int roundC; // round outputs to tf32 grid (feeds another GEMM)
    long long sAb, sAh, sBb, sBh, sCb, sCh;
    int zmod, groups;
};

__global__ void __launch_bounds__(256, 1) tc_gemm(GArgs g) {
    extern __shared__ float dsmf[];
    const int tid = threadIdx.x, lane = tid & 31, wid = tid >> 5;
    const int wm = wid & 1, wn = wid >> 1;
    const int gq = lane >> 2, qq = lane & 3;

    int m0, Mb;
    const float* Ab = g.A;
    const float* Bb = g.B;
    float* Cb = g.C;
    const float* resb = g.res;
    if (g.mode >= 1) {
        int e = g_tileE[blockIdx.y];
        if (e < 0) return;
        m0 = g_tileR0[blockIdx.y];
        Mb = g_coff[e + 1];
        Bb += (size_t)e * g.N * g.K;
    } else {
        m0 = blockIdx.y * 128;
        Mb = g.M;
        int bz = blockIdx.z;
        int b = bz / g.zmod, h = bz % g.zmod;
        Ab += (size_t)b * g.sAb + (size_t)h * g.sAh;
        Bb += (size_t)b * g.sBb + (size_t)(h / g.groups) * g.sBh;
        Cb += (size_t)b * g.sCb + (size_t)h * g.sCh;
        if (resb) resb += (size_t)b * g.sCb + (size_t)h * g.sCh;
    }
    const int n0 = blockIdx.x * 256;
    const int ntile = min(256, g.N - n0);

    __shared__ int rt[128];
    if (tid < 128) {
        int m = m0 + tid;
        int r = (m < Mb) ? m : -1;
        if (g.mode == 1 && r >= 0) r = g_toklist[r];
        rt[tid] = r;
    }
    __syncthreads();

    const uint32_t sbase = smem_to_u32(dsmf);
    const int NC = g.K >> 5;

    auto issue = [&](int c, int s) {
        const int k0 = c << 5;
        // A: 128 rows x 32 floats (4 passes)
        #pragma unroll
        for (int p = 0; p < 4; p++) {
            int idx = p * 256 + tid;
            int row = idx >> 3, c4 = idx & 7;
            int r = rt[row];
            const float* src = (r >= 0 ? Ab + (size_t)r * g.lda : Ab) + k0 + c4 * 4;
            uint32_t dst = sbase + (uint32_t)((s ? GA1 : GA0) + row * 36 + c4 * 4) * 4u;
            int sz = (r >= 0) ? 16 : 0;
            asm volatile("cp.async.cg.shared.global [%0], [%1], 16, %2;"
                         :: "r"(dst), "l"(src), "r"(sz) : "memory");
        }
        // B: 256 rows x 32 floats (8 passes), zero-fill rows >= ntile
        #pragma unroll
        for (int p = 0; p < 8; p++) {
            int idx = p * 256 + tid;
            int row = idx >> 3, c4 = idx & 7;
            const float* src = Bb + (size_t)(n0 + row) * g.ldb + k0 + c4 * 4;
            uint32_t dst = sbase + (uint32_t)((s ? GB1 : GB0) + row * 36 + c4 * 4) * 4u;
            int sz = (row < ntile) ? 16 : 0;
            asm volatile("cp.async.cg.shared.global [%0], [%1], 16, %2;"
                         :: "r"(dst), "l"(src), "r"(sz) : "memory");
        }
    };

    float acc[4][8][4] = {};

    issue(0, 0);
    asm volatile("cp.async.commit_group;" ::: "memory");
    if (NC > 1) issue(1, 1);
    asm volatile("cp.async.commit_group;" ::: "memory");

    const uint32_t* dsum = reinterpret_cast<const uint32_t*>(dsmf);

    for (int c = 0; c < NC; c++) {
        const int s = c & 1;
        asm volatile("cp.async.wait_group 1;" ::: "memory");
        __syncthreads();
        const uint32_t* Asm = dsum + (s ? GA1 : GA0);
        const uint32_t* Bsm = dsum + (s ? GB1 : GB0);
        #pragma unroll
        for (int kk = 0; kk < 4; kk++) {
            const int kb = kk * 8;
            uint32_t af[4][4];
            #pragma unroll
            for (int mt = 0; mt < 4; mt++) {
                int r0 = wm * 64 + mt * 16 + gq;
                af[mt][0] = Asm[r0 * 36 + kb + qq];
                af[mt][1] = Asm[(r0 + 8) * 36 + kb + qq];
                af[mt][2] = Asm[r0 * 36 + kb + qq + 4];
                af[mt][3] = Asm[(r0 + 8) * 36 + kb + qq + 4];
            }
            uint32_t bf[8][2];
            #pragma unroll
            for (int nt = 0; nt < 8; nt++) {
                int c0 = wn * 64 + nt * 8 + gq;
                bf[nt][0] = Bsm[c0 * 36 + kb + qq];
                bf[nt][1] = Bsm[c0 * 36 + kb + qq + 4];
            }
            #pragma unroll
            for (int mt = 0; mt < 4; mt++)
                #pragma unroll
                for (int nt = 0; nt < 8; nt++)
                    mma_tf32(acc[mt][nt], af[mt], bf[nt]);
        }
        __syncthreads();
        if (c + 2 < NC) issue(c + 2, s);
        asm volatile("cp.async.commit_group;" ::: "memory");
    }

    // Epilogue
    #pragma unroll
    for (int mt = 0; mt < 4; mt++) {
        #pragma unroll
        for (int half = 0; half < 2; half++) {
            int r = m0 + wm * 64 + mt * 16 + half * 8 + gq;
            if (r >= Mb) continue;
            float* crow = Cb + (size_t)r * g.ldc + n0;
            const float* rrow = resb ? resb + (size_t)r * g.ldc + n0 : nullptr;
            #pragma unroll
            for (int nt = 0; nt < 8; nt++) {
                int cloc = wn * 64 + nt * 8;
                if (cloc >= ntile) continue;
                int col = cloc + 2 * qq;
                float2 v;
                v.x = acc[mt][nt][half * 2 + 0] * g.alpha;
                v.y = acc[mt][nt][half * 2 + 1] * g.alpha;
                if (rrow) {
                    float2 rv = *reinterpret_cast<const float2*>(rrow + col);
                    v.x += rv.x; v.y += rv.y;
                }
                if (g.roundC) { v.x = rntf(v.x); v.y = rntf(v.y); }
                *reinterpret_cast<float2*>(crow + col) = v;
            }
        }
    }
}

// ---------------------------------------------------------------------------
// Fused flash attention (unchanged from R6)
// ---------------------------------------------------------------------------
__global__ void __launch_bounds__(256) flash_kernel() {
    extern __shared__ float fs[];
    const int tid = threadIdx.x, lane = tid & 31, wid = tid >> 5;
    const int wm = wid & 3, wn = wid >> 2;
    const int gq = lane >> 2, qq = lane & 3;
    const int bh = blockIdx.y, b = bh >> 4, h = bh & 15, kh = h >> 2;
    const int q0 = blockIdx.x * 128;

    const float* Qg = g_q + ((size_t)(b * nS + q0)) * (nNH * nDH) + h * nDH;
    const float* Kg = g_k + (size_t)b * nS * (nNKV * nDH) + kh * nDH;
    const float* Vg = g_v + (size_t)b * nS * (nNKV * nDH) + kh * nDH;
    float* Og = g_attn + ((size_t)(b * nS + q0)) * nH + h * nDH;

    const uint32_t sb = smem_to_u32(fs);

    #pragma unroll
    for (int p = 0; p < 16; p++) {
        int idx = p * 256 + tid;
        int row = idx >> 5, c4 = idx & 31;
        uint32_t dst = sb + (uint32_t)(FA_QS + row * 132 + c4 * 4) * 4u;
        const float* src = Qg + (size_t)row * (nNH * nDH) + c4 * 4;
        asm volatile("cp.async.cg.shared.global [%0], [%1], 16;"
                     :: "r"(dst), "l"(src) : "memory");
    }
    asm volatile("cp.async.commit_group;" ::: "memory");

    auto issueKV = [&](int it2) {
        const float* kg = Kg + (size_t)(it2 * 64) * (nNKV * nDH);
        const float* vg = Vg + (size_t)(it2 * 64) * (nNKV * nDH);
        const uint32_t vb = (uint32_t)(FA_VS + (it2 & 1) * 8704);
        #pragma unroll
        for (int p = 0; p < 8; p++) {
            int idx = p * 256 + tid;
            int row = idx >> 5, c4 = idx & 31;
            uint32_t dk = sb + (uint32_t)(FA_KS + row * 132 + c4 * 4) * 4u;
            asm volatile("cp.async.cg.shared.global [%0], [%1], 16;"
                         :: "r"(dk), "l"(kg + (size_t)row * (nNKV * nDH) + c4 * 4) : "memory");
            uint32_t dv = sb + (vb + (uint32_t)(row * 136 + c4 * 4)) * 4u;
            asm volatile("cp.async.cg.shared.global [%0], [%1], 16;"
                         :: "r"(dv), "l"(vg + (size_t)row * (nNKV * nDH) + c4 * 4) : "memory");
        }
    };
    issueKV(0);
    asm volatile("cp.async.commit_group;" ::: "memory");

    float accO[2][8][4] = {};
    float rm[2][2] = {{-1e30f, -1e30f}, {-1e30f, -1e30f}};
    float rl[2][2] = {{0.f, 0.f}, {0.f, 0.f}};
    const uint32_t* fsu = reinterpret_cast<const uint32_t*>(fs);

    for (int it = 0; it < nS / 64; it++) {
        asm volatile("cp.async.wait_group 0;" ::: "memory");
        __syncthreads();

        float S[2][4][4] = {};
        #pragma unroll
        for (int kc = 0; kc < 16; kc++) {
            const int kb = kc * 8;
            uint32_t af[2][4];
            #pragma unroll
            for (int mt = 0; mt < 2; mt++) {
                int r0 = wm * 32 + mt * 16 + gq;
                af[mt][0] = fsu[FA_QS + r0 * 132 + kb + qq];
                af[mt][1] = fsu[FA_QS + (r0 + 8) * 132 + kb + qq];
                af[mt][2] = fsu[FA_QS + r0 * 132 + kb + qq + 4];
                af[mt][3] = fsu[FA_QS + (r0 + 8) * 132 + kb + qq + 4];
            }
            uint32_t bf[4][2];
            #pragma unroll
            for (int nt = 0; nt < 4; nt++) {
                int c0 = wn * 32 + nt * 8 + gq;
                bf[nt][0] = fsu[FA_KS + c0 * 132 + kb + qq];
                bf[nt][1] = fsu[FA_KS + c0 * 132 + kb + qq + 4];
            }
            #pragma unroll
            for (int mt = 0; mt < 2; mt++)
                #pragma unroll
                for (int nt = 0; nt < 4; nt++)
                    mma_tf32(S[mt][nt], af[mt], bf[nt]);
        }
        __syncthreads();
        if (it + 1 < nS / 64) issueKV(it + 1);
        asm volatile("cp.async.commit_group;" ::: "memory");

        float tmax[2][2] = {{-1e30f, -1e30f}, {-1e30f, -1e30f}};
        #pragma unroll
        for (int mt = 0; mt < 2; mt++)
            #pragma unroll
            for (int nt = 0; nt < 4; nt++)
                #pragma unroll
                for (int c = 0; c < 4; c++) {
                    S[mt][nt][c] *= QK_SCALE;
                    tmax[mt][c >> 1] = fmaxf(tmax[mt][c >> 1], S[mt][nt][c]);
                }
        #pragma unroll
        for (int mt = 0; mt < 2; mt++)
            #pragma unroll
            for (int hf = 0; hf < 2; hf++) {
                float v = tmax[mt][hf];
                v = fmaxf(v, __shfl_xor_sync(0xffffffffu, v, 1));
                v = fmaxf(v, __shfl_xor_sync(0xffffffffu, v, 2));
                tmax[mt][hf] = v;
            }
        if (qq == 0) {
            #pragma unroll
            for (int mt = 0; mt < 2; mt++)
                #pragma unroll
                for (int hf = 0; hf < 2; hf++)
                    fs[FA_RM + (wm * 32 + mt * 16 + hf * 8 + gq) * 2 + wn] = tmax[mt][hf];
        }
        __syncthreads();

        float newm[2][2], sco[2][2];
        #pragma unroll
        for (int mt = 0; mt < 2; mt++)
            #pragma unroll
            for (int hf = 0; hf < 2; hf++) {
                int r = wm * 32 + mt * 16 + hf * 8 + gq;
                float tm = fmaxf(fs[FA_RM + r * 2], fs[FA_RM + r * 2 + 1]);
                float nm = fmaxf(rm[mt][hf], tm);
                sco[mt][hf] = __expf(rm[mt][hf] - nm);
                newm[mt][hf] = nm;
                rm[mt][hf] = nm;
            }

        float ps[2][2] = {{0.f, 0.f}, {0.f, 0.f}};
        #pragma unroll
        for (int mt = 0; mt < 2; mt++) {
            int r0 = wm * 32 + mt * 16 + gq;
            #pragma unroll
            for (int nt = 0; nt < 4; nt++) {
                int col = wn * 32 + nt * 8 + 2 * qq;
                float p0 = __expf(S[mt][nt][0] - newm[mt][0]);
                float p1 = __expf(S[mt][nt][1] - newm[mt][0]);
                float p2 = __expf(S[mt][nt][2] - newm[mt][1]);
                float p3 = __expf(S[mt][nt][3] - newm[mt][1]);
                ps[mt][0] += p0 + p1;
                ps[mt][1] += p2 + p3;
                float2 v01 = make_float2(rntf(p0), rntf(p1));
                float2 v23 = make_float2(rntf(p2), rntf(p3));
                *reinterpret_cast<float2*>(&fs[FA_PS + r0 * 68 + col]) = v01;
                *reinterpret_cast<float2*>(&fs[FA_PS + (r0 + 8) * 68 + col]) = v23;
            }
        }
        #pragma unroll
        for (int mt = 0; mt < 2; mt++)
            #pragma unroll
            for (int hf = 0; hf < 2; hf++) {
                float v = ps[mt][hf];
                v += __shfl_xor_sync(0xffffffffu, v, 1);
                v += __shfl_xor_sync(0xffffffffu, v, 2);
                ps[mt][hf] = v;
            }
        if (qq == 0) {
            #pragma unroll
            for (int mt = 0; mt < 2; mt++)
                #pragma unroll
                for (int hf = 0; hf < 2; hf++)
                    fs[FA_RL + (wm * 32 + mt * 16 + hf * 8 + gq) * 2 + wn] = ps[mt][hf];
        }
        __syncthreads();

        #pragma unroll
        for (int mt = 0; mt < 2; mt++)
            #pragma unroll
            for (int hf = 0; hf < 2; hf++) {
                int r = wm * 32 + mt * 16 + hf * 8 + gq;
                float ts = fs[FA_RL + r * 2] + fs[FA_RL + r * 2 + 1];
                rl[mt][hf] = rl[mt][hf] * sco[mt][hf] + ts;
            }
        #pragma unroll
        for (int mt = 0; mt < 2; mt++)
            #pragma unroll
            for (int nt = 0; nt < 8; nt++) {
                accO[mt][nt][0] *= sco[mt][0];
                accO[mt][nt][1] *= sco[mt][0];
                accO[mt][nt][2] *= sco[mt][1];
                accO[mt][nt][3] *= sco[mt][1];
            }

        const int vbase = FA_VS + (it & 1) * 8704;
        #pragma unroll
        for (int kc = 0; kc < 8; kc++) {
            const int kb = kc * 8;
            uint32_t af[2][4];
            #pragma unroll
            for (int mt = 0; mt < 2; mt++) {
                int r0 = wm * 32 + mt * 16 + gq;
                af[mt][0] = fsu[FA_PS + r0 * 68 + kb + qq];
                af[mt][1] = fsu[FA_PS + (r0 + 8) * 68 + kb + qq];
                af[mt][2] = fsu[FA_PS + r0 * 68 + kb + qq + 4];
                af[mt][3] = fsu[FA_PS + (r0 + 8) * 68 + kb + qq + 4];
            }
            uint32_t bf[8][2];
            #pragma unroll
            for (int nt = 0; nt < 8; nt++) {
                int c0 = wn * 64 + nt * 8 + gq;
                bf[nt][0] = fsu[vbase + (kb + qq) * 136 + c0];
                bf[nt][1] = fsu[vbase + (kb + qq + 4) * 136 + c0];
            }
            #pragma unroll
            for (int mt = 0; mt < 2; mt++)
                #pragma unroll
                for (int nt = 0; nt < 8; nt++)
                    mma_tf32(accO[mt][nt], af[mt], bf[nt]);
        }
    }

    #pragma unroll
    for (int mt = 0; mt < 2; mt++)
        #pragma unroll
        for (int hf = 0; hf < 2; hf++) {
            int r = wm * 32 + mt * 16 + hf * 8 + gq;
            float inv = 1.f / rl[mt][hf];
            #pragma unroll
            for (int nt = 0; nt < 8; nt++) {
                int col = wn * 64 + nt * 8 + 2 * qq;
                float2 v;
                v.x = rntf(accO[mt][nt][hf * 2 + 0] * inv);
                v.y = rntf(accO[mt][nt][hf * 2 + 1] * inv);
                *reinterpret_cast<float2*>(Og + (size_t)r * nH + col) = v;
            }
        }
}

// ---------------------------------------------------------------------------
// Batched tiled transpose (rounds to tf32): in [z][K][N] -> out [z][N][K]
// ---------------------------------------------------------------------------
__global__ void transpose_kernel(const float* __restrict__ in, float* __restrict__ out,
                                 int K, int N) {
    __shared__ float t[32][33];
    size_t zo = (size_t)blockIdx.z * K * N;
    const float* ip = in + zo;
    float* op = out + zo;
    int n0 = blockIdx.x * 32, k0 = blockIdx.y * 32;
    int tx = threadIdx.x & 31, ty = threadIdx.x >> 5;
    #pragma unroll
    for (int i = ty; i < 32; i += 8) t[i][tx] = ip[(size_t)(k0 + i) * N + n0 + tx];
    __syncthreads();
    #pragma unroll
    for (int i = ty; i < 32; i += 8) op[(size_t)(n0 + i) * K + k0 + tx] = rntf(t[tx][i]);
}

// ---------------------------------------------------------------------------
// RMSNorm. rmsnorm1: rounded out only. rmsnorm2: rounded out + unrounded copy
// ---------------------------------------------------------------------------
template <bool DUAL>
__device__ __forceinline__ void rmsnorm_row(const float* __restrict__ x,
                                            const float* __restrict__ w,
                                            float* __restrict__ out_r,
                                            float* __restrict__ out_f) {
    int row = blockIdx.x;
    const float* xr = x + (size_t)row * nH;
    float ss = 0.f;
    for (int i = threadIdx.x; i < nH; i += blockDim.x) { float v = xr[i]; ss += v * v; }
    __shared__ float sm[8];
    int lane = threadIdx.x & 31, wid = threadIdx.x >> 5;
    ss = warpSum(ss);
    if (lane == 0) sm[wid] = ss;
    __syncthreads();
    if (wid == 0) {
        float v = (lane < 8) ? sm[lane] : 0.f;
        v = warpSum(v);
        if (lane == 0) sm[0] = rsqrtf(v / (float)nH + RMS_EPS);
    }
    __syncthreads();
    float inv = sm[0];
    for (int i = threadIdx.x; i < nH; i += blockDim.x) {
        float v = xr[i] * inv * w[i];
        out_r[(size_t)row * nH + i] = rntf(v);
        if (DUAL) out_f[(size_t)row * nH + i] = v;
    }
}
__global__ void rmsnorm1_kernel(const float* __restrict__ hs, const float* __restrict__ w) {
    rmsnorm_row<false>(hs, w, g_xn, nullptr);
}
__global__ void rmsnorm2_kernel(const float* __restrict__ w) {
    rmsnorm_row<true>(g_hidden, w, g_x2, g_xn);
}

// ---------------------------------------------------------------------------
// RoPE (in-place on q and k; rounds output)
// ---------------------------------------------------------------------------
__global__ void rope_kernel(const float* __restrict__ cosb, const float* __restrict__ sinb) {
    int i = blockIdx.x * blockDim.x + threadIdx.x;
    if (i >= nT * (nNH + nNKV) * 64) return;
    int d  = i & 63;
    int hh = (i >> 6) % (nNH + nNKV);
    int t  = i / (64 * (nNH + nNKV));
    float* ptr = (hh < nNH)
        ? (g_q + (size_t)t * (nNH * nDH) + hh * nDH)
        : (g_k + (size_t)t * (nNKV * nDH) + (hh - nNH) * nDH);
    float x1 = ptr[d], x2 = ptr[d + 64];
    const float* cr = cosb + (size_t)t * nDH;
    const float* sr = sinb + (size_t)t * nDH;
    ptr[d]      = rntf(x1 * cr[d]      - x2 * sr[d]);
    ptr[d + 64] = rntf(x2 * cr[d + 64] + x1 * sr[d + 64]);
}

// ---------------------------------------------------------------------------
// Router (reads UNROUNDED normed activations from g_xn)
// ---------------------------------------------------------------------------
__global__ void router_kernel(const float* __restrict__ rw) {
    __shared__ float xs[nH];
    __shared__ float lg[nE];
    int t = blockIdx.x;
    for (int i = threadIdx.x; i < nH; i += blockDim.x) xs[i] = g_xn[(size_t)t * nH + i];
    __syncthreads();
    int w = threadIdx.x >> 5, lane = threadIdx.x & 31;
    float s = 0.f;
    for (int i = lane; i < nH; i += 32) s += xs[i] * rw[(size_t)i * nE + w];
    s = warpSum(s);
    if (lane == 0) lg[w] = s;
    __syncthreads();
    if (threadIdx.x == 0) {
        float mx = lg[0];
        #pragma unroll
        for (int e = 1; e < nE; e++) mx = fmaxf(mx, lg[e]);
        float p[nE]; float sum = 0.f;
        #pragma unroll
        for (int e = 0; e < nE; e++) { p[e] = expf(lg[e] - mx); sum += p[e]; }
        #pragma unroll
        for (int e = 0; e < nE; e++) p[e] /= sum;
        int i1 = 0;
        #pragma unroll
        for (int e = 1; e < nE; e++) if (p[e] > p[i1]) i1 = e;
        int i2 = (i1 == 0) ? 1 : 0;
        #pragma unroll
        for (int e = 0; e < nE; e++) if (e != i1 && p[e] > p[i2]) i2 = e;
        float s2 = p[i1] + p[i2];
        g_topi[t * 2] = i1; g_topi[t * 2 + 1] = i2;
        g_topw[t * 2] = p[i1] / s2; g_topw[t * 2 + 1] = p[i2] / s2;
    }
}

// ---------------------------------------------------------------------------
// MoE bookkeeping
// ---------------------------------------------------------------------------
__global__ void reset_kernel() {
    int i = threadIdx.x;
    if (i < nE) { g_counts[i] = 0; g_fill[i] = 0; }
}
__global__ void count_kernel() {
    int t = blockIdx.x * blockDim.x + threadIdx.x;
    if (t >= nT) return;
    atomicAdd(&g_counts[g_topi[t * 2]], 1);
    atomicAdd(&g_counts[g_topi[t * 2 + 1]], 1);
}
__global__ void scan_kernel() {
    if (threadIdx.x != 0) return;
    int off = 0, nt = 0;
    for (int e = 0; e < nE; e++) {
        g_coff[e] = off;
        int ne = g_counts[e];
        int ntl = (ne + 127) >> 7;
        for (int i = 0; i < ntl; i++) { g_tileE[nt] = e; g_tileR0[nt] = off + i * 128; nt++; }
        off += ne;
    }
    g_coff[nE] = off;
    for (int i = nt; i < MAXTILE; i++) g_tileE[i] = -1;
}
__global__ void scatter_kernel() {
    int t = blockIdx.x * blockDim.x + threadIdx.x;
    if (t >= nT) return;
    #pragma unroll
    for (int k = 0; k < 2; k++) {
        int e = g_topi[t * 2 + k];
        int pos = g_coff[e] + atomicAdd(&g_fill[e], 1);
        g_toklist[pos] = t;
        g_slot[t * 2 + k] = pos;
    }
}

__global__ void silu_kernel() {
    size_t i = (size_t)blockIdx.x * blockDim.x + threadIdx.x;
    if (i >= (size_t)GR * nMI) return;
    float gv = g_gbuf[i];
    g_ubuf[i] = rntf(gv * (1.f / (1.f + expf(-gv))) * g_ubuf[i]);
}

__global__ void combine_kernel(float* __restrict__ out) {
    size_t i = (size_t)blockIdx.x * blockDim.x + threadIdx.x;
    if (i >= (size_t)nT * nH) return;
    int t = (int)(i / nH), j = (int)(i % nH);
    float v = g_hidden[i];
    v += g_topw[t * 2]     * g_part[(size_t)g_slot[t * 2]     * nH + j];
    v += g_topw[t * 2 + 1] * g_part[(size_t)g_slot[t * 2 + 1] * nH + j];
    out[i] = v;
}

// ---------------------------------------------------------------------------
// Launch
// ---------------------------------------------------------------------------
static void launch_gemm(const float* A, long long lda, const float* B, long long ldb,
                        float* C, long long ldc, const float* res,
                        int M, int N, int K, float alpha, int mode, int roundC,
                        dim3 grid,
                        long long sAb = 0, long long sAh = 0, long long sBb = 0,
                        long long sBh = 0, long long sCb = 0, long long sCh = 0,
                        int zmod = 1, int groups = 1) {
    GArgs g;
    g.A = A; g.B = B; g.C = C; g.res = res;
    g.lda = lda; g.ldb = ldb; g.ldc = ldc;
    g.M = M; g.N = N; g.K = K; g.alpha = alpha; g.mode = mode; g.roundC = roundC;
    g.sAb = sAb; g.sAh = sAh; g.sBb = sBb; g.sBh = sBh; g.sCb = sCb; g.sCh = sCh;
    g.zmod = zmod; g.groups = groups;
    tc_gemm<<<grid, 256, SMEM_BYTES>>>(g);
}

extern "C" void kernel_launch(void* const* d_in, const int* in_sizes, int n_in,
                              void* d_out, int out_size) {
    const float* hs   = (const float*)d_in[0];
    const float* cosb = (const float*)d_in[1];
    const float* sinb = (const float*)d_in[2];
    const float* wq   = (const float*)d_in[3];
    const float* wk   = (const float*)d_in[4];
    const float* wv   = (const float*)d_in[5];
    const float* wo   = (const float*)d_in[6];
    const float* ln1  = (const float*)d_in[7];
    const float* ln2  = (const float*)d_in[8];
    const float* rw   = (const float*)d_in[9];
    const float* gw   = (const float*)d_in[10];
    const float* uw   = (const float*)d_in[11];
    const float* dw   = (const float*)d_in[12];
    float* out = (float*)d_out;

    static bool attr_set = false;
    if (!attr_set) {
        cudaFuncSetAttribute(tc_gemm, cudaFuncAttributeMaxDynamicSharedMemorySize, SMEM_BYTES);
        cudaFuncSetAttribute(flash_kernel, cudaFuncAttributeMaxDynamicSharedMemorySize, FA_BYTES);
        attr_set = true;
    }

    float* wqT; cudaGetSymbolAddress((void**)&wqT, g_wqT);
    float* wkT; cudaGetSymbolAddress((void**)&wkT, g_wkT);
    float* wvT; cudaGetSymbolAddress((void**)&wvT, g_wvT);
    float* woT; cudaGetSymbolAddress((void**)&woT, g_woT);
    float* gwT; cudaGetSymbolAddress((void**)&gwT, g_gwT);
    float* uwT; cudaGetSymbolAddress((void**)&uwT, g_uwT);
    float* dwT; cudaGetSymbolAddress((void**)&dwT, g_dwT);
    float* xn;  cudaGetSymbolAddress((void**)&xn, g_xn);
    float* q;   cudaGetSymbolAddress((void**)&q, g_q);
    float* k;   cudaGetSymbolAddress((void**)&k, g_k);
    float* v;   cudaGetSymbolAddress((void**)&v, g_v);
    float* at;  cudaGetSymbolAddress((void**)&at, g_attn);
    float* hid; cudaGetSymbolAddress((void**)&hid, g_hidden);
    float* x2;  cudaGetSymbolAddress((void**)&x2, g_x2);
    float* gb;  cudaGetSymbolAddress((void**)&gb, g_gbuf);
    float* ub;  cudaGetSymbolAddress((void**)&ub, g_ubuf);
    float* pt;  cudaGetSymbolAddress((void**)&pt, g_part);

    reset_kernel<<<1, 32>>>();

    // Weight transposes -> [N][K], tf32-rounded
    transpose_kernel<<<dim3(64, 64, 1), 256>>>(wq, wqT, nH, nNH * nDH);
    transpose_kernel<<<dim3(16, 64, 1), 256>>>(wk, wkT, nH, nNKV * nDH);
    transpose_kernel<<<dim3(16, 64, 1), 256>>>(wv, wvT, nH, nNKV * nDH);
    transpose_kernel<<<dim3(64, 64, 1), 256>>>(wo, woT, nH, nH);
    transpose_kernel<<<dim3(44, 64, nE), 256>>>(gw, gwT, nH, nMI);
    transpose_kernel<<<dim3(44, 64, nE), 256>>>(uw, uwT, nH, nMI);
    transpose_kernel<<<dim3(64, 44, nE), 256>>>(dw, dwT, nMI, nH);

    rmsnorm1_kernel<<<nT, 256>>>(hs, ln1);

    launch_gemm(xn, nH, wqT, nH, q, nNH * nDH, nullptr, nT, nNH * nDH, nH, 1.f, 0, 0,
                dim3(8, 32, 1));
    launch_gemm(xn, nH, wkT, nH, k, nNKV * nDH, nullptr, nT, nNKV * nDH, nH, 1.f, 0, 0,
                dim3(2, 32, 1));
    launch_gemm(xn, nH, wvT, nH, v, nNKV * nDH, nullptr, nT, nNKV * nDH, nH, 1.f, 0, 1,
                dim3(2, 32, 1));   // V rounded: feeds flash AV

    rope_kernel<<<(nT * (nNH + nNKV) * 64) / 256, 256>>>(cosb, sinb);

    // fused attention: QK + online softmax + AV
    flash_kernel<<<dim3(nS / 128, nB * nNH), 256, FA_BYTES>>>();

    // hidden = attn @ wo + residual (fp32 out)
    launch_gemm(at, nH, woT, nH, hid, nH, hs, nT, nH, nH, 1.f, 0, 0, dim3(8, 32, 1));

    rmsnorm2_kernel<<<nT, 256>>>(ln2);
    router_kernel<<<nT, 256>>>(rw);

    count_kernel<<<nT / 256, 256>>>();
    scan_kernel<<<1, 1>>>();
    scatter_kernel<<<nT / 256, 256>>>();

    // MoE: gate & up (gathered A), silu (rounds), down
    launch_gemm(x2, nH, gwT, nH, gb, nMI, nullptr, GR, nMI, nH, 1.f, 1, 0, dim3(6, MAXTILE, 1));
    launch_gemm(x2, nH, uwT, nH, ub, nMI, nullptr, GR, nMI, nH, 1.f, 1, 0, dim3(6, MAXTILE, 1));
    silu_kernel<<<((size_t)GR * nMI) / 256, 256>>>();
    launch_gemm(ub, nMI, dwT, nMI, pt, nH, nullptr, GR, nH, nMI, 1.f, 2, 0, dim3(8, MAXTILE, 1));

    combine_kernel<<<((size_t)nT * nH) / 256, 256>>>(out);
}

// round 8
// speedup vs baseline: 1.1621x; 1.1621x over previous
#include <cuda_runtime.h>
#include <cuda_bf16.h>
#include <math.h>
#include <stdint.h>

// ---------------------------------------------------------------------------
// Problem constants
// ---------------------------------------------------------------------------
namespace {
constexpr int nB = 2, nS = 2048, nH = 2048, nNH = 16, nNKV = 4, nDH = 128;
constexpr int nE = 8, nMI = 1408;
constexpr int nT = nB * nS;          // 4096 tokens
constexpr int GR = nT * 2;           // 8192 gathered (token, expert) rows
constexpr int MAXTILE = 72;          // ceil(8192/128) + 8 experts padding
constexpr float RMS_EPS = 1e-6f;
constexpr float QK_SCALE = 0.088388347648318447f;  // 1/sqrt(128)
constexpr int SMEM_FLOATS = 4 * 128 * 36;          // 2 bufs x (A+B) tiles
constexpr int SMEM_BYTES = SMEM_FLOATS * 4;        // 73728

// flash attention smem layout (float indices)
constexpr int FA_QS = 0;                 // Q  [128][132]
constexpr int FA_KS = 16896;             // K  [64][132]
constexpr int FA_VS = 25344;             // V  2 x [64][136]
constexpr int FA_PS = 42752;             // P  [128][68]
constexpr int FA_RM = 51456;             // rowmax exchange [128][2]
constexpr int FA_RL = 51712;             // rowsum exchange [128][2]
constexpr int FA_FLOATS = 51968;
constexpr int FA_BYTES = FA_FLOATS * 4;  // 207872
}

// ---------------------------------------------------------------------------
// Scratch (device globals)
// ---------------------------------------------------------------------------
__device__ float g_xn    [(size_t)nT * nH];   // rmsnorm1 out; later: unrounded rmsnorm2 out
__device__ float g_q     [(size_t)nT * nNH * nDH];
__device__ float g_k     [(size_t)nT * nNKV * nDH];
__device__ float g_v     [(size_t)nT * nNKV * nDH];
__device__ float g_attn  [(size_t)nT * nH];
__device__ float g_hidden[(size_t)nT * nH];
__device__ float g_x2    [(size_t)nT * nH];
__device__ int   g_topi  [nT * 2];
__device__ float g_topw  [nT * 2];
__device__ int   g_counts[nE];
__device__ int   g_fill  [nE];
__device__ int   g_coff  [nE + 1];
__device__ int   g_tileE [MAXTILE];
__device__ int   g_tileR0[MAXTILE];
__device__ int   g_toklist[GR];
__device__ int   g_slot  [nT * 2];
__device__ float g_gbuf  [(size_t)GR * nMI];
__device__ float g_ubuf  [(size_t)GR * nMI];
__device__ float g_part  [(size_t)GR * nH];
// transposed weights [N][K] K-major (tf32-rounded)
__device__ float g_wqT [(size_t)(nNH * nDH) * nH];
__device__ float g_wkT [(size_t)(nNKV * nDH) * nH];
__device__ float g_wvT [(size_t)(nNKV * nDH) * nH];
__device__ float g_woT [(size_t)nH * nH];
__device__ float g_gwT [(size_t)nE * nMI * nH];
__device__ float g_uwT [(size_t)nE * nMI * nH];
__device__ float g_dwT [(size_t)nE * nH * nMI];

// ---------------------------------------------------------------------------
// Helpers
// ---------------------------------------------------------------------------
__device__ __forceinline__ uint32_t smem_to_u32(const void* p) {
    uint32_t a;
    asm("{ .reg .u64 t; cvta.to.shared.u64 t, %1; cvt.u32.u64 %0, t; }" : "=r"(a) : "l"(p));
    return a;
}
__device__ __forceinline__ float rntf(float x) {
    uint32_t r;
    asm("cvt.rna.tf32.f32 %0, %1;" : "=r"(r) : "f"(x));
    return __uint_as_float(r);
}
__device__ __forceinline__ void mma_tf32(float* d, const uint32_t* a, const uint32_t* b) {
    asm volatile("mma.sync.aligned.m16n8k8.row.col.f32.tf32.tf32.f32 "
        "{%0,%1,%2,%3}, {%4,%5,%6,%7}, {%8,%9}, {%0,%1,%2,%3};"
        : "+f"(d[0]), "+f"(d[1]), "+f"(d[2]), "+f"(d[3])
        : "r"(a[0]), "r"(a[1]), "r"(a[2]), "r"(a[3]), "r"(b[0]), "r"(b[1]));
}
__device__ __forceinline__ float warpSum(float v) {
    #pragma unroll
    for (int o = 16; o; o >>= 1) v += __shfl_xor_sync(0xffffffffu, v, o);
    return v;
}

// ---------------------------------------------------------------------------
// tf32 mma.sync GEMM (R6 shape): inputs PRE-ROUNDED; no cvt inside.
// C[M,N] = alpha * A[M,K](K-major) x B[N,K](K-major) (+res | fused-silu)
// CTA tile 128x128, K-chunks of 32, 256 threads (8 warps 4m x 2n).
// ---------------------------------------------------------------------------
struct GArgs {
    const float* A; const float* B; float* C; const float* res;
    long long lda, ldb, ldc;
    int M, N, K;
    float alpha;
    int mode;     // 0 normal, 1 moe gather-A, 2 moe no-gather
    int roundC;   // round outputs to tf32 grid
    int fuseSilu; // res = gate buffer; C = rntf(silu(res) * acc)
    long long sAb, sAh, sBb, sBh, sCb, sCh;
    int zmod, groups;
};

__global__ void __launch_bounds__(256) tc_gemm(GArgs g) {
    extern __shared__ float dsmf[];
    const int tid = threadIdx.x, lane = tid & 31, wid = tid >> 5;
    const int wm = wid & 3, wn = wid >> 2;
    const int gq = lane >> 2, qq = lane & 3;

    int m0, Mb;
    const float* Ab = g.A;
    const float* Bb = g.B;
    float* Cb = g.C;
    const float* resb = g.res;
    if (g.mode >= 1) {
        int e = g_tileE[blockIdx.y];
        if (e < 0) return;
        m0 = g_tileR0[blockIdx.y];
        Mb = g_coff[e + 1];
        Bb += (size_t)e * g.N * g.K;
    } else {
        m0 = blockIdx.y * 128;
        Mb = g.M;
        int bz = blockIdx.z;
        int b = bz / g.zmod, h = bz % g.zmod;
        Ab += (size_t)b * g.sAb + (size_t)h * g.sAh;
        Bb += (size_t)b * g.sBb + (size_t)(h / g.groups) * g.sBh;
        Cb += (size_t)b * g.sCb + (size_t)h * g.sCh;
        if (resb) resb += (size_t)b * g.sCb + (size_t)h * g.sCh;
    }
    const int n0 = blockIdx.x * 128;

    __shared__ int rt[128];
    if (tid < 128) {
        int m = m0 + tid;
        int r = (m < Mb) ? m : -1;
        if (g.mode == 1 && r >= 0) r = g_toklist[r];
        rt[tid] = r;
    }
    __syncthreads();

    const uint32_t sbase = smem_to_u32(dsmf);
    const int NC = g.K >> 5;

    auto issue = [&](int c, int s) {
        const int k0 = c << 5;
        #pragma unroll
        for (int p = 0; p < 4; p++) {
            int idx = p * 256 + tid;
            int row = idx >> 3, c4 = idx & 7;
            int r = rt[row];
            const float* src = (r >= 0 ? Ab + (size_t)r * g.lda : Ab) + k0 + c4 * 4;
            uint32_t dst = sbase + (uint32_t)(s * 4608 + row * 36 + c4 * 4) * 4u;
            int sz = (r >= 0) ? 16 : 0;
            asm volatile("cp.async.cg.shared.global [%0], [%1], 16, %2;"
                         :: "r"(dst), "l"(src), "r"(sz) : "memory");
        }
        #pragma unroll
        for (int p = 0; p < 4; p++) {
            int idx = p * 256 + tid;
            int row = idx >> 3, c4 = idx & 7;
            const float* src = Bb + (size_t)(n0 + row) * g.ldb + k0 + c4 * 4;
            uint32_t dst = sbase + (uint32_t)(9216 + s * 4608 + row * 36 + c4 * 4) * 4u;
            asm volatile("cp.async.cg.shared.global [%0], [%1], 16, %2;"
                         :: "r"(dst), "l"(src), "r"(16) : "memory");
        }
    };

    float acc[2][8][4] = {};

    issue(0, 0);
    asm volatile("cp.async.commit_group;" ::: "memory");
    if (NC > 1) issue(1, 1);
    asm volatile("cp.async.commit_group;" ::: "memory");

    const uint32_t* dsum = reinterpret_cast<const uint32_t*>(dsmf);

    for (int c = 0; c < NC; c++) {
        const int s = c & 1;
        asm volatile("cp.async.wait_group 1;" ::: "memory");
        __syncthreads();
        const uint32_t* Asm = dsum + s * 4608;
        const uint32_t* Bsm = dsum + 9216 + s * 4608;
        #pragma unroll
        for (int kk = 0; kk < 4; kk++) {
            const int kb = kk * 8;
            uint32_t af[2][4];
            #pragma unroll
            for (int mt = 0; mt < 2; mt++) {
                int r0 = wm * 32 + mt * 16 + gq;
                af[mt][0] = Asm[r0 * 36 + kb + qq];
                af[mt][1] = Asm[(r0 + 8) * 36 + kb + qq];
                af[mt][2] = Asm[r0 * 36 + kb + qq + 4];
                af[mt][3] = Asm[(r0 + 8) * 36 + kb + qq + 4];
            }
            uint32_t bf[8][2];
            #pragma unroll
            for (int nt = 0; nt < 8; nt++) {
                int c0 = wn * 64 + nt * 8 + gq;
                bf[nt][0] = Bsm[c0 * 36 + kb + qq];
                bf[nt][1] = Bsm[c0 * 36 + kb + qq + 4];
            }
            #pragma unroll
            for (int mt = 0; mt < 2; mt++)
                #pragma unroll
                for (int nt = 0; nt < 8; nt++)
                    mma_tf32(acc[mt][nt], af[mt], bf[nt]);
        }
        __syncthreads();
        if (c + 2 < NC) issue(c + 2, s);
        asm volatile("cp.async.commit_group;" ::: "memory");
    }

    // Epilogue
    #pragma unroll
    for (int mt = 0; mt < 2; mt++) {
        int row = m0 + wm * 32 + mt * 16 + gq;
        #pragma unroll
        for (int half = 0; half < 2; half++) {
            int r = row + half * 8;
            if (r >= Mb) continue;
            float* crow = Cb + (size_t)r * g.ldc + n0 + wn * 64 + 2 * qq;
            const float* rrow = resb ? resb + (size_t)r * g.ldc + n0 + wn * 64 + 2 * qq : nullptr;
            #pragma unroll
            for (int nt = 0; nt < 8; nt++) {
                float2 v;
                v.x = acc[mt][nt][half * 2 + 0] * g.alpha;
                v.y = acc[mt][nt][half * 2 + 1] * g.alpha;
                if (g.fuseSilu) {
                    float2 gv = *reinterpret_cast<const float2*>(rrow + nt * 8);
                    v.x = rntf(gv.x * (1.f / (1.f + expf(-gv.x))) * v.x);
                    v.y = rntf(gv.y * (1.f / (1.f + expf(-gv.y))) * v.y);
                } else {
                    if (rrow) {
                        float2 rv = *reinterpret_cast<const float2*>(rrow + nt * 8);
                        v.x += rv.x; v.y += rv.y;
                    }
                    if (g.roundC) { v.x = rntf(v.x); v.y = rntf(v.y); }
                }
                *reinterpret_cast<float2*>(crow + nt * 8) = v;
            }
        }
    }
}

// ---------------------------------------------------------------------------
// Fused flash attention (unchanged from R6)
// ---------------------------------------------------------------------------
__global__ void __launch_bounds__(256) flash_kernel() {
    extern __shared__ float fs[];
    const int tid = threadIdx.x, lane = tid & 31, wid = tid >> 5;
    const int wm = wid & 3, wn = wid >> 2;
    const int gq = lane >> 2, qq = lane & 3;
    const int bh = blockIdx.y, b = bh >> 4, h = bh & 15, kh = h >> 2;
    const int q0 = blockIdx.x * 128;

    const float* Qg = g_q + ((size_t)(b * nS + q0)) * (nNH * nDH) + h * nDH;
    const float* Kg = g_k + (size_t)b * nS * (nNKV * nDH) + kh * nDH;
    const float* Vg = g_v + (size_t)b * nS * (nNKV * nDH) + kh * nDH;
    float* Og = g_attn + ((size_t)(b * nS + q0)) * nH + h * nDH;

    const uint32_t sb = smem_to_u32(fs);

    #pragma unroll
    for (int p = 0; p < 16; p++) {
        int idx = p * 256 + tid;
        int row = idx >> 5, c4 = idx & 31;
        uint32_t dst = sb + (uint32_t)(FA_QS + row * 132 + c4 * 4) * 4u;
        const float* src = Qg + (size_t)row * (nNH * nDH) + c4 * 4;
        asm volatile("cp.async.cg.shared.global [%0], [%1], 16;"
                     :: "r"(dst), "l"(src) : "memory");
    }
    asm volatile("cp.async.commit_group;" ::: "memory");

    auto issueKV = [&](int it2) {
        const float* kg = Kg + (size_t)(it2 * 64) * (nNKV * nDH);
        const float* vg = Vg + (size_t)(it2 * 64) * (nNKV * nDH);
        const uint32_t vb = (uint32_t)(FA_VS + (it2 & 1) * 8704);
        #pragma unroll
        for (int p = 0; p < 8; p++) {
            int idx = p * 256 + tid;
            int row = idx >> 5, c4 = idx & 31;
            uint32_t dk = sb + (uint32_t)(FA_KS + row * 132 + c4 * 4) * 4u;
            asm volatile("cp.async.cg.shared.global [%0], [%1], 16;"
                         :: "r"(dk), "l"(kg + (size_t)row * (nNKV * nDH) + c4 * 4) : "memory");
            uint32_t dv = sb + (vb + (uint32_t)(row * 136 + c4 * 4)) * 4u;
            asm volatile("cp.async.cg.shared.global [%0], [%1], 16;"
                         :: "r"(dv), "l"(vg + (size_t)row * (nNKV * nDH) + c4 * 4) : "memory");
        }
    };
    issueKV(0);
    asm volatile("cp.async.commit_group;" ::: "memory");

    float accO[2][8][4] = {};
    float rm[2][2] = {{-1e30f, -1e30f}, {-1e30f, -1e30f}};
    float rl[2][2] = {{0.f, 0.f}, {0.f, 0.f}};
    const uint32_t* fsu = reinterpret_cast<const uint32_t*>(fs);

    for (int it = 0; it < nS / 64; it++) {
        asm volatile("cp.async.wait_group 0;" ::: "memory");
        __syncthreads();

        float S[2][4][4] = {};
        #pragma unroll
        for (int kc = 0; kc < 16; kc++) {
            const int kb = kc * 8;
            uint32_t af[2][4];
            #pragma unroll
            for (int mt = 0; mt < 2; mt++) {
                int r0 = wm * 32 + mt * 16 + gq;
                af[mt][0] = fsu[FA_QS + r0 * 132 + kb + qq];
                af[mt][1] = fsu[FA_QS + (r0 + 8) * 132 + kb + qq];
                af[mt][2] = fsu[FA_QS + r0 * 132 + kb + qq + 4];
                af[mt][3] = fsu[FA_QS + (r0 + 8) * 132 + kb + qq + 4];
            }
            uint32_t bf[4][2];
            #pragma unroll
            for (int nt = 0; nt < 4; nt++) {
                int c0 = wn * 32 + nt * 8 + gq;
                bf[nt][0] = fsu[FA_KS + c0 * 132 + kb + qq];
                bf[nt][1] = fsu[FA_KS + c0 * 132 + kb + qq + 4];
            }
            #pragma unroll
            for (int mt = 0; mt < 2; mt++)
                #pragma unroll
                for (int nt = 0; nt < 4; nt++)
                    mma_tf32(S[mt][nt], af[mt], bf[nt]);
        }
        __syncthreads();
        if (it + 1 < nS / 64) issueKV(it + 1);
        asm volatile("cp.async.commit_group;" ::: "memory");

        float tmax[2][2] = {{-1e30f, -1e30f}, {-1e30f, -1e30f}};
        #pragma unroll
        for (int mt = 0; mt < 2; mt++)
            #pragma unroll
            for (int nt = 0; nt < 4; nt++)
                #pragma unroll
                for (int c = 0; c < 4; c++) {
                    S[mt][nt][c] *= QK_SCALE;
                    tmax[mt][c >> 1] = fmaxf(tmax[mt][c >> 1], S[mt][nt][c]);
                }
        #pragma unroll
        for (int mt = 0; mt < 2; mt++)
            #pragma unroll
            for (int hf = 0; hf < 2; hf++) {
                float v = tmax[mt][hf];
                v = fmaxf(v, __shfl_xor_sync(0xffffffffu, v, 1));
                v = fmaxf(v, __shfl_xor_sync(0xffffffffu, v, 2));
                tmax[mt][hf] = v;
            }
        if (qq == 0) {
            #pragma unroll
            for (int mt = 0; mt < 2; mt++)
                #pragma unroll
                for (int hf = 0; hf < 2; hf++)
                    fs[FA_RM + (wm * 32 + mt * 16 + hf * 8 + gq) * 2 + wn] = tmax[mt][hf];
        }
        __syncthreads();

        float newm[2][2], sco[2][2];
        #pragma unroll
        for (int mt = 0; mt < 2; mt++)
            #pragma unroll
            for (int hf = 0; hf < 2; hf++) {
                int r = wm * 32 + mt * 16 + hf * 8 + gq;
                float tm = fmaxf(fs[FA_RM + r * 2], fs[FA_RM + r * 2 + 1]);
                float nm = fmaxf(rm[mt][hf], tm);
                sco[mt][hf] = __expf(rm[mt][hf] - nm);
                newm[mt][hf] = nm;
                rm[mt][hf] = nm;
            }

        float ps[2][2] = {{0.f, 0.f}, {0.f, 0.f}};
        #pragma unroll
        for (int mt = 0; mt < 2; mt++) {
            int r0 = wm * 32 + mt * 16 + gq;
            #pragma unroll
            for (int nt = 0; nt < 4; nt++) {
                int col = wn * 32 + nt * 8 + 2 * qq;
                float p0 = __expf(S[mt][nt][0] - newm[mt][0]);
                float p1 = __expf(S[mt][nt][1] - newm[mt][0]);
                float p2 = __expf(S[mt][nt][2] - newm[mt][1]);
                float p3 = __expf(S[mt][nt][3] - newm[mt][1]);
                ps[mt][0] += p0 + p1;
                ps[mt][1] += p2 + p3;
                float2 v01 = make_float2(rntf(p0), rntf(p1));
                float2 v23 = make_float2(rntf(p2), rntf(p3));
                *reinterpret_cast<float2*>(&fs[FA_PS + r0 * 68 + col]) = v01;
                *reinterpret_cast<float2*>(&fs[FA_PS + (r0 + 8) * 68 + col]) = v23;
            }
        }
        #pragma unroll
        for (int mt = 0; mt < 2; mt++)
            #pragma unroll
            for (int hf = 0; hf < 2; hf++) {
                float v = ps[mt][hf];
                v += __shfl_xor_sync(0xffffffffu, v, 1);
                v += __shfl_xor_sync(0xffffffffu, v, 2);
                ps[mt][hf] = v;
            }
        if (qq == 0) {
            #pragma unroll
            for (int mt = 0; mt < 2; mt++)
                #pragma unroll
                for (int hf = 0; hf < 2; hf++)
                    fs[FA_RL + (wm * 32 + mt * 16 + hf * 8 + gq) * 2 + wn] = ps[mt][hf];
        }
        __syncthreads();

        #pragma unroll
        for (int mt = 0; mt < 2; mt++)
            #pragma unroll
            for (int hf = 0; hf < 2; hf++) {
                int r = wm * 32 + mt * 16 + hf * 8 + gq;
                float ts = fs[FA_RL + r * 2] + fs[FA_RL + r * 2 + 1];
                rl[mt][hf] = rl[mt][hf] * sco[mt][hf] + ts;
            }
        #pragma unroll
        for (int mt = 0; mt < 2; mt++)
            #pragma unroll
            for (int nt = 0; nt < 8; nt++) {
                accO[mt][nt][0] *= sco[mt][0];
                accO[mt][nt][1] *= sco[mt][0];
                accO[mt][nt][2] *= sco[mt][1];
                accO[mt][nt][3] *= sco[mt][1];
            }

        const int vbase = FA_VS + (it & 1) * 8704;
        #pragma unroll
        for (int kc = 0; kc < 8; kc++) {
            const int kb = kc * 8;
            uint32_t af[2][4];
            #pragma unroll
            for (int mt = 0; mt < 2; mt++) {
                int r0 = wm * 32 + mt * 16 + gq;
                af[mt][0] = fsu[FA_PS + r0 * 68 + kb + qq];
                af[mt][1] = fsu[FA_PS + (r0 + 8) * 68 + kb + qq];
                af[mt][2] = fsu[FA_PS + r0 * 68 + kb + qq + 4];
                af[mt][3] = fsu[FA_PS + (r0 + 8) * 68 + kb + qq + 4];
            }
            uint32_t bf[8][2];
            #pragma unroll
            for (int nt = 0; nt < 8; nt++) {
                int c0 = wn * 64 + nt * 8 + gq;
                bf[nt][0] = fsu[vbase + (kb + qq) * 136 + c0];
                bf[nt][1] = fsu[vbase + (kb + qq + 4) * 136 + c0];
            }
            #pragma unroll
            for (int mt = 0; mt < 2; mt++)
                #pragma unroll
                for (int nt = 0; nt < 8; nt++)
                    mma_tf32(accO[mt][nt], af[mt], bf[nt]);
        }
    }

    #pragma unroll
    for (int mt = 0; mt < 2; mt++)
        #pragma unroll
        for (int hf = 0; hf < 2; hf++) {
            int r = wm * 32 + mt * 16 + hf * 8 + gq;
            float inv = 1.f / rl[mt][hf];
            #pragma unroll
            for (int nt = 0; nt < 8; nt++) {
                int col = wn * 64 + nt * 8 + 2 * qq;
                float2 v;
                v.x = rntf(accO[mt][nt][hf * 2 + 0] * inv);
                v.y = rntf(accO[mt][nt][hf * 2 + 1] * inv);
                *reinterpret_cast<float2*>(Og + (size_t)r * nH + col) = v;
            }
        }
}

// ---------------------------------------------------------------------------
// Vectorized batched transpose (rounds to tf32): in [z][K][N] -> out [z][N][K]
// Tile 32(k) x 128(n); LDG.128 + STG.128 both sides; smem pad 137 for
// conflict-free transposed reads. Requires K%32==0, N%128==0.
// ---------------------------------------------------------------------------
__global__ void __launch_bounds__(256) transpose_kernel(const float* __restrict__ in,
                                                        float* __restrict__ out,
                                                        int K, int N) {
    __shared__ float t[32][137];
    size_t zo = (size_t)blockIdx.z * K * N;
    const float* ip = in + zo;
    float* op = out + zo;
    const int n0 = blockIdx.x * 128, k0 = blockIdx.y * 32;
    const int tid = threadIdx.x;
    const int rr = tid >> 5, rc = tid & 31;       // read: k-row, n-float4
    #pragma unroll
    for (int p = 0; p < 4; p++) {
        int kk = rr + p * 8;
        float4 v = *reinterpret_cast<const float4*>(ip + (size_t)(k0 + kk) * N + n0 + rc * 4);
        t[kk][rc * 4 + 0] = v.x; t[kk][rc * 4 + 1] = v.y;
        t[kk][rc * 4 + 2] = v.z; t[kk][rc * 4 + 3] = v.w;
    }
    __syncthreads();
    const int wr = tid >> 3, wk4 = (tid & 7) * 4; // write: n-row, k-float4
    #pragma unroll
    for (int p = 0; p < 4; p++) {
        int nn = wr + p * 32;
        float4 v;
        v.x = rntf(t[wk4 + 0][nn]); v.y = rntf(t[wk4 + 1][nn]);
        v.z = rntf(t[wk4 + 2][nn]); v.w = rntf(t[wk4 + 3][nn]);
        *reinterpret_cast<float4*>(op + (size_t)(n0 + nn) * K + k0 + wk4) = v;
    }
}

// ---------------------------------------------------------------------------
// RMSNorm. rmsnorm1: rounded out only. rmsnorm2: rounded out + unrounded copy
// ---------------------------------------------------------------------------
template <bool DUAL>
__device__ __forceinline__ void rmsnorm_row(const float* __restrict__ x,
                                            const float* __restrict__ w,
                                            float* __restrict__ out_r,
                                            float* __restrict__ out_f) {
    int row = blockIdx.x;
    const float* xr = x + (size_t)row * nH;
    float ss = 0.f;
    for (int i = threadIdx.x; i < nH; i += blockDim.x) { float v = xr[i]; ss += v * v; }
    __shared__ float sm[8];
    int lane = threadIdx.x & 31, wid = threadIdx.x >> 5;
    ss = warpSum(ss);
    if (lane == 0) sm[wid] = ss;
    __syncthreads();
    if (wid == 0) {
        float v = (lane < 8) ? sm[lane] : 0.f;
        v = warpSum(v);
        if (lane == 0) sm[0] = rsqrtf(v / (float)nH + RMS_EPS);
    }
    __syncthreads();
    float inv = sm[0];
    for (int i = threadIdx.x; i < nH; i += blockDim.x) {
        float v = xr[i] * inv * w[i];
        out_r[(size_t)row * nH + i] = rntf(v);
        if (DUAL) out_f[(size_t)row * nH + i] = v;
    }
}
__global__ void rmsnorm1_kernel(const float* __restrict__ hs, const float* __restrict__ w) {
    rmsnorm_row<false>(hs, w, g_xn, nullptr);
}
__global__ void rmsnorm2_kernel(const float* __restrict__ w) {
    rmsnorm_row<true>(g_hidden, w, g_x2, g_xn);
}

// ---------------------------------------------------------------------------
// RoPE (in-place on q and k; rounds output)
// ---------------------------------------------------------------------------
__global__ void rope_kernel(const float* __restrict__ cosb, const float* __restrict__ sinb) {
    int i = blockIdx.x * blockDim.x + threadIdx.x;
    if (i >= nT * (nNH + nNKV) * 64) return;
    int d  = i & 63;
    int hh = (i >> 6) % (nNH + nNKV);
    int t  = i / (64 * (nNH + nNKV));
    float* ptr = (hh < nNH)
        ? (g_q + (size_t)t * (nNH * nDH) + hh * nDH)
        : (g_k + (size_t)t * (nNKV * nDH) + (hh - nNH) * nDH);
    float x1 = ptr[d], x2 = ptr[d + 64];
    const float* cr = cosb + (size_t)t * nDH;
    const float* sr = sinb + (size_t)t * nDH;
    ptr[d]      = rntf(x1 * cr[d]      - x2 * sr[d]);
    ptr[d + 64] = rntf(x2 * cr[d + 64] + x1 * sr[d + 64]);
}

// ---------------------------------------------------------------------------
// Router (reads UNROUNDED normed activations from g_xn)
// ---------------------------------------------------------------------------
__global__ void router_kernel(const float* __restrict__ rw) {
    __shared__ float xs[nH];
    __shared__ float lg[nE];
    int t = blockIdx.x;
    for (int i = threadIdx.x; i < nH; i += blockDim.x) xs[i] = g_xn[(size_t)t * nH + i];
    __syncthreads();
    int w = threadIdx.x >> 5, lane = threadIdx.x & 31;
    float s = 0.f;
    for (int i = lane; i < nH; i += 32) s += xs[i] * rw[(size_t)i * nE + w];
    s = warpSum(s);
    if (lane == 0) lg[w] = s;
    __syncthreads();
    if (threadIdx.x == 0) {
        float mx = lg[0];
        #pragma unroll
        for (int e = 1; e < nE; e++) mx = fmaxf(mx, lg[e]);
        float p[nE]; float sum = 0.f;
        #pragma unroll
        for (int e = 0; e < nE; e++) { p[e] = expf(lg[e] - mx); sum += p[e]; }
        #pragma unroll
        for (int e = 0; e < nE; e++) p[e] /= sum;
        int i1 = 0;
        #pragma unroll
        for (int e = 1; e < nE; e++) if (p[e] > p[i1]) i1 = e;
        int i2 = (i1 == 0) ? 1 : 0;
        #pragma unroll
        for (int e = 0; e < nE; e++) if (e != i1 && p[e] > p[i2]) i2 = e;
        float s2 = p[i1] + p[i2];
        g_topi[t * 2] = i1; g_topi[t * 2 + 1] = i2;
        g_topw[t * 2] = p[i1] / s2; g_topw[t * 2 + 1] = p[i2] / s2;
    }
}

// ---------------------------------------------------------------------------
// MoE bookkeeping
// ---------------------------------------------------------------------------
__global__ void reset_kernel() {
    int i = threadIdx.x;
    if (i < nE) { g_counts[i] = 0; g_fill[i] = 0; }
}
__global__ void count_kernel() {
    int t = blockIdx.x * blockDim.x + threadIdx.x;
    if (t >= nT) return;
    atomicAdd(&g_counts[g_topi[t * 2]], 1);
    atomicAdd(&g_counts[g_topi[t * 2 + 1]], 1);
}
__global__ void scan_kernel() {
    if (threadIdx.x != 0) return;
    int off = 0, nt = 0;
    for (int e = 0; e < nE; e++) {
        g_coff[e] = off;
        int ne = g_counts[e];
        int ntl = (ne + 127) >> 7;
        for (int i = 0; i < ntl; i++) { g_tileE[nt] = e; g_tileR0[nt] = off + i * 128; nt++; }
        off += ne;
    }
    g_coff[nE] = off;
    for (int i = nt; i < MAXTILE; i++) g_tileE[i] = -1;
}
__global__ void scatter_kernel() {
    int t = blockIdx.x * blockDim.x + threadIdx.x;
    if (t >= nT) return;
    #pragma unroll
    for (int k = 0; k < 2; k++) {
        int e = g_topi[t * 2 + k];
        int pos = g_coff[e] + atomicAdd(&g_fill[e], 1);
        g_toklist[pos] = t;
        g_slot[t * 2 + k] = pos;
    }
}

__global__ void combine_kernel(float* __restrict__ out) {
    size_t i = (size_t)blockIdx.x * blockDim.x + threadIdx.x;
    if (i >= (size_t)nT * nH) return;
    int t = (int)(i / nH), j = (int)(i % nH);
    float v = g_hidden[i];
    v += g_topw[t * 2]     * g_part[(size_t)g_slot[t * 2]     * nH + j];
    v += g_topw[t * 2 + 1] * g_part[(size_t)g_slot[t * 2 + 1] * nH + j];
    out[i] = v;
}

// ---------------------------------------------------------------------------
// Launch
// ---------------------------------------------------------------------------
static void launch_gemm(const float* A, long long lda, const float* B, long long ldb,
                        float* C, long long ldc, const float* res,
                        int M, int N, int K, float alpha, int mode, int roundC,
                        int fuseSilu, dim3 grid,
                        long long sAb = 0, long long sAh = 0, long long sBb = 0,
                        long long sBh = 0, long long sCb = 0, long long sCh = 0,
                        int zmod = 1, int groups = 1) {
    GArgs g;
    g.A = A; g.B = B; g.C = C; g.res = res;
    g.lda = lda; g.ldb = ldb; g.ldc = ldc;
    g.M = M; g.N = N; g.K = K; g.alpha = alpha; g.mode = mode; g.roundC = roundC;
    g.fuseSilu = fuseSilu;
    g.sAb = sAb; g.sAh = sAh; g.sBb = sBb; g.sBh = sBh; g.sCb = sCb; g.sCh = sCh;
    g.zmod = zmod; g.groups = groups;
    tc_gemm<<<grid, 256, SMEM_BYTES>>>(g);
}

extern "C" void kernel_launch(void* const* d_in, const int* in_sizes, int n_in,
                              void* d_out, int out_size) {
    const float* hs   = (const float*)d_in[0];
    const float* cosb = (const float*)d_in[1];
    const float* sinb = (const float*)d_in[2];
    const float* wq   = (const float*)d_in[3];
    const float* wk   = (const float*)d_in[4];
    const float* wv   = (const float*)d_in[5];
    const float* wo   = (const float*)d_in[6];
    const float* ln1  = (const float*)d_in[7];
    const float* ln2  = (const float*)d_in[8];
    const float* rw   = (const float*)d_in[9];
    const float* gw   = (const float*)d_in[10];
    const float* uw   = (const float*)d_in[11];
    const float* dw   = (const float*)d_in[12];
    float* out = (float*)d_out;

    static bool attr_set = false;
    if (!attr_set) {
        cudaFuncSetAttribute(tc_gemm, cudaFuncAttributeMaxDynamicSharedMemorySize, SMEM_BYTES);
        cudaFuncSetAttribute(flash_kernel, cudaFuncAttributeMaxDynamicSharedMemorySize, FA_BYTES);
        attr_set = true;
    }

    float* wqT; cudaGetSymbolAddress((void**)&wqT, g_wqT);
    float* wkT; cudaGetSymbolAddress((void**)&wkT, g_wkT);
    float* wvT; cudaGetSymbolAddress((void**)&wvT, g_wvT);
    float* woT; cudaGetSymbolAddress((void**)&woT, g_woT);
    float* gwT; cudaGetSymbolAddress((void**)&gwT, g_gwT);
    float* uwT; cudaGetSymbolAddress((void**)&uwT, g_uwT);
    float* dwT; cudaGetSymbolAddress((void**)&dwT, g_dwT);
    float* xn;  cudaGetSymbolAddress((void**)&xn, g_xn);
    float* q;   cudaGetSymbolAddress((void**)&q, g_q);
    float* k;   cudaGetSymbolAddress((void**)&k, g_k);
    float* v;   cudaGetSymbolAddress((void**)&v, g_v);
    float* at;  cudaGetSymbolAddress((void**)&at, g_attn);
    float* hid; cudaGetSymbolAddress((void**)&hid, g_hidden);
    float* x2;  cudaGetSymbolAddress((void**)&x2, g_x2);
    float* gb;  cudaGetSymbolAddress((void**)&gb, g_gbuf);
    float* ub;  cudaGetSymbolAddress((void**)&ub, g_ubuf);
    float* pt;  cudaGetSymbolAddress((void**)&pt, g_part);

    reset_kernel<<<1, 32>>>();

    // Weight transposes -> [N][K], tf32-rounded (tile 32k x 128n)
    transpose_kernel<<<dim3(16, 64, 1), 256>>>(wq, wqT, nH, nNH * nDH);
    transpose_kernel<<<dim3(4, 64, 1), 256>>>(wk, wkT, nH, nNKV * nDH);
    transpose_kernel<<<dim3(4, 64, 1), 256>>>(wv, wvT, nH, nNKV * nDH);
    transpose_kernel<<<dim3(16, 64, 1), 256>>>(wo, woT, nH, nH);
    transpose_kernel<<<dim3(11, 64, nE), 256>>>(gw, gwT, nH, nMI);
    transpose_kernel<<<dim3(11, 64, nE), 256>>>(uw, uwT, nH, nMI);
    transpose_kernel<<<dim3(16, 44, nE), 256>>>(dw, dwT, nMI, nH);

    rmsnorm1_kernel<<<nT, 256>>>(hs, ln1);

    launch_gemm(xn, nH, wqT, nH, q, nNH * nDH, nullptr, nT, nNH * nDH, nH, 1.f, 0, 0, 0,
                dim3(16, 32, 1));
    launch_gemm(xn, nH, wkT, nH, k, nNKV * nDH, nullptr, nT, nNKV * nDH, nH, 1.f, 0, 0, 0,
                dim3(4, 32, 1));
    launch_gemm(xn, nH, wvT, nH, v, nNKV * nDH, nullptr, nT, nNKV * nDH, nH, 1.f, 0, 1, 0,
                dim3(4, 32, 1));   // V rounded: feeds flash AV

    rope_kernel<<<(nT * (nNH + nNKV) * 64) / 256, 256>>>(cosb, sinb);

    // fused attention: QK + online softmax + AV
    flash_kernel<<<dim3(nS / 128, nB * nNH), 256, FA_BYTES>>>();

    // hidden = attn @ wo + residual (fp32 out)
    launch_gemm(at, nH, woT, nH, hid, nH, hs, nT, nH, nH, 1.f, 0, 0, 0, dim3(16, 32, 1));

    rmsnorm2_kernel<<<nT, 256>>>(ln2);
    router_kernel<<<nT, 256>>>(rw);

    count_kernel<<<nT / 256, 256>>>();
    scan_kernel<<<1, 1>>>();
    scatter_kernel<<<nT / 256, 256>>>();

    // MoE: gate (raw out), up with fused silu epilogue, down
    launch_gemm(x2, nH, gwT, nH, gb, nMI, nullptr, GR, nMI, nH, 1.f, 1, 0, 0,
                dim3(11, MAXTILE, 1));
    launch_gemm(x2, nH, uwT, nH, ub, nMI, gb, GR, nMI, nH, 1.f, 1, 0, 1,
                dim3(11, MAXTILE, 1));
    launch_gemm(ub, nMI, dwT, nMI, pt, nH, nullptr, GR, nH, nMI, 1.f, 2, 0, 0,
                dim3(16, MAXTILE, 1));

    combine_kernel<<<((size_t)nT * nH) / 256, 256>>>(out);
}

// round 9
// speedup vs baseline: 1.9590x; 1.6857x over previous
#include <cuda_runtime.h>
#include <cuda_fp16.h>
#include <math.h>
#include <stdint.h>

// ---------------------------------------------------------------------------
// Problem constants
// ---------------------------------------------------------------------------
namespace {
constexpr int nB = 2, nS = 2048, nH = 2048, nNH = 16, nNKV = 4, nDH = 128;
constexpr int nE = 8, nMI = 1408;
constexpr int nT = nB * nS;          // 4096 tokens
constexpr int GR = nT * 2;           // 8192 gathered (token, expert) rows
constexpr int MAXTILE = 72;
constexpr float RMS_EPS = 1e-6f;
constexpr float QK_SCALE = 0.088388347648318447f;  // 1/sqrt(128)

// GEMM smem (half indices): 2 bufs x (A 128x72 + B 128x72)
constexpr int GA0 = 0, GA1 = 9216, GB0 = 18432, GB1 = 27648;
constexpr int G_HALFS = 36864;
constexpr int SMEM_BYTES = G_HALFS * 2;            // 73728

// flash smem (half indices)
constexpr int FA_QS = 0;                 // Q  [128][136]
constexpr int FA_KS = 17408;             // K  [64][136]
constexpr int FA_VS = 26112;             // V^T 2 x [128][72]
constexpr int FA_PS = 44544;             // P  [128][72]
constexpr int FA_END = 53760;            // halfs
constexpr int FA_RMf = FA_END / 2;       // float idx: rowmax [128][2]
constexpr int FA_RLf = FA_RMf + 256;     // float idx: rowsum [128][2]
constexpr int FA_BYTES = (FA_RLf + 256) * 4;   // 109568
}

// ---------------------------------------------------------------------------
// Scratch (device globals)
// ---------------------------------------------------------------------------
__device__ __half g_xnh  [(size_t)nT * nH];        // rmsnorm1 out (half)
__device__ float  g_xf   [(size_t)nT * nH];        // unrounded rmsnorm2 (router)
__device__ __half g_q    [(size_t)nT * nNH * nDH];
__device__ __half g_k    [(size_t)nT * nNKV * nDH];
__device__ __half g_v    [(size_t)nT * nNKV * nDH];
__device__ __half g_vT   [(size_t)nB * nNKV * nDH * nS];
__device__ __half g_attn [(size_t)nT * nH];
__device__ float  g_hidden[(size_t)nT * nH];
__device__ __half g_x2h  [(size_t)nT * nH];
__device__ int    g_topi [nT * 2];
__device__ float  g_topw [nT * 2];
__device__ int    g_counts[nE];
__device__ int    g_fill [nE];
__device__ int    g_coff [nE + 1];
__device__ int    g_tileE[MAXTILE];
__device__ int    g_tileR0[MAXTILE];
__device__ int    g_toklist[GR];
__device__ int    g_slot [nT * 2];
__device__ float  g_gbuf [(size_t)GR * nMI];       // raw gate (fp32, silu input)
__device__ __half g_ubuf [(size_t)GR * nMI];       // silu(g)*u (half)
__device__ float  g_part [(size_t)GR * nH];
// transposed weights [N][K] K-major, fp16
__device__ __half g_wqT [(size_t)(nNH * nDH) * nH];
__device__ __half g_wkT [(size_t)(nNKV * nDH) * nH];
__device__ __half g_wvT [(size_t)(nNKV * nDH) * nH];
__device__ __half g_woT [(size_t)nH * nH];
__device__ __half g_gwT [(size_t)nE * nMI * nH];
__device__ __half g_uwT [(size_t)nE * nMI * nH];
__device__ __half g_dwT [(size_t)nE * nH * nMI];

// ---------------------------------------------------------------------------
// Helpers
// ---------------------------------------------------------------------------
__device__ __forceinline__ uint32_t smem_to_u32(const void* p) {
    uint32_t a;
    asm("{ .reg .u64 t; cvta.to.shared.u64 t, %1; cvt.u32.u64 %0, t; }" : "=r"(a) : "l"(p));
    return a;
}
__device__ __forceinline__ uint32_t pack2h(float x, float y) {
    __half2 h = __floats2half2_rn(x, y);
    return *reinterpret_cast<uint32_t*>(&h);
}
__device__ __forceinline__ void mma_f16(float* d, const uint32_t* a, const uint32_t* b) {
    asm volatile("mma.sync.aligned.m16n8k16.row.col.f32.f16.f16.f32 "
        "{%0,%1,%2,%3}, {%4,%5,%6,%7}, {%8,%9}, {%0,%1,%2,%3};"
        : "+f"(d[0]), "+f"(d[1]), "+f"(d[2]), "+f"(d[3])
        : "r"(a[0]), "r"(a[1]), "r"(a[2]), "r"(a[3]), "r"(b[0]), "r"(b[1]));
}
__device__ __forceinline__ float warpSum(float v) {
    #pragma unroll
    for (int o = 16; o; o >>= 1) v += __shfl_xor_sync(0xffffffffu, v, o);
    return v;
}

// ---------------------------------------------------------------------------
// fp16 mma GEMM: C[M,N] = A[M,K](half,K-major) x B[N,K](half,K-major)
// CTA tile 128x128, K-chunks of 64, 256 threads (8 warps 4m x 2n).
// Outputs: half (rounded) OR float (+optional residual) OR fused-silu half.
// ---------------------------------------------------------------------------
struct GArgs {
    const __half* A; const __half* B;
    float* Cf; __half* Ch;
    const float* resf;       // residual (float out) or gate buffer (fuseSilu)
    long long lda, ldb, ldc;
    int M, N, K;
    int mode;     // 0 normal, 1 moe gather-A, 2 moe no-gather
    int outHalf;  // write Ch (half) else Cf (float)
    int fuseSilu; // Ch = h(silu(resf) * acc)
};

__global__ void __launch_bounds__(256) tc_gemm(GArgs g) {
    extern __shared__ __half gsm[];
    const int tid = threadIdx.x, lane = tid & 31, wid = tid >> 5;
    const int wm = wid & 3, wn = wid >> 2;
    const int gq = lane >> 2, qq = lane & 3;

    int m0, Mb;
    const __half* Ab = g.A;
    const __half* Bb = g.B;
    if (g.mode >= 1) {
        int e = g_tileE[blockIdx.y];
        if (e < 0) return;
        m0 = g_tileR0[blockIdx.y];
        Mb = g_coff[e + 1];
        Bb += (size_t)e * g.N * g.K;
    } else {
        m0 = blockIdx.y * 128;
        Mb = g.M;
    }
    const int n0 = blockIdx.x * 128;

    __shared__ int rt[128];
    if (tid < 128) {
        int m = m0 + tid;
        int r = (m < Mb) ? m : -1;
        if (g.mode == 1 && r >= 0) r = g_toklist[r];
        rt[tid] = r;
    }
    __syncthreads();

    const uint32_t sbase = smem_to_u32(gsm);
    const int NC = g.K >> 6;

    auto issue = [&](int c, int s) {
        const int k0 = c << 6;
        #pragma unroll
        for (int p = 0; p < 4; p++) {
            int idx = p * 256 + tid;
            int row = idx >> 3, c8 = idx & 7;
            int r = rt[row];
            const __half* src = (r >= 0 ? Ab + (size_t)r * g.lda : Ab) + k0 + c8 * 8;
            uint32_t dst = sbase + (uint32_t)((s ? GA1 : GA0) + row * 72 + c8 * 8) * 2u;
            int sz = (r >= 0) ? 16 : 0;
            asm volatile("cp.async.cg.shared.global [%0], [%1], 16, %2;"
                         :: "r"(dst), "l"(src), "r"(sz) : "memory");
        }
        #pragma unroll
        for (int p = 0; p < 4; p++) {
            int idx = p * 256 + tid;
            int row = idx >> 3, c8 = idx & 7;
            const __half* src = Bb + (size_t)(n0 + row) * g.ldb + k0 + c8 * 8;
            uint32_t dst = sbase + (uint32_t)((s ? GB1 : GB0) + row * 72 + c8 * 8) * 2u;
            asm volatile("cp.async.cg.shared.global [%0], [%1], 16, %2;"
                         :: "r"(dst), "l"(src), "r"(16) : "memory");
        }
    };

    float acc[2][8][4] = {};

    issue(0, 0);
    asm volatile("cp.async.commit_group;" ::: "memory");
    if (NC > 1) issue(1, 1);
    asm volatile("cp.async.commit_group;" ::: "memory");

    const uint32_t* su = reinterpret_cast<const uint32_t*>(gsm);

    for (int c = 0; c < NC; c++) {
        const int s = c & 1;
        asm volatile("cp.async.wait_group 1;" ::: "memory");
        __syncthreads();
        const uint32_t* Asm = su + (s ? GA1 : GA0) / 2;
        const uint32_t* Bsm = su + (s ? GB1 : GB0) / 2;
        #pragma unroll
        for (int kk = 0; kk < 4; kk++) {
            const int kb = kk * 8;                 // u32 offset (16 halfs)
            uint32_t af[2][4];
            #pragma unroll
            for (int mt = 0; mt < 2; mt++) {
                int r0 = wm * 32 + mt * 16 + gq;
                af[mt][0] = Asm[r0 * 36 + kb + qq];
                af[mt][1] = Asm[(r0 + 8) * 36 + kb + qq];
                af[mt][2] = Asm[r0 * 36 + kb + qq + 4];
                af[mt][3] = Asm[(r0 + 8) * 36 + kb + qq + 4];
            }
            uint32_t bf[8][2];
            #pragma unroll
            for (int nt = 0; nt < 8; nt++) {
                int c0 = wn * 64 + nt * 8 + gq;
                bf[nt][0] = Bsm[c0 * 36 + kb + qq];
                bf[nt][1] = Bsm[c0 * 36 + kb + qq + 4];
            }
            #pragma unroll
            for (int mt = 0; mt < 2; mt++)
                #pragma unroll
                for (int nt = 0; nt < 8; nt++)
                    mma_f16(acc[mt][nt], af[mt], bf[nt]);
        }
        __syncthreads();
        if (c + 2 < NC) issue(c + 2, s);
        asm volatile("cp.async.commit_group;" ::: "memory");
    }

    // Epilogue
    #pragma unroll
    for (int mt = 0; mt < 2; mt++) {
        #pragma unroll
        for (int half_ = 0; half_ < 2; half_++) {
            int r = m0 + wm * 32 + mt * 16 + half_ * 8 + gq;
            if (r >= Mb) continue;
            const int cb = n0 + wn * 64 + 2 * qq;
            #pragma unroll
            for (int nt = 0; nt < 8; nt++) {
                float vx = acc[mt][nt][half_ * 2 + 0];
                float vy = acc[mt][nt][half_ * 2 + 1];
                int col = cb + nt * 8;
                if (g.fuseSilu) {
                    const float* gr = g.resf + (size_t)r * g.ldc + col;
                    float gx = gr[0], gy = gr[1];
                    vx = gx * (1.f / (1.f + expf(-gx))) * vx;
                    vy = gy * (1.f / (1.f + expf(-gy))) * vy;
                    *reinterpret_cast<uint32_t*>(g.Ch + (size_t)r * g.ldc + col) = pack2h(vx, vy);
                } else if (g.outHalf) {
                    *reinterpret_cast<uint32_t*>(g.Ch + (size_t)r * g.ldc + col) = pack2h(vx, vy);
                } else {
                    if (g.resf) {
                        float2 rv = *reinterpret_cast<const float2*>(g.resf + (size_t)r * g.ldc + col);
                        vx += rv.x; vy += rv.y;
                    }
                    *reinterpret_cast<float2*>(g.Cf + (size_t)r * g.ldc + col) = make_float2(vx, vy);
                }
            }
        }
    }
}

// ---------------------------------------------------------------------------
// Fused flash attention, fp16 operands / fp32 softmax+accum.
// ---------------------------------------------------------------------------
__global__ void __launch_bounds__(256) flash_kernel() {
    extern __shared__ __half fh[];
    float* ff = reinterpret_cast<float*>(fh);
    const uint32_t* fu = reinterpret_cast<const uint32_t*>(fh);
    const int tid = threadIdx.x, lane = tid & 31, wid = tid >> 5;
    const int wm = wid & 3, wn = wid >> 2;
    const int gq = lane >> 2, qq = lane & 3;
    const int bh = blockIdx.y, b = bh >> 4, h = bh & 15, kh = h >> 2;
    const int q0 = blockIdx.x * 128;

    const __half* Qg = g_q + ((size_t)(b * nS + q0)) * (nNH * nDH) + h * nDH;
    const __half* Kg = g_k + (size_t)b * nS * (nNKV * nDH) + kh * nDH;
    const __half* Vt = g_vT + ((size_t)(b * nNKV + kh)) * nDH * nS;   // [dh][S]
    __half* Og = g_attn + ((size_t)(b * nS + q0)) * nH + h * nDH;

    const uint32_t sb = smem_to_u32(fh);

    // Q tile: 128 rows x 128 halfs (stride 136)
    #pragma unroll
    for (int p = 0; p < 8; p++) {
        int idx = p * 256 + tid;
        int row = idx >> 4, c8 = idx & 15;
        uint32_t dst = sb + (uint32_t)(FA_QS + row * 136 + c8 * 8) * 2u;
        const __half* src = Qg + (size_t)row * (nNH * nDH) + c8 * 8;
        asm volatile("cp.async.cg.shared.global [%0], [%1], 16;"
                     :: "r"(dst), "l"(src) : "memory");
    }
    asm volatile("cp.async.commit_group;" ::: "memory");

    auto issueKV = [&](int it2) {
        const __half* kg = Kg + (size_t)(it2 * 64) * (nNKV * nDH);
        const __half* vg = Vt + it2 * 64;
        const int vb = FA_VS + (it2 & 1) * 9216;
        // K: 64 rows x 128 halfs (stride 136)
        #pragma unroll
        for (int p = 0; p < 4; p++) {
            int idx = p * 256 + tid;
            int row = idx >> 4, c8 = idx & 15;
            uint32_t dk = sb + (uint32_t)(FA_KS + row * 136 + c8 * 8) * 2u;
            asm volatile("cp.async.cg.shared.global [%0], [%1], 16;"
                         :: "r"(dk), "l"(kg + (size_t)row * (nNKV * nDH) + c8 * 8) : "memory");
        }
        // V^T: 128 rows(dh) x 64 halfs (stride 72)
        #pragma unroll
        for (int p = 0; p < 4; p++) {
            int idx = p * 256 + tid;
            int row = idx >> 3, c8 = idx & 7;
            uint32_t dv = sb + (uint32_t)(vb + row * 72 + c8 * 8) * 2u;
            asm volatile("cp.async.cg.shared.global [%0], [%1], 16;"
                         :: "r"(dv), "l"(vg + (size_t)row * nS + c8 * 8) : "memory");
        }
    };
    issueKV(0);
    asm volatile("cp.async.commit_group;" ::: "memory");

    float accO[2][8][4] = {};
    float rm[2][2] = {{-1e30f, -1e30f}, {-1e30f, -1e30f}};
    float rl[2][2] = {{0.f, 0.f}, {0.f, 0.f}};
    const int QSu = FA_QS / 2, KSu = FA_KS / 2, PSu = FA_PS / 2;

    for (int it = 0; it < nS / 64; it++) {
        asm volatile("cp.async.wait_group 0;" ::: "memory");
        __syncthreads();

        // --- S = Q x K^T (warp 32 q x 32 keys), k16 steps over dh=128 ---
        float S[2][4][4] = {};
        #pragma unroll
        for (int kc = 0; kc < 8; kc++) {
            const int kb = kc * 8;
            uint32_t af[2][4];
            #pragma unroll
            for (int mt = 0; mt < 2; mt++) {
                int r0 = wm * 32 + mt * 16 + gq;
                af[mt][0] = fu[QSu + r0 * 68 + kb + qq];
                af[mt][1] = fu[QSu + (r0 + 8) * 68 + kb + qq];
                af[mt][2] = fu[QSu + r0 * 68 + kb + qq + 4];
                af[mt][3] = fu[QSu + (r0 + 8) * 68 + kb + qq + 4];
            }
            uint32_t bf[4][2];
            #pragma unroll
            for (int nt = 0; nt < 4; nt++) {
                int c0 = wn * 32 + nt * 8 + gq;
                bf[nt][0] = fu[KSu + c0 * 68 + kb + qq];
                bf[nt][1] = fu[KSu + c0 * 68 + kb + qq + 4];
            }
            #pragma unroll
            for (int mt = 0; mt < 2; mt++)
                #pragma unroll
                for (int nt = 0; nt < 4; nt++)
                    mma_f16(S[mt][nt], af[mt], bf[nt]);
        }
        __syncthreads();
        if (it + 1 < nS / 64) issueKV(it + 1);
        asm volatile("cp.async.commit_group;" ::: "memory");

        // --- scale + tile row max ---
        float tmax[2][2] = {{-1e30f, -1e30f}, {-1e30f, -1e30f}};
        #pragma unroll
        for (int mt = 0; mt < 2; mt++)
            #pragma unroll
            for (int nt = 0; nt < 4; nt++)
                #pragma unroll
                for (int c = 0; c < 4; c++) {
                    S[mt][nt][c] *= QK_SCALE;
                    tmax[mt][c >> 1] = fmaxf(tmax[mt][c >> 1], S[mt][nt][c]);
                }
        #pragma unroll
        for (int mt = 0; mt < 2; mt++)
            #pragma unroll
            for (int hf = 0; hf < 2; hf++) {
                float v = tmax[mt][hf];
                v = fmaxf(v, __shfl_xor_sync(0xffffffffu, v, 1));
                v = fmaxf(v, __shfl_xor_sync(0xffffffffu, v, 2));
                tmax[mt][hf] = v;
            }
        if (qq == 0) {
            #pragma unroll
            for (int mt = 0; mt < 2; mt++)
                #pragma unroll
                for (int hf = 0; hf < 2; hf++)
                    ff[FA_RMf + (wm * 32 + mt * 16 + hf * 8 + gq) * 2 + wn] = tmax[mt][hf];
        }
        __syncthreads();

        float newm[2][2], sco[2][2];
        #pragma unroll
        for (int mt = 0; mt < 2; mt++)
            #pragma unroll
            for (int hf = 0; hf < 2; hf++) {
                int r = wm * 32 + mt * 16 + hf * 8 + gq;
                float tm = fmaxf(ff[FA_RMf + r * 2], ff[FA_RMf + r * 2 + 1]);
                float nm = fmaxf(rm[mt][hf], tm);
                sco[mt][hf] = __expf(rm[mt][hf] - nm);
                newm[mt][hf] = nm;
                rm[mt][hf] = nm;
            }

        // --- P = exp(S-newm) -> half tile; partial sums fp32 ---
        float ps[2][2] = {{0.f, 0.f}, {0.f, 0.f}};
        uint32_t* Pw = reinterpret_cast<uint32_t*>(fh);
        #pragma unroll
        for (int mt = 0; mt < 2; mt++) {
            int r0 = wm * 32 + mt * 16 + gq;
            #pragma unroll
            for (int nt = 0; nt < 4; nt++) {
                int ci = wn * 16 + nt * 4 + qq;    // u32 col index (= col/2)
                float p0 = __expf(S[mt][nt][0] - newm[mt][0]);
                float p1 = __expf(S[mt][nt][1] - newm[mt][0]);
                float p2 = __expf(S[mt][nt][2] - newm[mt][1]);
                float p3 = __expf(S[mt][nt][3] - newm[mt][1]);
                ps[mt][0] += p0 + p1;
                ps[mt][1] += p2 + p3;
                Pw[PSu + r0 * 36 + ci] = pack2h(p0, p1);
                Pw[PSu + (r0 + 8) * 36 + ci] = pack2h(p2, p3);
            }
        }
        #pragma unroll
        for (int mt = 0; mt < 2; mt++)
            #pragma unroll
            for (int hf = 0; hf < 2; hf++) {
                float v = ps[mt][hf];
                v += __shfl_xor_sync(0xffffffffu, v, 1);
                v += __shfl_xor_sync(0xffffffffu, v, 2);
                ps[mt][hf] = v;
            }
        if (qq == 0) {
            #pragma unroll
            for (int mt = 0; mt < 2; mt++)
                #pragma unroll
                for (int hf = 0; hf < 2; hf++)
                    ff[FA_RLf + (wm * 32 + mt * 16 + hf * 8 + gq) * 2 + wn] = ps[mt][hf];
        }
        __syncthreads();

        #pragma unroll
        for (int mt = 0; mt < 2; mt++)
            #pragma unroll
            for (int hf = 0; hf < 2; hf++) {
                int r = wm * 32 + mt * 16 + hf * 8 + gq;
                float ts = ff[FA_RLf + r * 2] + ff[FA_RLf + r * 2 + 1];
                rl[mt][hf] = rl[mt][hf] * sco[mt][hf] + ts;
            }
        #pragma unroll
        for (int mt = 0; mt < 2; mt++)
            #pragma unroll
            for (int nt = 0; nt < 8; nt++) {
                accO[mt][nt][0] *= sco[mt][0];
                accO[mt][nt][1] *= sco[mt][0];
                accO[mt][nt][2] *= sco[mt][1];
                accO[mt][nt][3] *= sco[mt][1];
            }

        // --- O += P x V (warp 32 q x 64 dh), k16 steps over 64 keys ---
        const int Vu = (FA_VS + (it & 1) * 9216) / 2;
        #pragma unroll
        for (int kc = 0; kc < 4; kc++) {
            const int kb = kc * 8;
            uint32_t af[2][4];
            #pragma unroll
            for (int mt = 0; mt < 2; mt++) {
                int r0 = wm * 32 + mt * 16 + gq;
                af[mt][0] = fu[PSu + r0 * 36 + kb + qq];
                af[mt][1] = fu[PSu + (r0 + 8) * 36 + kb + qq];
                af[mt][2] = fu[PSu + r0 * 36 + kb + qq + 4];
                af[mt][3] = fu[PSu + (r0 + 8) * 36 + kb + qq + 4];
            }
            uint32_t bf[8][2];
            #pragma unroll
            for (int nt = 0; nt < 8; nt++) {
                int c0 = wn * 64 + nt * 8 + gq;    // dh index
                bf[nt][0] = fu[Vu + c0 * 36 + kb + qq];
                bf[nt][1] = fu[Vu + c0 * 36 + kb + qq + 4];
            }
            #pragma unroll
            for (int mt = 0; mt < 2; mt++)
                #pragma unroll
                for (int nt = 0; nt < 8; nt++)
                    mma_f16(accO[mt][nt], af[mt], bf[nt]);
        }
    }

    // epilogue: O/l -> half
    #pragma unroll
    for (int mt = 0; mt < 2; mt++)
        #pragma unroll
        for (int hf = 0; hf < 2; hf++) {
            int r = wm * 32 + mt * 16 + hf * 8 + gq;
            float inv = 1.f / rl[mt][hf];
            #pragma unroll
            for (int nt = 0; nt < 8; nt++) {
                int col = wn * 64 + nt * 8 + 2 * qq;
                *reinterpret_cast<uint32_t*>(Og + (size_t)r * nH + col) =
                    pack2h(accO[mt][nt][hf * 2 + 0] * inv, accO[mt][nt][hf * 2 + 1] * inv);
            }
        }
}

// ---------------------------------------------------------------------------
// Weight transpose fp32->fp16: in [z][K][N] -> out [z][N][K]
// ---------------------------------------------------------------------------
__global__ void __launch_bounds__(256) transpose_kernel(const float* __restrict__ in,
                                                        __half* __restrict__ out,
                                                        int K, int N) {
    __shared__ float t[32][137];
    const float* ip = in + (size_t)blockIdx.z * K * N;
    __half* op = out + (size_t)blockIdx.z * K * N;
    const int n0 = blockIdx.x * 128, k0 = blockIdx.y * 32;
    const int tid = threadIdx.x;
    const int rr = tid >> 5, rc = tid & 31;
    #pragma unroll
    for (int p = 0; p < 4; p++) {
        int kk = rr + p * 8;
        float4 v = *reinterpret_cast<const float4*>(ip + (size_t)(k0 + kk) * N + n0 + rc * 4);
        t[kk][rc * 4 + 0] = v.x; t[kk][rc * 4 + 1] = v.y;
        t[kk][rc * 4 + 2] = v.z; t[kk][rc * 4 + 3] = v.w;
    }
    __syncthreads();
    const int wr = tid >> 2, wk8 = (tid & 3) * 8;
    #pragma unroll
    for (int p = 0; p < 2; p++) {
        int nn = wr + p * 64;
        __half hv[8];
        #pragma unroll
        for (int j = 0; j < 8; j++) hv[j] = __float2half_rn(t[wk8 + j][nn]);
        *reinterpret_cast<uint4*>(op + (size_t)(n0 + nn) * K + k0 + wk8) =
            *reinterpret_cast<uint4*>(hv);
    }
}

// V transpose (half): g_v [b*S][512] head kh -> g_vT [(b*4+kh)][dh][S]
__global__ void vtrans_kernel() {
    __shared__ __half t[32][33];
    int z = blockIdx.z, b = z >> 2, kh = z & 3;
    int s0 = blockIdx.x * 32, d0 = blockIdx.y * 32;
    int tx = threadIdx.x & 31, ty = threadIdx.x >> 5;
    #pragma unroll
    for (int i = ty; i < 32; i += 8)
        t[i][tx] = g_v[((size_t)(b * nS + s0 + i)) * (nNKV * nDH) + kh * nDH + d0 + tx];
    __syncthreads();
    #pragma unroll
    for (int i = ty; i < 32; i += 8)
        g_vT[((size_t)z * nDH + d0 + i) * nS + s0 + tx] = t[tx][i];
}

// ---------------------------------------------------------------------------
// RMSNorm. rmsnorm1 -> half only. rmsnorm2 -> half + unrounded float (router).
// ---------------------------------------------------------------------------
template <bool DUAL>
__device__ __forceinline__ void rmsnorm_row(const float* __restrict__ x,
                                            const float* __restrict__ w,
                                            __half* __restrict__ out_h,
                                            float* __restrict__ out_f) {
    int row = blockIdx.x;
    const float* xr = x + (size_t)row * nH;
    float ss = 0.f;
    for (int i = threadIdx.x; i < nH; i += blockDim.x) { float v = xr[i]; ss += v * v; }
    __shared__ float sm[8];
    int lane = threadIdx.x & 31, wid = threadIdx.x >> 5;
    ss = warpSum(ss);
    if (lane == 0) sm[wid] = ss;
    __syncthreads();
    if (wid == 0) {
        float v = (lane < 8) ? sm[lane] : 0.f;
        v = warpSum(v);
        if (lane == 0) sm[0] = rsqrtf(v / (float)nH + RMS_EPS);
    }
    __syncthreads();
    float inv = sm[0];
    for (int i = threadIdx.x; i < nH; i += blockDim.x) {
        float v = xr[i] * inv * w[i];
        out_h[(size_t)row * nH + i] = __float2half_rn(v);
        if (DUAL) out_f[(size_t)row * nH + i] = v;
    }
}
__global__ void rmsnorm1_kernel(const float* __restrict__ hs, const float* __restrict__ w) {
    rmsnorm_row<false>(hs, w, g_xnh, nullptr);
}
__global__ void rmsnorm2_kernel(const float* __restrict__ w) {
    rmsnorm_row<true>(g_hidden, w, g_x2h, g_xf);
}

// ---------------------------------------------------------------------------
// RoPE on half q/k (fp32 math)
// ---------------------------------------------------------------------------
__global__ void rope_kernel(const float* __restrict__ cosb, const float* __restrict__ sinb) {
    int i = blockIdx.x * blockDim.x + threadIdx.x;
    if (i >= nT * (nNH + nNKV) * 64) return;
    int d  = i & 63;
    int hh = (i >> 6) % (nNH + nNKV);
    int t  = i / (64 * (nNH + nNKV));
    __half* ptr = (hh < nNH)
        ? (g_q + (size_t)t * (nNH * nDH) + hh * nDH)
        : (g_k + (size_t)t * (nNKV * nDH) + (hh - nNH) * nDH);
    float x1 = __half2float(ptr[d]), x2 = __half2float(ptr[d + 64]);
    const float* cr = cosb + (size_t)t * nDH;
    const float* sr = sinb + (size_t)t * nDH;
    ptr[d]      = __float2half_rn(x1 * cr[d]      - x2 * sr[d]);
    ptr[d + 64] = __float2half_rn(x2 * cr[d + 64] + x1 * sr[d + 64]);
}

// ---------------------------------------------------------------------------
// Router (UNROUNDED fp32 input)
// ---------------------------------------------------------------------------
__global__ void router_kernel(const float* __restrict__ rw) {
    __shared__ float xs[nH];
    __shared__ float lg[nE];
    int t = blockIdx.x;
    for (int i = threadIdx.x; i < nH; i += blockDim.x) xs[i] = g_xf[(size_t)t * nH + i];
    __syncthreads();
    int w = threadIdx.x >> 5, lane = threadIdx.x & 31;
    float s = 0.f;
    for (int i = lane; i < nH; i += 32) s += xs[i] * rw[(size_t)i * nE + w];
    s = warpSum(s);
    if (lane == 0) lg[w] = s;
    __syncthreads();
    if (threadIdx.x == 0) {
        float mx = lg[0];
        #pragma unroll
        for (int e = 1; e < nE; e++) mx = fmaxf(mx, lg[e]);
        float p[nE]; float sum = 0.f;
        #pragma unroll
        for (int e = 0; e < nE; e++) { p[e] = expf(lg[e] - mx); sum += p[e]; }
        #pragma unroll
        for (int e = 0; e < nE; e++) p[e] /= sum;
        int i1 = 0;
        #pragma unroll
        for (int e = 1; e < nE; e++) if (p[e] > p[i1]) i1 = e;
        int i2 = (i1 == 0) ? 1 : 0;
        #pragma unroll
        for (int e = 0; e < nE; e++) if (e != i1 && p[e] > p[i2]) i2 = e;
        float s2 = p[i1] + p[i2];
        g_topi[t * 2] = i1; g_topi[t * 2 + 1] = i2;
        g_topw[t * 2] = p[i1] / s2; g_topw[t * 2 + 1] = p[i2] / s2;
    }
}

// ---------------------------------------------------------------------------
// MoE bookkeeping
// ---------------------------------------------------------------------------
__global__ void reset_kernel() {
    int i = threadIdx.x;
    if (i < nE) { g_counts[i] = 0; g_fill[i] = 0; }
}
__global__ void count_kernel() {
    int t = blockIdx.x * blockDim.x + threadIdx.x;
    if (t >= nT) return;
    atomicAdd(&g_counts[g_topi[t * 2]], 1);
    atomicAdd(&g_counts[g_topi[t * 2 + 1]], 1);
}
__global__ void scan_kernel() {
    if (threadIdx.x != 0) return;
    int off = 0, nt = 0;
    for (int e = 0; e < nE; e++) {
        g_coff[e] = off;
        int ne = g_counts[e];
        int ntl = (ne + 127) >> 7;
        for (int i = 0; i < ntl; i++) { g_tileE[nt] = e; g_tileR0[nt] = off + i * 128; nt++; }
        off += ne;
    }
    g_coff[nE] = off;
    for (int i = nt; i < MAXTILE; i++) g_tileE[i] = -1;
}
__global__ void scatter_kernel() {
    int t = blockIdx.x * blockDim.x + threadIdx.x;
    if (t >= nT) return;
    #pragma unroll
    for (int k = 0; k < 2; k++) {
        int e = g_topi[t * 2 + k];
        int pos = g_coff[e] + atomicAdd(&g_fill[e], 1);
        g_toklist[pos] = t;
        g_slot[t * 2 + k] = pos;
    }
}

__global__ void combine_kernel(float* __restrict__ out) {
    size_t i = (size_t)blockIdx.x * blockDim.x + threadIdx.x;
    if (i >= (size_t)nT * nH) return;
    int t = (int)(i / nH), j = (int)(i % nH);
    float v = g_hidden[i];
    v += g_topw[t * 2]     * g_part[(size_t)g_slot[t * 2]     * nH + j];
    v += g_topw[t * 2 + 1] * g_part[(size_t)g_slot[t * 2 + 1] * nH + j];
    out[i] = v;
}

// ---------------------------------------------------------------------------
// Launch
// ---------------------------------------------------------------------------
static void launch_gemm(const __half* A, long long lda, const __half* B, long long ldb,
                        float* Cf, __half* Ch, long long ldc, const float* resf,
                        int M, int N, int K, int mode, int outHalf, int fuseSilu,
                        dim3 grid) {
    GArgs g;
    g.A = A; g.B = B; g.Cf = Cf; g.Ch = Ch; g.resf = resf;
    g.lda = lda; g.ldb = ldb; g.ldc = ldc;
    g.M = M; g.N = N; g.K = K;
    g.mode = mode; g.outHalf = outHalf; g.fuseSilu = fuseSilu;
    tc_gemm<<<grid, 256, SMEM_BYTES>>>(g);
}

extern "C" void kernel_launch(void* const* d_in, const int* in_sizes, int n_in,
                              void* d_out, int out_size) {
    const float* hs   = (const float*)d_in[0];
    const float* cosb = (const float*)d_in[1];
    const float* sinb = (const float*)d_in[2];
    const float* wq   = (const float*)d_in[3];
    const float* wk   = (const float*)d_in[4];
    const float* wv   = (const float*)d_in[5];
    const float* wo   = (const float*)d_in[6];
    const float* ln1  = (const float*)d_in[7];
    const float* ln2  = (const float*)d_in[8];
    const float* rw   = (const float*)d_in[9];
    const float* gw   = (const float*)d_in[10];
    const float* uw   = (const float*)d_in[11];
    const float* dw   = (const float*)d_in[12];
    float* out = (float*)d_out;

    static bool attr_set = false;
    if (!attr_set) {
        cudaFuncSetAttribute(tc_gemm, cudaFuncAttributeMaxDynamicSharedMemorySize, SMEM_BYTES);
        cudaFuncSetAttribute(flash_kernel, cudaFuncAttributeMaxDynamicSharedMemorySize, FA_BYTES);
        attr_set = true;
    }

    __half* wqT; cudaGetSymbolAddress((void**)&wqT, g_wqT);
    __half* wkT; cudaGetSymbolAddress((void**)&wkT, g_wkT);
    __half* wvT; cudaGetSymbolAddress((void**)&wvT, g_wvT);
    __half* woT; cudaGetSymbolAddress((void**)&woT, g_woT);
    __half* gwT; cudaGetSymbolAddress((void**)&gwT, g_gwT);
    __half* uwT; cudaGetSymbolAddress((void**)&uwT, g_uwT);
    __half* dwT; cudaGetSymbolAddress((void**)&dwT, g_dwT);
    __half* xnh; cudaGetSymbolAddress((void**)&xnh, g_xnh);
    __half* q;   cudaGetSymbolAddress((void**)&q, g_q);
    __half* k;   cudaGetSymbolAddress((void**)&k, g_k);
    __half* v;   cudaGetSymbolAddress((void**)&v, g_v);
    __half* at;  cudaGetSymbolAddress((void**)&at, g_attn);
    float*  hid; cudaGetSymbolAddress((void**)&hid, g_hidden);
    __half* x2h; cudaGetSymbolAddress((void**)&x2h, g_x2h);
    float*  gb;  cudaGetSymbolAddress((void**)&gb, g_gbuf);
    __half* ub;  cudaGetSymbolAddress((void**)&ub, g_ubuf);
    float*  pt;  cudaGetSymbolAddress((void**)&pt, g_part);

    reset_kernel<<<1, 32>>>();

    // Weight transposes -> [N][K] fp16
    transpose_kernel<<<dim3(16, 64, 1), 256>>>(wq, wqT, nH, nNH * nDH);
    transpose_kernel<<<dim3(4, 64, 1), 256>>>(wk, wkT, nH, nNKV * nDH);
    transpose_kernel<<<dim3(4, 64, 1), 256>>>(wv, wvT, nH, nNKV * nDH);
    transpose_kernel<<<dim3(16, 64, 1), 256>>>(wo, woT, nH, nH);
    transpose_kernel<<<dim3(11, 64, nE), 256>>>(gw, gwT, nH, nMI);
    transpose_kernel<<<dim3(11, 64, nE), 256>>>(uw, uwT, nH, nMI);
    transpose_kernel<<<dim3(16, 44, nE), 256>>>(dw, dwT, nMI, nH);

    rmsnorm1_kernel<<<nT, 256>>>(hs, ln1);

    // QKV projections (half out)
    launch_gemm(xnh, nH, wqT, nH, nullptr, q, nNH * nDH, nullptr,
                nT, nNH * nDH, nH, 0, 1, 0, dim3(16, 32, 1));
    launch_gemm(xnh, nH, wkT, nH, nullptr, k, nNKV * nDH, nullptr,
                nT, nNKV * nDH, nH, 0, 1, 0, dim3(4, 32, 1));
    launch_gemm(xnh, nH, wvT, nH, nullptr, v, nNKV * nDH, nullptr,
                nT, nNKV * nDH, nH, 0, 1, 0, dim3(4, 32, 1));

    rope_kernel<<<(nT * (nNH + nNKV) * 64) / 256, 256>>>(cosb, sinb);
    vtrans_kernel<<<dim3(nS / 32, nDH / 32, nB * nNKV), 256>>>();

    // fused attention
    flash_kernel<<<dim3(nS / 128, nB * nNH), 256, FA_BYTES>>>();

    // hidden = attn @ wo + residual (fp32)
    launch_gemm(at, nH, woT, nH, hid, nullptr, nH, hs,
                nT, nH, nH, 0, 0, 0, dim3(16, 32, 1));

    rmsnorm2_kernel<<<nT, 256>>>(ln2);
    router_kernel<<<nT, 256>>>(rw);

    count_kernel<<<nT / 256, 256>>>();
    scan_kernel<<<1, 1>>>();
    scatter_kernel<<<nT / 256, 256>>>();

    // MoE: gate (fp32 raw), up + fused silu (half), down (fp32)
    launch_gemm(x2h, nH, gwT, nH, gb, nullptr, nMI, nullptr,
                GR, nMI, nH, 1, 0, 0, dim3(11, MAXTILE, 1));
    launch_gemm(x2h, nH, uwT, nH, nullptr, ub, nMI, gb,
                GR, nMI, nH, 1, 0, 1, dim3(11, MAXTILE, 1));
    launch_gemm(ub, nMI, dwT, nMI, pt, nullptr, nH, nullptr,
                GR, nH, nMI, 2, 0, 0, dim3(16, MAXTILE, 1));

    combine_kernel<<<((size_t)nT * nH) / 256, 256>>>(out);
}

// round 10
// speedup vs baseline: 2.0110x; 1.0266x over previous
#include <cuda_runtime.h>
#include <cuda_fp16.h>
#include <math.h>
#include <stdint.h>

// ---------------------------------------------------------------------------
// Problem constants
// ---------------------------------------------------------------------------
namespace {
constexpr int nB = 2, nS = 2048, nH = 2048, nNH = 16, nNKV = 4, nDH = 128;
constexpr int nE = 8, nMI = 1408;
constexpr int nT = nB * nS;          // 4096 tokens
constexpr int GR = nT * 2;           // 8192 gathered (token, expert) rows
constexpr int MAXTILE = 72;
constexpr int nQKV = (nNH + 2 * nNKV) * nDH;       // 3072 fused qkv width
constexpr int KOFF = nNH * nDH;                    // 2048
constexpr int VOFF = KOFF + nNKV * nDH;            // 2560
constexpr float RMS_EPS = 1e-6f;
constexpr float QK_SCALE = 0.088388347648318447f;  // 1/sqrt(128)

// GEMM smem (half indices): 3 stages x (A 128x72 + B 128x72)
constexpr int G_HALFS = 55296;
constexpr int SMEM_BYTES = G_HALFS * 2;            // 110592

// flash smem (half indices)
constexpr int FA_QS = 0;                 // Q  [128][136]
constexpr int FA_KS = 17408;             // K  [64][136]
constexpr int FA_VS = 26112;             // V^T 2 x [128][72]
constexpr int FA_PS = 44544;             // P  [128][72]
constexpr int FA_END = 53760;            // halfs
constexpr int FA_RMf = FA_END / 2;       // float idx: rowmax [128][2]
constexpr int FA_RLf = FA_RMf + 256;     // float idx: rowsum [128][2]
constexpr int FA_BYTES = (FA_RLf + 256) * 4;   // 109568
}

// ---------------------------------------------------------------------------
// Scratch (device globals)
// ---------------------------------------------------------------------------
__device__ __half g_xnh  [(size_t)nT * nH];        // rmsnorm1 out (half)
__device__ float  g_xf   [(size_t)nT * nH];        // unrounded rmsnorm2 (router)
__device__ __half g_qkv  [(size_t)nT * nQKV];      // fused q|k|v (post-rope)
__device__ __half g_vT   [(size_t)nB * nNKV * nDH * nS];
__device__ __half g_attn [(size_t)nT * nH];
__device__ float  g_hidden[(size_t)nT * nH];
__device__ __half g_x2h  [(size_t)nT * nH];
__device__ int    g_topi [nT * 2];
__device__ float  g_topw [nT * 2];
__device__ int    g_counts[nE];
__device__ int    g_fill [nE];
__device__ int    g_coff [nE + 1];
__device__ int    g_tileE[MAXTILE];
__device__ int    g_tileR0[MAXTILE];
__device__ int    g_toklist[GR];
__device__ int    g_slot [nT * 2];
__device__ float  g_gbuf [(size_t)GR * nMI];       // raw gate (fp32, silu input)
__device__ __half g_ubuf [(size_t)GR * nMI];       // silu(g)*u (half)
__device__ float  g_part [(size_t)GR * nH];
// transposed weights [N][K] K-major, fp16
__device__ __half g_wqkvT[(size_t)nQKV * nH];
__device__ __half g_woT [(size_t)nH * nH];
__device__ __half g_gwT [(size_t)nE * nMI * nH];
__device__ __half g_uwT [(size_t)nE * nMI * nH];
__device__ __half g_dwT [(size_t)nE * nH * nMI];

// ---------------------------------------------------------------------------
// Helpers
// ---------------------------------------------------------------------------
__device__ __forceinline__ uint32_t smem_to_u32(const void* p) {
    uint32_t a;
    asm("{ .reg .u64 t; cvta.to.shared.u64 t, %1; cvt.u32.u64 %0, t; }" : "=r"(a) : "l"(p));
    return a;
}
__device__ __forceinline__ uint32_t pack2h(float x, float y) {
    __half2 h = __floats2half2_rn(x, y);
    return *reinterpret_cast<uint32_t*>(&h);
}
__device__ __forceinline__ void mma_f16(float* d, const uint32_t* a, const uint32_t* b) {
    asm volatile("mma.sync.aligned.m16n8k16.row.col.f32.f16.f16.f32 "
        "{%0,%1,%2,%3}, {%4,%5,%6,%7}, {%8,%9}, {%0,%1,%2,%3};"
        : "+f"(d[0]), "+f"(d[1]), "+f"(d[2]), "+f"(d[3])
        : "r"(a[0]), "r"(a[1]), "r"(a[2]), "r"(a[3]), "r"(b[0]), "r"(b[1]));
}
__device__ __forceinline__ float warpSum(float v) {
    #pragma unroll
    for (int o = 16; o; o >>= 1) v += __shfl_xor_sync(0xffffffffu, v, o);
    return v;
}

// ---------------------------------------------------------------------------
// fp16 mma GEMM: C[M,N] = A[M,K](half,K-major) x B[N,K](half,K-major)
// CTA tile 128x128, K-chunks of 64, 3-stage cp.async pipeline, 256 threads.
// ---------------------------------------------------------------------------
struct GArgs {
    const __half* A; const __half* B;
    float* Cf; __half* Ch;
    const float* resf;       // residual (float out) or gate buffer (fuseSilu)
    long long lda, ldb, ldc;
    int M, N, K;
    int mode;     // 0 normal, 1 moe gather-A, 2 moe no-gather
    int outHalf;  // write Ch (half) else Cf (float)
    int fuseSilu; // Ch = h(silu(resf) * acc)
};

__global__ void __launch_bounds__(256) tc_gemm(GArgs g) {
    extern __shared__ __half gsm[];
    const int tid = threadIdx.x, lane = tid & 31, wid = tid >> 5;
    const int wm = wid & 3, wn = wid >> 2;
    const int gq = lane >> 2, qq = lane & 3;

    int m0, Mb;
    const __half* Ab = g.A;
    const __half* Bb = g.B;
    if (g.mode >= 1) {
        int e = g_tileE[blockIdx.y];
        if (e < 0) return;
        m0 = g_tileR0[blockIdx.y];
        Mb = g_coff[e + 1];
        Bb += (size_t)e * g.N * g.K;
    } else {
        m0 = blockIdx.y * 128;
        Mb = g.M;
    }
    const int n0 = blockIdx.x * 128;

    __shared__ int rt[128];
    if (tid < 128) {
        int m = m0 + tid;
        int r = (m < Mb) ? m : -1;
        if (g.mode == 1 && r >= 0) r = g_toklist[r];
        rt[tid] = r;
    }
    __syncthreads();

    const uint32_t sbase = smem_to_u32(gsm);
    const int NC = g.K >> 6;

    auto issue = [&](int c, int s) {
        const int k0 = c << 6;
        const uint32_t ao = (uint32_t)(s * 9216);
        const uint32_t bo = (uint32_t)(27648 + s * 9216);
        #pragma unroll
        for (int p = 0; p < 4; p++) {
            int idx = p * 256 + tid;
            int row = idx >> 3, c8 = idx & 7;
            int r = rt[row];
            const __half* src = (r >= 0 ? Ab + (size_t)r * g.lda : Ab) + k0 + c8 * 8;
            uint32_t dst = sbase + (ao + (uint32_t)(row * 72 + c8 * 8)) * 2u;
            int sz = (r >= 0) ? 16 : 0;
            asm volatile("cp.async.cg.shared.global [%0], [%1], 16, %2;"
                         :: "r"(dst), "l"(src), "r"(sz) : "memory");
        }
        #pragma unroll
        for (int p = 0; p < 4; p++) {
            int idx = p * 256 + tid;
            int row = idx >> 3, c8 = idx & 7;
            const __half* src = Bb + (size_t)(n0 + row) * g.ldb + k0 + c8 * 8;
            uint32_t dst = sbase + (bo + (uint32_t)(row * 72 + c8 * 8)) * 2u;
            asm volatile("cp.async.cg.shared.global [%0], [%1], 16, %2;"
                         :: "r"(dst), "l"(src), "r"(16) : "memory");
        }
    };

    float acc[2][8][4] = {};

    issue(0, 0);
    asm volatile("cp.async.commit_group;" ::: "memory");
    issue(1, 1);
    asm volatile("cp.async.commit_group;" ::: "memory");

    const uint32_t* su = reinterpret_cast<const uint32_t*>(gsm);

    for (int c = 0; c < NC; c++) {
        const int s = c % 3;
        asm volatile("cp.async.wait_group 1;" ::: "memory");
        __syncthreads();
        if (c + 2 < NC) issue(c + 2, (c + 2) % 3);
        asm volatile("cp.async.commit_group;" ::: "memory");

        const uint32_t* Asm = su + s * 4608;
        const uint32_t* Bsm = su + 13824 + s * 4608;
        #pragma unroll
        for (int kk = 0; kk < 4; kk++) {
            const int kb = kk * 8;                 // u32 offset (16 halfs)
            uint32_t af[2][4];
            #pragma unroll
            for (int mt = 0; mt < 2; mt++) {
                int r0 = wm * 32 + mt * 16 + gq;
                af[mt][0] = Asm[r0 * 36 + kb + qq];
                af[mt][1] = Asm[(r0 + 8) * 36 + kb + qq];
                af[mt][2] = Asm[r0 * 36 + kb + qq + 4];
                af[mt][3] = Asm[(r0 + 8) * 36 + kb + qq + 4];
            }
            uint32_t bf[8][2];
            #pragma unroll
            for (int nt = 0; nt < 8; nt++) {
                int c0 = wn * 64 + nt * 8 + gq;
                bf[nt][0] = Bsm[c0 * 36 + kb + qq];
                bf[nt][1] = Bsm[c0 * 36 + kb + qq + 4];
            }
            #pragma unroll
            for (int mt = 0; mt < 2; mt++)
                #pragma unroll
                for (int nt = 0; nt < 8; nt++)
                    mma_f16(acc[mt][nt], af[mt], bf[nt]);
        }
    }

    // Epilogue
    #pragma unroll
    for (int mt = 0; mt < 2; mt++) {
        #pragma unroll
        for (int half_ = 0; half_ < 2; half_++) {
            int r = m0 + wm * 32 + mt * 16 + half_ * 8 + gq;
            if (r >= Mb) continue;
            const int cb = n0 + wn * 64 + 2 * qq;
            #pragma unroll
            for (int nt = 0; nt < 8; nt++) {
                float vx = acc[mt][nt][half_ * 2 + 0];
                float vy = acc[mt][nt][half_ * 2 + 1];
                int col = cb + nt * 8;
                if (g.fuseSilu) {
                    const float* gr = g.resf + (size_t)r * g.ldc + col;
                    float gx = gr[0], gy = gr[1];
                    vx = gx * (1.f / (1.f + expf(-gx))) * vx;
                    vy = gy * (1.f / (1.f + expf(-gy))) * vy;
                    *reinterpret_cast<uint32_t*>(g.Ch + (size_t)r * g.ldc + col) = pack2h(vx, vy);
                } else if (g.outHalf) {
                    *reinterpret_cast<uint32_t*>(g.Ch + (size_t)r * g.ldc + col) = pack2h(vx, vy);
                } else {
                    if (g.resf) {
                        float2 rv = *reinterpret_cast<const float2*>(g.resf + (size_t)r * g.ldc + col);
                        vx += rv.x; vy += rv.y;
                    }
                    *reinterpret_cast<float2*>(g.Cf + (size_t)r * g.ldc + col) = make_float2(vx, vy);
                }
            }
        }
    }
}

// ---------------------------------------------------------------------------
// Fused flash attention, fp16 operands / fp32 softmax+accum.
// ---------------------------------------------------------------------------
__global__ void __launch_bounds__(256) flash_kernel() {
    extern __shared__ __half fh[];
    float* ff = reinterpret_cast<float*>(fh);
    const uint32_t* fu = reinterpret_cast<const uint32_t*>(fh);
    const int tid = threadIdx.x, lane = tid & 31, wid = tid >> 5;
    const int wm = wid & 3, wn = wid >> 2;
    const int gq = lane >> 2, qq = lane & 3;
    const int bh = blockIdx.y, b = bh >> 4, h = bh & 15, kh = h >> 2;
    const int q0 = blockIdx.x * 128;

    const __half* Qg = g_qkv + ((size_t)(b * nS + q0)) * nQKV + h * nDH;
    const __half* Kg = g_qkv + (size_t)b * nS * nQKV + KOFF + kh * nDH;
    const __half* Vt = g_vT + ((size_t)(b * nNKV + kh)) * nDH * nS;   // [dh][S]
    __half* Og = g_attn + ((size_t)(b * nS + q0)) * nH + h * nDH;

    const uint32_t sb = smem_to_u32(fh);

    // Q tile: 128 rows x 128 halfs (stride 136)
    #pragma unroll
    for (int p = 0; p < 8; p++) {
        int idx = p * 256 + tid;
        int row = idx >> 4, c8 = idx & 15;
        uint32_t dst = sb + (uint32_t)(FA_QS + row * 136 + c8 * 8) * 2u;
        const __half* src = Qg + (size_t)row * nQKV + c8 * 8;
        asm volatile("cp.async.cg.shared.global [%0], [%1], 16;"
                     :: "r"(dst), "l"(src) : "memory");
    }
    asm volatile("cp.async.commit_group;" ::: "memory");

    auto issueKV = [&](int it2) {
        const __half* kg = Kg + (size_t)(it2 * 64) * nQKV;
        const __half* vg = Vt + it2 * 64;
        const int vb = FA_VS + (it2 & 1) * 9216;
        #pragma unroll
        for (int p = 0; p < 4; p++) {
            int idx = p * 256 + tid;
            int row = idx >> 4, c8 = idx & 15;
            uint32_t dk = sb + (uint32_t)(FA_KS + row * 136 + c8 * 8) * 2u;
            asm volatile("cp.async.cg.shared.global [%0], [%1], 16;"
                         :: "r"(dk), "l"(kg + (size_t)row * nQKV + c8 * 8) : "memory");
        }
        #pragma unroll
        for (int p = 0; p < 4; p++) {
            int idx = p * 256 + tid;
            int row = idx >> 3, c8 = idx & 7;
            uint32_t dv = sb + (uint32_t)(vb + row * 72 + c8 * 8) * 2u;
            asm volatile("cp.async.cg.shared.global [%0], [%1], 16;"
                         :: "r"(dv), "l"(vg + (size_t)row * nS + c8 * 8) : "memory");
        }
    };
    issueKV(0);
    asm volatile("cp.async.commit_group;" ::: "memory");

    float accO[2][8][4] = {};
    float rm[2][2] = {{-1e30f, -1e30f}, {-1e30f, -1e30f}};
    float rl[2][2] = {{0.f, 0.f}, {0.f, 0.f}};
    const int QSu = FA_QS / 2, KSu = FA_KS / 2, PSu = FA_PS / 2;

    for (int it = 0; it < nS / 64; it++) {
        asm volatile("cp.async.wait_group 0;" ::: "memory");
        __syncthreads();

        float S[2][4][4] = {};
        #pragma unroll
        for (int kc = 0; kc < 8; kc++) {
            const int kb = kc * 8;
            uint32_t af[2][4];
            #pragma unroll
            for (int mt = 0; mt < 2; mt++) {
                int r0 = wm * 32 + mt * 16 + gq;
                af[mt][0] = fu[QSu + r0 * 68 + kb + qq];
                af[mt][1] = fu[QSu + (r0 + 8) * 68 + kb + qq];
                af[mt][2] = fu[QSu + r0 * 68 + kb + qq + 4];
                af[mt][3] = fu[QSu + (r0 + 8) * 68 + kb + qq + 4];
            }
            uint32_t bf[4][2];
            #pragma unroll
            for (int nt = 0; nt < 4; nt++) {
                int c0 = wn * 32 + nt * 8 + gq;
                bf[nt][0] = fu[KSu + c0 * 68 + kb + qq];
                bf[nt][1] = fu[KSu + c0 * 68 + kb + qq + 4];
            }
            #pragma unroll
            for (int mt = 0; mt < 2; mt++)
                #pragma unroll
                for (int nt = 0; nt < 4; nt++)
                    mma_f16(S[mt][nt], af[mt], bf[nt]);
        }
        __syncthreads();
        if (it + 1 < nS / 64) issueKV(it + 1);
        asm volatile("cp.async.commit_group;" ::: "memory");

        float tmax[2][2] = {{-1e30f, -1e30f}, {-1e30f, -1e30f}};
        #pragma unroll
        for (int mt = 0; mt < 2; mt++)
            #pragma unroll
            for (int nt = 0; nt < 4; nt++)
                #pragma unroll
                for (int c = 0; c < 4; c++) {
                    S[mt][nt][c] *= QK_SCALE;
                    tmax[mt][c >> 1] = fmaxf(tmax[mt][c >> 1], S[mt][nt][c]);
                }
        #pragma unroll
        for (int mt = 0; mt < 2; mt++)
            #pragma unroll
            for (int hf = 0; hf < 2; hf++) {
                float v = tmax[mt][hf];
                v = fmaxf(v, __shfl_xor_sync(0xffffffffu, v, 1));
                v = fmaxf(v, __shfl_xor_sync(0xffffffffu, v, 2));
                tmax[mt][hf] = v;
            }
        if (qq == 0) {
            #pragma unroll
            for (int mt = 0; mt < 2; mt++)
                #pragma unroll
                for (int hf = 0; hf < 2; hf++)
                    ff[FA_RMf + (wm * 32 + mt * 16 + hf * 8 + gq) * 2 + wn] = tmax[mt][hf];
        }
        __syncthreads();

        float newm[2][2], sco[2][2];
        #pragma unroll
        for (int mt = 0; mt < 2; mt++)
            #pragma unroll
            for (int hf = 0; hf < 2; hf++) {
                int r = wm * 32 + mt * 16 + hf * 8 + gq;
                float tm = fmaxf(ff[FA_RMf + r * 2], ff[FA_RMf + r * 2 + 1]);
                float nm = fmaxf(rm[mt][hf], tm);
                sco[mt][hf] = __expf(rm[mt][hf] - nm);
                newm[mt][hf] = nm;
                rm[mt][hf] = nm;
            }

        float ps[2][2] = {{0.f, 0.f}, {0.f, 0.f}};
        uint32_t* Pw = reinterpret_cast<uint32_t*>(fh);
        #pragma unroll
        for (int mt = 0; mt < 2; mt++) {
            int r0 = wm * 32 + mt * 16 + gq;
            #pragma unroll
            for (int nt = 0; nt < 4; nt++) {
                int ci = wn * 16 + nt * 4 + qq;
                float p0 = __expf(S[mt][nt][0] - newm[mt][0]);
                float p1 = __expf(S[mt][nt][1] - newm[mt][0]);
                float p2 = __expf(S[mt][nt][2] - newm[mt][1]);
                float p3 = __expf(S[mt][nt][3] - newm[mt][1]);
                ps[mt][0] += p0 + p1;
                ps[mt][1] += p2 + p3;
                Pw[PSu + r0 * 36 + ci] = pack2h(p0, p1);
                Pw[PSu + (r0 + 8) * 36 + ci] = pack2h(p2, p3);
            }
        }
        #pragma unroll
        for (int mt = 0; mt < 2; mt++)
            #pragma unroll
            for (int hf = 0; hf < 2; hf++) {
                float v = ps[mt][hf];
                v += __shfl_xor_sync(0xffffffffu, v, 1);
                v += __shfl_xor_sync(0xffffffffu, v, 2);
                ps[mt][hf] = v;
            }
        if (qq == 0) {
            #pragma unroll
            for (int mt = 0; mt < 2; mt++)
                #pragma unroll
                for (int hf = 0; hf < 2; hf++)
                    ff[FA_RLf + (wm * 32 + mt * 16 + hf * 8 + gq) * 2 + wn] = ps[mt][hf];
        }
        __syncthreads();

        #pragma unroll
        for (int mt = 0; mt < 2; mt++)
            #pragma unroll
            for (int hf = 0; hf < 2; hf++) {
                int r = wm * 32 + mt * 16 + hf * 8 + gq;
                float ts = ff[FA_RLf + r * 2] + ff[FA_RLf + r * 2 + 1];
                rl[mt][hf] = rl[mt][hf] * sco[mt][hf] + ts;
            }
        #pragma unroll
        for (int mt = 0; mt < 2; mt++)
            #pragma unroll
            for (int nt = 0; nt < 8; nt++) {
                accO[mt][nt][0] *= sco[mt][0];
                accO[mt][nt][1] *= sco[mt][0];
                accO[mt][nt][2] *= sco[mt][1];
                accO[mt][nt][3] *= sco[mt][1];
            }

        const int Vu = (FA_VS + (it & 1) * 9216) / 2;
        #pragma unroll
        for (int kc = 0; kc < 4; kc++) {
            const int kb = kc * 8;
            uint32_t af[2][4];
            #pragma unroll
            for (int mt = 0; mt < 2; mt++) {
                int r0 = wm * 32 + mt * 16 + gq;
                af[mt][0] = fu[PSu + r0 * 36 + kb + qq];
                af[mt][1] = fu[PSu + (r0 + 8) * 36 + kb + qq];
                af[mt][2] = fu[PSu + r0 * 36 + kb + qq + 4];
                af[mt][3] = fu[PSu + (r0 + 8) * 36 + kb + qq + 4];
            }
            uint32_t bf[8][2];
            #pragma unroll
            for (int nt = 0; nt < 8; nt++) {
                int c0 = wn * 64 + nt * 8 + gq;
                bf[nt][0] = fu[Vu + c0 * 36 + kb + qq];
                bf[nt][1] = fu[Vu + c0 * 36 + kb + qq + 4];
            }
            #pragma unroll
            for (int mt = 0; mt < 2; mt++)
                #pragma unroll
                for (int nt = 0; nt < 8; nt++)
                    mma_f16(accO[mt][nt], af[mt], bf[nt]);
        }
    }

    #pragma unroll
    for (int mt = 0; mt < 2; mt++)
        #pragma unroll
        for (int hf = 0; hf < 2; hf++) {
            int r = wm * 32 + mt * 16 + hf * 8 + gq;
            float inv = 1.f / rl[mt][hf];
            #pragma unroll
            for (int nt = 0; nt < 8; nt++) {
                int col = wn * 64 + nt * 8 + 2 * qq;
                *reinterpret_cast<uint32_t*>(Og + (size_t)r * nH + col) =
                    pack2h(accO[mt][nt][hf * 2 + 0] * inv, accO[mt][nt][hf * 2 + 1] * inv);
            }
        }
}

// ---------------------------------------------------------------------------
// Weight transpose fp32->fp16: in [z][K][N] -> out [z][N][K]
// ---------------------------------------------------------------------------
__global__ void __launch_bounds__(256) transpose_kernel(const float* __restrict__ in,
                                                        __half* __restrict__ out,
                                                        int K, int N) {
    __shared__ float t[32][137];
    const float* ip = in + (size_t)blockIdx.z * K * N;
    __half* op = out + (size_t)blockIdx.z * K * N;
    const int n0 = blockIdx.x * 128, k0 = blockIdx.y * 32;
    const int tid = threadIdx.x;
    const int rr = tid >> 5, rc = tid & 31;
    #pragma unroll
    for (int p = 0; p < 4; p++) {
        int kk = rr + p * 8;
        float4 v = *reinterpret_cast<const float4*>(ip + (size_t)(k0 + kk) * N + n0 + rc * 4);
        t[kk][rc * 4 + 0] = v.x; t[kk][rc * 4 + 1] = v.y;
        t[kk][rc * 4 + 2] = v.z; t[kk][rc * 4 + 3] = v.w;
    }
    __syncthreads();
    const int wr = tid >> 2, wk8 = (tid & 3) * 8;
    #pragma unroll
    for (int p = 0; p < 2; p++) {
        int nn = wr + p * 64;
        __half hv[8];
        #pragma unroll
        for (int j = 0; j < 8; j++) hv[j] = __float2half_rn(t[wk8 + j][nn]);
        *reinterpret_cast<uint4*>(op + (size_t)(n0 + nn) * K + k0 + wk8) =
            *reinterpret_cast<uint4*>(hv);
    }
}

// V transpose (half): g_qkv v-section -> g_vT [(b*4+kh)][dh][S]
__global__ void vtrans_kernel() {
    __shared__ __half t[32][33];
    int z = blockIdx.z, b = z >> 2, kh = z & 3;
    int s0 = blockIdx.x * 32, d0 = blockIdx.y * 32;
    int tx = threadIdx.x & 31, ty = threadIdx.x >> 5;
    #pragma unroll
    for (int i = ty; i < 32; i += 8)
        t[i][tx] = g_qkv[((size_t)(b * nS + s0 + i)) * nQKV + VOFF + kh * nDH + d0 + tx];
    __syncthreads();
    #pragma unroll
    for (int i = ty; i < 32; i += 8)
        g_vT[((size_t)z * nDH + d0 + i) * nS + s0 + tx] = t[tx][i];
}

// ---------------------------------------------------------------------------
// RMSNorm. rmsnorm1 -> half only. rmsnorm2 -> half + unrounded float (router).
// ---------------------------------------------------------------------------
template <bool DUAL>
__device__ __forceinline__ void rmsnorm_row(const float* __restrict__ x,
                                            const float* __restrict__ w,
                                            __half* __restrict__ out_h,
                                            float* __restrict__ out_f) {
    int row = blockIdx.x;
    const float* xr = x + (size_t)row * nH;
    float ss = 0.f;
    for (int i = threadIdx.x; i < nH; i += blockDim.x) { float v = xr[i]; ss += v * v; }
    __shared__ float sm[8];
    int lane = threadIdx.x & 31, wid = threadIdx.x >> 5;
    ss = warpSum(ss);
    if (lane == 0) sm[wid] = ss;
    __syncthreads();
    if (wid == 0) {
        float v = (lane < 8) ? sm[lane] : 0.f;
        v = warpSum(v);
        if (lane == 0) sm[0] = rsqrtf(v / (float)nH + RMS_EPS);
    }
    __syncthreads();
    float inv = sm[0];
    for (int i = threadIdx.x; i < nH; i += blockDim.x) {
        float v = xr[i] * inv * w[i];
        out_h[(size_t)row * nH + i] = __float2half_rn(v);
        if (DUAL) out_f[(size_t)row * nH + i] = v;
    }
}
__global__ void rmsnorm1_kernel(const float* __restrict__ hs, const float* __restrict__ w) {
    rmsnorm_row<false>(hs, w, g_xnh, nullptr);
}
__global__ void rmsnorm2_kernel(const float* __restrict__ w) {
    rmsnorm_row<true>(g_hidden, w, g_x2h, g_xf);
}

// ---------------------------------------------------------------------------
// RoPE on fused qkv (fp32 math). Only q and k sections.
// ---------------------------------------------------------------------------
__global__ void rope_kernel(const float* __restrict__ cosb, const float* __restrict__ sinb) {
    int i = blockIdx.x * blockDim.x + threadIdx.x;
    if (i >= nT * (nNH + nNKV) * 64) return;
    int d  = i & 63;
    int hh = (i >> 6) % (nNH + nNKV);
    int t  = i / (64 * (nNH + nNKV));
    __half* ptr = g_qkv + (size_t)t * nQKV +
                  (hh < nNH ? hh * nDH : KOFF + (hh - nNH) * nDH);
    float x1 = __half2float(ptr[d]), x2 = __half2float(ptr[d + 64]);
    const float* cr = cosb + (size_t)t * nDH;
    const float* sr = sinb + (size_t)t * nDH;
    ptr[d]      = __float2half_rn(x1 * cr[d]      - x2 * sr[d]);
    ptr[d + 64] = __float2half_rn(x2 * cr[d + 64] + x1 * sr[d + 64]);
}

// ---------------------------------------------------------------------------
// Router (UNROUNDED fp32 input)
// ---------------------------------------------------------------------------
__global__ void router_kernel(const float* __restrict__ rw) {
    __shared__ float xs[nH];
    __shared__ float lg[nE];
    int t = blockIdx.x;
    for (int i = threadIdx.x; i < nH; i += blockDim.x) xs[i] = g_xf[(size_t)t * nH + i];
    __syncthreads();
    int w = threadIdx.x >> 5, lane = threadIdx.x & 31;
    float s = 0.f;
    for (int i = lane; i < nH; i += 32) s += xs[i] * rw[(size_t)i * nE + w];
    s = warpSum(s);
    if (lane == 0) lg[w] = s;
    __syncthreads();
    if (threadIdx.x == 0) {
        float mx = lg[0];
        #pragma unroll
        for (int e = 1; e < nE; e++) mx = fmaxf(mx, lg[e]);
        float p[nE]; float sum = 0.f;
        #pragma unroll
        for (int e = 0; e < nE; e++) { p[e] = expf(lg[e] - mx); sum += p[e]; }
        #pragma unroll
        for (int e = 0; e < nE; e++) p[e] /= sum;
        int i1 = 0;
        #pragma unroll
        for (int e = 1; e < nE; e++) if (p[e] > p[i1]) i1 = e;
        int i2 = (i1 == 0) ? 1 : 0;
        #pragma unroll
        for (int e = 0; e < nE; e++) if (e != i1 && p[e] > p[i2]) i2 = e;
        float s2 = p[i1] + p[i2];
        g_topi[t * 2] = i1; g_topi[t * 2 + 1] = i2;
        g_topw[t * 2] = p[i1] / s2; g_topw[t * 2 + 1] = p[i2] / s2;
    }
}

// ---------------------------------------------------------------------------
// MoE bookkeeping
// ---------------------------------------------------------------------------
__global__ void reset_kernel() {
    int i = threadIdx.x;
    if (i < nE) { g_counts[i] = 0; g_fill[i] = 0; }
}
__global__ void count_kernel() {
    int t = blockIdx.x * blockDim.x + threadIdx.x;
    if (t >= nT) return;
    atomicAdd(&g_counts[g_topi[t * 2]], 1);
    atomicAdd(&g_counts[g_topi[t * 2 + 1]], 1);
}
__global__ void scan_kernel() {
    if (threadIdx.x != 0) return;
    int off = 0, nt = 0;
    for (int e = 0; e < nE; e++) {
        g_coff[e] = off;
        int ne = g_counts[e];
        int ntl = (ne + 127) >> 7;
        for (int i = 0; i < ntl; i++) { g_tileE[nt] = e; g_tileR0[nt] = off + i * 128; nt++; }
        off += ne;
    }
    g_coff[nE] = off;
    for (int i = nt; i < MAXTILE; i++) g_tileE[i] = -1;
}
__global__ void scatter_kernel() {
    int t = blockIdx.x * blockDim.x + threadIdx.x;
    if (t >= nT) return;
    #pragma unroll
    for (int k = 0; k < 2; k++) {
        int e = g_topi[t * 2 + k];
        int pos = g_coff[e] + atomicAdd(&g_fill[e], 1);
        g_toklist[pos] = t;
        g_slot[t * 2 + k] = pos;
    }
}

__global__ void combine_kernel(float* __restrict__ out) {
    size_t i = (size_t)blockIdx.x * blockDim.x + threadIdx.x;
    if (i >= (size_t)nT * nH) return;
    int t = (int)(i / nH), j = (int)(i % nH);
    float v = g_hidden[i];
    v += g_topw[t * 2]     * g_part[(size_t)g_slot[t * 2]     * nH + j];
    v += g_topw[t * 2 + 1] * g_part[(size_t)g_slot[t * 2 + 1] * nH + j];
    out[i] = v;
}

// ---------------------------------------------------------------------------
// Launch
// ---------------------------------------------------------------------------
static void launch_gemm(const __half* A, long long lda, const __half* B, long long ldb,
                        float* Cf, __half* Ch, long long ldc, const float* resf,
                        int M, int N, int K, int mode, int outHalf, int fuseSilu,
                        dim3 grid) {
    GArgs g;
    g.A = A; g.B = B; g.Cf = Cf; g.Ch = Ch; g.resf = resf;
    g.lda = lda; g.ldb = ldb; g.ldc = ldc;
    g.M = M; g.N = N; g.K = K;
    g.mode = mode; g.outHalf = outHalf; g.fuseSilu = fuseSilu;
    tc_gemm<<<grid, 256, SMEM_BYTES>>>(g);
}

extern "C" void kernel_launch(void* const* d_in, const int* in_sizes, int n_in,
                              void* d_out, int out_size) {
    const float* hs   = (const float*)d_in[0];
    const float* cosb = (const float*)d_in[1];
    const float* sinb = (const float*)d_in[2];
    const float* wq   = (const float*)d_in[3];
    const float* wk   = (const float*)d_in[4];
    const float* wv   = (const float*)d_in[5];
    const float* wo   = (const float*)d_in[6];
    const float* ln1  = (const float*)d_in[7];
    const float* ln2  = (const float*)d_in[8];
    const float* rw   = (const float*)d_in[9];
    const float* gw   = (const float*)d_in[10];
    const float* uw   = (const float*)d_in[11];
    const float* dw   = (const float*)d_in[12];
    float* out = (float*)d_out;

    static bool attr_set = false;
    if (!attr_set) {
        cudaFuncSetAttribute(tc_gemm, cudaFuncAttributeMaxDynamicSharedMemorySize, SMEM_BYTES);
        cudaFuncSetAttribute(flash_kernel, cudaFuncAttributeMaxDynamicSharedMemorySize, FA_BYTES);
        attr_set = true;
    }

    __half* wqkvT; cudaGetSymbolAddress((void**)&wqkvT, g_wqkvT);
    __half* woT; cudaGetSymbolAddress((void**)&woT, g_woT);
    __half* gwT; cudaGetSymbolAddress((void**)&gwT, g_gwT);
    __half* uwT; cudaGetSymbolAddress((void**)&uwT, g_uwT);
    __half* dwT; cudaGetSymbolAddress((void**)&dwT, g_dwT);
    __half* xnh; cudaGetSymbolAddress((void**)&xnh, g_xnh);
    __half* qkv; cudaGetSymbolAddress((void**)&qkv, g_qkv);
    __half* at;  cudaGetSymbolAddress((void**)&at, g_attn);
    float*  hid; cudaGetSymbolAddress((void**)&hid, g_hidden);
    __half* x2h; cudaGetSymbolAddress((void**)&x2h, g_x2h);
    float*  gb;  cudaGetSymbolAddress((void**)&gb, g_gbuf);
    __half* ub;  cudaGetSymbolAddress((void**)&ub, g_ubuf);
    float*  pt;  cudaGetSymbolAddress((void**)&pt, g_part);

    reset_kernel<<<1, 32>>>();

    // Weight transposes -> [N][K] fp16 (q/k/v into one fused buffer)
    transpose_kernel<<<dim3(16, 64, 1), 256>>>(wq, wqkvT, nH, nNH * nDH);
    transpose_kernel<<<dim3(4, 64, 1), 256>>>(wk, wqkvT + (size_t)KOFF * nH, nH, nNKV * nDH);
    transpose_kernel<<<dim3(4, 64, 1), 256>>>(wv, wqkvT + (size_t)VOFF * nH, nH, nNKV * nDH);
    transpose_kernel<<<dim3(16, 64, 1), 256>>>(wo, woT, nH, nH);
    transpose_kernel<<<dim3(11, 64, nE), 256>>>(gw, gwT, nH, nMI);
    transpose_kernel<<<dim3(11, 64, nE), 256>>>(uw, uwT, nH, nMI);
    transpose_kernel<<<dim3(16, 44, nE), 256>>>(dw, dwT, nMI, nH);

    rmsnorm1_kernel<<<nT, 256>>>(hs, ln1);

    // Fused QKV projection (half out, N=3072)
    launch_gemm(xnh, nH, wqkvT, nH, nullptr, qkv, nQKV, nullptr,
                nT, nQKV, nH, 0, 1, 0, dim3(24, 32, 1));

    rope_kernel<<<(nT * (nNH + nNKV) * 64) / 256, 256>>>(cosb, sinb);
    vtrans_kernel<<<dim3(nS / 32, nDH / 32, nB * nNKV), 256>>>();

    // fused attention
    flash_kernel<<<dim3(nS / 128, nB * nNH), 256, FA_BYTES>>>();

    // hidden = attn @ wo + residual (fp32)
    launch_gemm(at, nH, woT, nH, hid, nullptr, nH, hs,
                nT, nH, nH, 0, 0, 0, dim3(16, 32, 1));

    rmsnorm2_kernel<<<nT, 256>>>(ln2);
    router_kernel<<<nT, 256>>>(rw);

    count_kernel<<<nT / 256, 256>>>();
    scan_kernel<<<1, 1>>>();
    scatter_kernel<<<nT / 256, 256>>>();

    // MoE: gate (fp32 raw), up + fused silu (half), down (fp32)
    launch_gemm(x2h, nH, gwT, nH, gb, nullptr, nMI, nullptr,
                GR, nMI, nH, 1, 0, 0, dim3(11, MAXTILE, 1));
    launch_gemm(x2h, nH, uwT, nH, nullptr, ub, nMI, gb,
                GR, nMI, nH, 1, 0, 1, dim3(11, MAXTILE, 1));
    launch_gemm(ub, nMI, dwT, nMI, pt, nullptr, nH, nullptr,
                GR, nH, nMI, 2, 0, 0, dim3(16, MAXTILE, 1));

    combine_kernel<<<((size_t)nT * nH) / 256, 256>>>(out);
}

// round 11
// speedup vs baseline: 2.0670x; 1.0279x over previous
#include <cuda_runtime.h>
#include <cuda_fp16.h>
#include <math.h>
#include <stdint.h>

// ---------------------------------------------------------------------------
// Problem constants
// ---------------------------------------------------------------------------
namespace {
constexpr int nB = 2, nS = 2048, nH = 2048, nNH = 16, nNKV = 4, nDH = 128;
constexpr int nE = 8, nMI = 1408;
constexpr int nT = nB * nS;          // 4096 tokens
constexpr int GR = nT * 2;           // 8192 gathered (token, expert) rows
constexpr int MAXTILE = 72;
constexpr int nQKV = (nNH + 2 * nNKV) * nDH;       // 3072 fused qkv width
constexpr int KOFF = nNH * nDH;                    // 2048
constexpr int VOFF = KOFF + nNKV * nDH;            // 2560
constexpr int nGU = 2 * nMI;                       // 2816 interleaved gate|up
constexpr float RMS_EPS = 1e-6f;
constexpr float QK_SCALE = 0.088388347648318447f;  // 1/sqrt(128)

// GEMM smem (half indices): 3 stages x (A 128x72 + B 128x72)
constexpr int G_HALFS = 55296;
constexpr int SMEM_BYTES = G_HALFS * 2;            // 110592

// flash smem (half indices)
constexpr int FA_QS = 0;                 // Q  [128][136]
constexpr int FA_KS = 17408;             // K  [64][136]
constexpr int FA_VS = 26112;             // V^T 2 x [128][72]
constexpr int FA_PS = 44544;             // P  [128][72]
constexpr int FA_END = 53760;            // halfs
constexpr int FA_RMf = FA_END / 2;       // float idx: rowmax [128][2]
constexpr int FA_RLf = FA_RMf + 256;     // float idx: rowsum [128][2]
constexpr int FA_BYTES = (FA_RLf + 256) * 4;   // 109568
}

// ---------------------------------------------------------------------------
// Scratch (device globals)
// ---------------------------------------------------------------------------
__device__ __half g_xnh  [(size_t)nT * nH];        // rmsnorm1 out (half)
__device__ float  g_xf   [(size_t)nT * nH];        // unrounded rmsnorm2 (router)
__device__ __half g_qkv  [(size_t)nT * nQKV];      // fused q|k|v (post-rope)
__device__ __half g_vT   [(size_t)nB * nNKV * nDH * nS];
__device__ __half g_attn [(size_t)nT * nH];
__device__ float  g_hidden[(size_t)nT * nH];
__device__ __half g_x2h  [(size_t)nT * nH];
__device__ int    g_topi [nT * 2];
__device__ float  g_topw [nT * 2];
__device__ int    g_counts[nE];
__device__ int    g_fill [nE];
__device__ int    g_coff [nE + 1];
__device__ int    g_tileE[MAXTILE];
__device__ int    g_tileR0[MAXTILE];
__device__ int    g_toklist[GR];
__device__ float  g_slotw[GR];
__device__ __half g_ubuf [(size_t)GR * nMI];       // silu(g)*u (half)
// transposed weights [N][K] K-major, fp16
__device__ __half g_wqkvT[(size_t)nQKV * nH];
__device__ __half g_woT [(size_t)nH * nH];
__device__ __half g_guT [(size_t)nE * nGU * nH];   // interleaved gate|up
__device__ __half g_dwT [(size_t)nE * nH * nMI];

// ---------------------------------------------------------------------------
// Helpers
// ---------------------------------------------------------------------------
__device__ __forceinline__ uint32_t smem_to_u32(const void* p) {
    uint32_t a;
    asm("{ .reg .u64 t; cvta.to.shared.u64 t, %1; cvt.u32.u64 %0, t; }" : "=r"(a) : "l"(p));
    return a;
}
__device__ __forceinline__ uint32_t pack2h(float x, float y) {
    __half2 h = __floats2half2_rn(x, y);
    return *reinterpret_cast<uint32_t*>(&h);
}
__device__ __forceinline__ void mma_f16(float* d, const uint32_t* a, const uint32_t* b) {
    asm volatile("mma.sync.aligned.m16n8k16.row.col.f32.f16.f16.f32 "
        "{%0,%1,%2,%3}, {%4,%5,%6,%7}, {%8,%9}, {%0,%1,%2,%3};"
        : "+f"(d[0]), "+f"(d[1]), "+f"(d[2]), "+f"(d[3])
        : "r"(a[0]), "r"(a[1]), "r"(a[2]), "r"(a[3]), "r"(b[0]), "r"(b[1]));
}
__device__ __forceinline__ float warpSum(float v) {
    #pragma unroll
    for (int o = 16; o; o >>= 1) v += __shfl_xor_sync(0xffffffffu, v, o);
    return v;
}
__device__ __forceinline__ float siluf(float x) {
    return x * (1.f / (1.f + expf(-x)));
}

// ---------------------------------------------------------------------------
// fp16 mma GEMM: C[M,N] = A[M,K](half,K-major) x B[N,K](half,K-major)
// CTA tile 128x128, K-chunks of 64, 3-stage cp.async pipeline, 256 threads.
// Epilogues: float out (+res), half out, interleaved gate/up silu, scatter-add.
// ---------------------------------------------------------------------------
struct GArgs {
    const __half* A; const __half* B;
    float* Cf; __half* Ch;
    const float* resf;
    long long lda, ldb, ldc;
    int M, N, K;
    int mode;     // 0 normal, 1 moe gather-A, 2 moe no-gather
    int outHalf;  // write Ch (half)
    int fuseSilu; // interleaved gate/up: Ch[..nMI] = h(silu(g)*u)
    int scatter;  // atomicAdd into Cf[tok][col] with g_slotw weight
};

__global__ void __launch_bounds__(256) tc_gemm(GArgs g) {
    extern __shared__ __half gsm[];
    const int tid = threadIdx.x, lane = tid & 31, wid = tid >> 5;
    const int wm = wid & 3, wn = wid >> 2;
    const int gq = lane >> 2, qq = lane & 3;

    int m0, Mb;
    const __half* Ab = g.A;
    const __half* Bb = g.B;
    if (g.mode >= 1) {
        int e = g_tileE[blockIdx.y];
        if (e < 0) return;
        m0 = g_tileR0[blockIdx.y];
        Mb = g_coff[e + 1];
        Bb += (size_t)e * g.N * g.K;
    } else {
        m0 = blockIdx.y * 128;
        Mb = g.M;
    }
    const int n0 = blockIdx.x * 128;

    __shared__ int rt[128];
    if (tid < 128) {
        int m = m0 + tid;
        int r = (m < Mb) ? m : -1;
        if (g.mode == 1 && r >= 0) r = g_toklist[r];
        rt[tid] = r;
    }
    __syncthreads();

    const uint32_t sbase = smem_to_u32(gsm);
    const int NC = g.K >> 6;

    auto issue = [&](int c, int s) {
        const int k0 = c << 6;
        const uint32_t ao = (uint32_t)(s * 9216);
        const uint32_t bo = (uint32_t)(27648 + s * 9216);
        #pragma unroll
        for (int p = 0; p < 4; p++) {
            int idx = p * 256 + tid;
            int row = idx >> 3, c8 = idx & 7;
            int r = rt[row];
            const __half* src = (r >= 0 ? Ab + (size_t)r * g.lda : Ab) + k0 + c8 * 8;
            uint32_t dst = sbase + (ao + (uint32_t)(row * 72 + c8 * 8)) * 2u;
            int sz = (r >= 0) ? 16 : 0;
            asm volatile("cp.async.cg.shared.global [%0], [%1], 16, %2;"
                         :: "r"(dst), "l"(src), "r"(sz) : "memory");
        }
        #pragma unroll
        for (int p = 0; p < 4; p++) {
            int idx = p * 256 + tid;
            int row = idx >> 3, c8 = idx & 7;
            const __half* src = Bb + (size_t)(n0 + row) * g.ldb + k0 + c8 * 8;
            uint32_t dst = sbase + (bo + (uint32_t)(row * 72 + c8 * 8)) * 2u;
            asm volatile("cp.async.cg.shared.global [%0], [%1], 16, %2;"
                         :: "r"(dst), "l"(src), "r"(16) : "memory");
        }
    };

    float acc[2][8][4] = {};

    issue(0, 0);
    asm volatile("cp.async.commit_group;" ::: "memory");
    issue(1, 1);
    asm volatile("cp.async.commit_group;" ::: "memory");

    const uint32_t* su = reinterpret_cast<const uint32_t*>(gsm);

    for (int c = 0; c < NC; c++) {
        const int s = c % 3;
        asm volatile("cp.async.wait_group 1;" ::: "memory");
        __syncthreads();
        if (c + 2 < NC) issue(c + 2, (c + 2) % 3);
        asm volatile("cp.async.commit_group;" ::: "memory");

        const uint32_t* Asm = su + s * 4608;
        const uint32_t* Bsm = su + 13824 + s * 4608;
        #pragma unroll
        for (int kk = 0; kk < 4; kk++) {
            const int kb = kk * 8;
            uint32_t af[2][4];
            #pragma unroll
            for (int mt = 0; mt < 2; mt++) {
                int r0 = wm * 32 + mt * 16 + gq;
                af[mt][0] = Asm[r0 * 36 + kb + qq];
                af[mt][1] = Asm[(r0 + 8) * 36 + kb + qq];
                af[mt][2] = Asm[r0 * 36 + kb + qq + 4];
                af[mt][3] = Asm[(r0 + 8) * 36 + kb + qq + 4];
            }
            uint32_t bf[8][2];
            #pragma unroll
            for (int nt = 0; nt < 8; nt++) {
                int c0 = wn * 64 + nt * 8 + gq;
                bf[nt][0] = Bsm[c0 * 36 + kb + qq];
                bf[nt][1] = Bsm[c0 * 36 + kb + qq + 4];
            }
            #pragma unroll
            for (int mt = 0; mt < 2; mt++)
                #pragma unroll
                for (int nt = 0; nt < 8; nt++)
                    mma_f16(acc[mt][nt], af[mt], bf[nt]);
        }
    }

    // Epilogue
    #pragma unroll
    for (int mt = 0; mt < 2; mt++) {
        #pragma unroll
        for (int half_ = 0; half_ < 2; half_++) {
            int r = m0 + wm * 32 + mt * 16 + half_ * 8 + gq;
            if (r >= Mb) continue;
            if (g.fuseSilu) {
                // interleaved gate/up pairs: nt even = gate, nt+1 = up
                #pragma unroll
                for (int nt = 0; nt < 8; nt += 2) {
                    float g0 = acc[mt][nt][half_ * 2 + 0];
                    float g1 = acc[mt][nt][half_ * 2 + 1];
                    float u0 = acc[mt][nt + 1][half_ * 2 + 0];
                    float u1 = acc[mt][nt + 1][half_ * 2 + 1];
                    int cint = n0 + wn * 64 + nt * 8;
                    int L = ((cint) >> 4) * 8 + 2 * qq;
                    *reinterpret_cast<uint32_t*>(g.Ch + (size_t)r * g.ldc + L) =
                        pack2h(siluf(g0) * u0, siluf(g1) * u1);
                }
            } else if (g.scatter) {
                int tok = g_toklist[r];
                float w = g_slotw[r];
                float* orow = g.Cf + (size_t)tok * g.ldc;
                const int cb = n0 + wn * 64 + 2 * qq;
                #pragma unroll
                for (int nt = 0; nt < 8; nt++) {
                    atomicAdd(&orow[cb + nt * 8],     w * acc[mt][nt][half_ * 2 + 0]);
                    atomicAdd(&orow[cb + nt * 8 + 1], w * acc[mt][nt][half_ * 2 + 1]);
                }
            } else {
                const int cb = n0 + wn * 64 + 2 * qq;
                #pragma unroll
                for (int nt = 0; nt < 8; nt++) {
                    float vx = acc[mt][nt][half_ * 2 + 0];
                    float vy = acc[mt][nt][half_ * 2 + 1];
                    int col = cb + nt * 8;
                    if (g.outHalf) {
                        *reinterpret_cast<uint32_t*>(g.Ch + (size_t)r * g.ldc + col) = pack2h(vx, vy);
                    } else {
                        if (g.resf) {
                            float2 rv = *reinterpret_cast<const float2*>(g.resf + (size_t)r * g.ldc + col);
                            vx += rv.x; vy += rv.y;
                        }
                        *reinterpret_cast<float2*>(g.Cf + (size_t)r * g.ldc + col) = make_float2(vx, vy);
                    }
                }
            }
        }
    }
}

// ---------------------------------------------------------------------------
// Fused flash attention, fp16 operands / fp32 softmax+accum.
// ---------------------------------------------------------------------------
__global__ void __launch_bounds__(256) flash_kernel() {
    extern __shared__ __half fh[];
    float* ff = reinterpret_cast<float*>(fh);
    const uint32_t* fu = reinterpret_cast<const uint32_t*>(fh);
    const int tid = threadIdx.x, lane = tid & 31, wid = tid >> 5;
    const int wm = wid & 3, wn = wid >> 2;
    const int gq = lane >> 2, qq = lane & 3;
    const int bh = blockIdx.y, b = bh >> 4, h = bh & 15, kh = h >> 2;
    const int q0 = blockIdx.x * 128;

    const __half* Qg = g_qkv + ((size_t)(b * nS + q0)) * nQKV + h * nDH;
    const __half* Kg = g_qkv + (size_t)b * nS * nQKV + KOFF + kh * nDH;
    const __half* Vt = g_vT + ((size_t)(b * nNKV + kh)) * nDH * nS;
    __half* Og = g_attn + ((size_t)(b * nS + q0)) * nH + h * nDH;

    const uint32_t sb = smem_to_u32(fh);

    #pragma unroll
    for (int p = 0; p < 8; p++) {
        int idx = p * 256 + tid;
        int row = idx >> 4, c8 = idx & 15;
        uint32_t dst = sb + (uint32_t)(FA_QS + row * 136 + c8 * 8) * 2u;
        const __half* src = Qg + (size_t)row * nQKV + c8 * 8;
        asm volatile("cp.async.cg.shared.global [%0], [%1], 16;"
                     :: "r"(dst), "l"(src) : "memory");
    }
    asm volatile("cp.async.commit_group;" ::: "memory");

    auto issueKV = [&](int it2) {
        const __half* kg = Kg + (size_t)(it2 * 64) * nQKV;
        const __half* vg = Vt + it2 * 64;
        const int vb = FA_VS + (it2 & 1) * 9216;
        #pragma unroll
        for (int p = 0; p < 4; p++) {
            int idx = p * 256 + tid;
            int row = idx >> 4, c8 = idx & 15;
            uint32_t dk = sb + (uint32_t)(FA_KS + row * 136 + c8 * 8) * 2u;
            asm volatile("cp.async.cg.shared.global [%0], [%1], 16;"
                         :: "r"(dk), "l"(kg + (size_t)row * nQKV + c8 * 8) : "memory");
        }
        #pragma unroll
        for (int p = 0; p < 4; p++) {
            int idx = p * 256 + tid;
            int row = idx >> 3, c8 = idx & 7;
            uint32_t dv = sb + (uint32_t)(vb + row * 72 + c8 * 8) * 2u;
            asm volatile("cp.async.cg.shared.global [%0], [%1], 16;"
                         :: "r"(dv), "l"(vg + (size_t)row * nS + c8 * 8) : "memory");
        }
    };
    issueKV(0);
    asm volatile("cp.async.commit_group;" ::: "memory");

    float accO[2][8][4] = {};
    float rm[2][2] = {{-1e30f, -1e30f}, {-1e30f, -1e30f}};
    float rl[2][2] = {{0.f, 0.f}, {0.f, 0.f}};
    const int QSu = FA_QS / 2, KSu = FA_KS / 2, PSu = FA_PS / 2;

    for (int it = 0; it < nS / 64; it++) {
        asm volatile("cp.async.wait_group 0;" ::: "memory");
        __syncthreads();

        float S[2][4][4] = {};
        #pragma unroll
        for (int kc = 0; kc < 8; kc++) {
            const int kb = kc * 8;
            uint32_t af[2][4];
            #pragma unroll
            for (int mt = 0; mt < 2; mt++) {
                int r0 = wm * 32 + mt * 16 + gq;
                af[mt][0] = fu[QSu + r0 * 68 + kb + qq];
                af[mt][1] = fu[QSu + (r0 + 8) * 68 + kb + qq];
                af[mt][2] = fu[QSu + r0 * 68 + kb + qq + 4];
                af[mt][3] = fu[QSu + (r0 + 8) * 68 + kb + qq + 4];
            }
            uint32_t bf[4][2];
            #pragma unroll
            for (int nt = 0; nt < 4; nt++) {
                int c0 = wn * 32 + nt * 8 + gq;
                bf[nt][0] = fu[KSu + c0 * 68 + kb + qq];
                bf[nt][1] = fu[KSu + c0 * 68 + kb + qq + 4];
            }
            #pragma unroll
            for (int mt = 0; mt < 2; mt++)
                #pragma unroll
                for (int nt = 0; nt < 4; nt++)
                    mma_f16(S[mt][nt], af[mt], bf[nt]);
        }
        __syncthreads();
        if (it + 1 < nS / 64) issueKV(it + 1);
        asm volatile("cp.async.commit_group;" ::: "memory");

        float tmax[2][2] = {{-1e30f, -1e30f}, {-1e30f, -1e30f}};
        #pragma unroll
        for (int mt = 0; mt < 2; mt++)
            #pragma unroll
            for (int nt = 0; nt < 4; nt++)
                #pragma unroll
                for (int c = 0; c < 4; c++) {
                    S[mt][nt][c] *= QK_SCALE;
                    tmax[mt][c >> 1] = fmaxf(tmax[mt][c >> 1], S[mt][nt][c]);
                }
        #pragma unroll
        for (int mt = 0; mt < 2; mt++)
            #pragma unroll
            for (int hf = 0; hf < 2; hf++) {
                float v = tmax[mt][hf];
                v = fmaxf(v, __shfl_xor_sync(0xffffffffu, v, 1));
                v = fmaxf(v, __shfl_xor_sync(0xffffffffu, v, 2));
                tmax[mt][hf] = v;
            }
        if (qq == 0) {
            #pragma unroll
            for (int mt = 0; mt < 2; mt++)
                #pragma unroll
                for (int hf = 0; hf < 2; hf++)
                    ff[FA_RMf + (wm * 32 + mt * 16 + hf * 8 + gq) * 2 + wn] = tmax[mt][hf];
        }
        __syncthreads();

        float newm[2][2], sco[2][2];
        #pragma unroll
        for (int mt = 0; mt < 2; mt++)
            #pragma unroll
            for (int hf = 0; hf < 2; hf++) {
                int r = wm * 32 + mt * 16 + hf * 8 + gq;
                float tm = fmaxf(ff[FA_RMf + r * 2], ff[FA_RMf + r * 2 + 1]);
                float nm = fmaxf(rm[mt][hf], tm);
                sco[mt][hf] = __expf(rm[mt][hf] - nm);
                newm[mt][hf] = nm;
                rm[mt][hf] = nm;
            }

        float ps[2][2] = {{0.f, 0.f}, {0.f, 0.f}};
        uint32_t* Pw = reinterpret_cast<uint32_t*>(fh);
        #pragma unroll
        for (int mt = 0; mt < 2; mt++) {
            int r0 = wm * 32 + mt * 16 + gq;
            #pragma unroll
            for (int nt = 0; nt < 4; nt++) {
                int ci = wn * 16 + nt * 4 + qq;
                float p0 = __expf(S[mt][nt][0] - newm[mt][0]);
                float p1 = __expf(S[mt][nt][1] - newm[mt][0]);
                float p2 = __expf(S[mt][nt][2] - newm[mt][1]);
                float p3 = __expf(S[mt][nt][3] - newm[mt][1]);
                ps[mt][0] += p0 + p1;
                ps[mt][1] += p2 + p3;
                Pw[PSu + r0 * 36 + ci] = pack2h(p0, p1);
                Pw[PSu + (r0 + 8) * 36 + ci] = pack2h(p2, p3);
            }
        }
        #pragma unroll
        for (int mt = 0; mt < 2; mt++)
            #pragma unroll
            for (int hf = 0; hf < 2; hf++) {
                float v = ps[mt][hf];
                v += __shfl_xor_sync(0xffffffffu, v, 1);
                v += __shfl_xor_sync(0xffffffffu, v, 2);
                ps[mt][hf] = v;
            }
        if (qq == 0) {
            #pragma unroll
            for (int mt = 0; mt < 2; mt++)
                #pragma unroll
                for (int hf = 0; hf < 2; hf++)
                    ff[FA_RLf + (wm * 32 + mt * 16 + hf * 8 + gq) * 2 + wn] = ps[mt][hf];
        }
        __syncthreads();

        #pragma unroll
        for (int mt = 0; mt < 2; mt++)
            #pragma unroll
            for (int hf = 0; hf < 2; hf++) {
                int r = wm * 32 + mt * 16 + hf * 8 + gq;
                float ts = ff[FA_RLf + r * 2] + ff[FA_RLf + r * 2 + 1];
                rl[mt][hf] = rl[mt][hf] * sco[mt][hf] + ts;
            }
        #pragma unroll
        for (int mt = 0; mt < 2; mt++)
            #pragma unroll
            for (int nt = 0; nt < 8; nt++) {
                accO[mt][nt][0] *= sco[mt][0];
                accO[mt][nt][1] *= sco[mt][0];
                accO[mt][nt][2] *= sco[mt][1];
                accO[mt][nt][3] *= sco[mt][1];
            }

        const int Vu = (FA_VS + (it & 1) * 9216) / 2;
        #pragma unroll
        for (int kc = 0; kc < 4; kc++) {
            const int kb = kc * 8;
            uint32_t af[2][4];
            #pragma unroll
            for (int mt = 0; mt < 2; mt++) {
                int r0 = wm * 32 + mt * 16 + gq;
                af[mt][0] = fu[PSu + r0 * 36 + kb + qq];
                af[mt][1] = fu[PSu + (r0 + 8) * 36 + kb + qq];
                af[mt][2] = fu[PSu + r0 * 36 + kb + qq + 4];
                af[mt][3] = fu[PSu + (r0 + 8) * 36 + kb + qq + 4];
            }
            uint32_t bf[8][2];
            #pragma unroll
            for (int nt = 0; nt < 8; nt++) {
                int c0 = wn * 64 + nt * 8 + gq;
                bf[nt][0] = fu[Vu + c0 * 36 + kb + qq];
                bf[nt][1] = fu[Vu + c0 * 36 + kb + qq + 4];
            }
            #pragma unroll
            for (int mt = 0; mt < 2; mt++)
                #pragma unroll
                for (int nt = 0; nt < 8; nt++)
                    mma_f16(accO[mt][nt], af[mt], bf[nt]);
        }
    }

    #pragma unroll
    for (int mt = 0; mt < 2; mt++)
        #pragma unroll
        for (int hf = 0; hf < 2; hf++) {
            int r = wm * 32 + mt * 16 + hf * 8 + gq;
            float inv = 1.f / rl[mt][hf];
            #pragma unroll
            for (int nt = 0; nt < 8; nt++) {
                int col = wn * 64 + nt * 8 + 2 * qq;
                *reinterpret_cast<uint32_t*>(Og + (size_t)r * nH + col) =
                    pack2h(accO[mt][nt][hf * 2 + 0] * inv, accO[mt][nt][hf * 2 + 1] * inv);
            }
        }
}

// ---------------------------------------------------------------------------
// Weight transpose fp32->fp16, 64k x 128n tile, optional gate/up interleave.
// remapOfs: -1 none; 0 gate rows; 8 up rows (dst row = (n>>3)*16 + (n&7) + ofs)
// ---------------------------------------------------------------------------
__global__ void __launch_bounds__(256) transpose_kernel(
    const float* __restrict__ in, __half* __restrict__ out, int K, int N,
    long long srcZ, long long dstZ, int remapOfs) {
    __shared__ float t[64][137];
    const float* ip = in + (size_t)blockIdx.z * srcZ;
    __half* op = out + (size_t)blockIdx.z * dstZ;
    const int n0 = blockIdx.x * 128, k0 = blockIdx.y * 64;
    const int tid = threadIdx.x;
    const int rr = tid >> 5, rc = tid & 31;
    #pragma unroll
    for (int p = 0; p < 8; p++) {
        int kk = rr + p * 8;
        float4 v = *reinterpret_cast<const float4*>(ip + (size_t)(k0 + kk) * N + n0 + rc * 4);
        t[kk][rc * 4 + 0] = v.x; t[kk][rc * 4 + 1] = v.y;
        t[kk][rc * 4 + 2] = v.z; t[kk][rc * 4 + 3] = v.w;
    }
    __syncthreads();
    const int wr = tid >> 3, wk8 = (tid & 7) * 8;
    #pragma unroll
    for (int p = 0; p < 4; p++) {
        int nn = wr + p * 32;
        int ng = n0 + nn;
        int nd = (remapOfs < 0) ? ng : ((ng >> 3) << 4) + (ng & 7) + remapOfs;
        __half hv[8];
        #pragma unroll
        for (int j = 0; j < 8; j++) hv[j] = __float2half_rn(t[wk8 + j][nn]);
        *reinterpret_cast<uint4*>(op + (size_t)nd * K + k0 + wk8) =
            *reinterpret_cast<uint4*>(hv);
    }
}

// V transpose (half): g_qkv v-section -> g_vT [(b*4+kh)][dh][S]
__global__ void vtrans_kernel() {
    __shared__ __half t[32][33];
    int z = blockIdx.z, b = z >> 2, kh = z & 3;
    int s0 = blockIdx.x * 32, d0 = blockIdx.y * 32;
    int tx = threadIdx.x & 31, ty = threadIdx.x >> 5;
    #pragma unroll
    for (int i = ty; i < 32; i += 8)
        t[i][tx] = g_qkv[((size_t)(b * nS + s0 + i)) * nQKV + VOFF + kh * nDH + d0 + tx];
    __syncthreads();
    #pragma unroll
    for (int i = ty; i < 32; i += 8)
        g_vT[((size_t)z * nDH + d0 + i) * nS + s0 + tx] = t[tx][i];
}

// ---------------------------------------------------------------------------
// RMSNorm. rmsnorm1 -> half. rmsnorm2 -> half + float (router) + out init.
// ---------------------------------------------------------------------------
template <bool DUAL>
__device__ __forceinline__ void rmsnorm_row(const float* __restrict__ x,
                                            const float* __restrict__ w,
                                            __half* __restrict__ out_h,
                                            float* __restrict__ out_f,
                                            float* __restrict__ out_cp) {
    int row = blockIdx.x;
    const float* xr = x + (size_t)row * nH;
    float ss = 0.f;
    for (int i = threadIdx.x; i < nH; i += blockDim.x) { float v = xr[i]; ss += v * v; }
    __shared__ float sm[8];
    int lane = threadIdx.x & 31, wid = threadIdx.x >> 5;
    ss = warpSum(ss);
    if (lane == 0) sm[wid] = ss;
    __syncthreads();
    if (wid == 0) {
        float v = (lane < 8) ? sm[lane] : 0.f;
        v = warpSum(v);
        if (lane == 0) sm[0] = rsqrtf(v / (float)nH + RMS_EPS);
    }
    __syncthreads();
    float inv = sm[0];
    for (int i = threadIdx.x; i < nH; i += blockDim.x) {
        float xi = xr[i];
        float v = xi * inv * w[i];
        out_h[(size_t)row * nH + i] = __float2half_rn(v);
        if (DUAL) {
            out_f[(size_t)row * nH + i] = v;
            out_cp[(size_t)row * nH + i] = xi;   // out = hidden (residual base)
        }
    }
}
__global__ void rmsnorm1_kernel(const float* __restrict__ hs, const float* __restrict__ w) {
    rmsnorm_row<false>(hs, w, g_xnh, nullptr, nullptr);
}
__global__ void rmsnorm2_kernel(const float* __restrict__ w, float* __restrict__ out) {
    rmsnorm_row<true>(g_hidden, w, g_x2h, g_xf, out);
}

// ---------------------------------------------------------------------------
// RoPE on fused qkv (fp32 math). Only q and k sections.
// ---------------------------------------------------------------------------
__global__ void rope_kernel(const float* __restrict__ cosb, const float* __restrict__ sinb) {
    int i = blockIdx.x * blockDim.x + threadIdx.x;
    if (i >= nT * (nNH + nNKV) * 64) return;
    int d  = i & 63;
    int hh = (i >> 6) % (nNH + nNKV);
    int t  = i / (64 * (nNH + nNKV));
    __half* ptr = g_qkv + (size_t)t * nQKV +
                  (hh < nNH ? hh * nDH : KOFF + (hh - nNH) * nDH);
    float x1 = __half2float(ptr[d]), x2 = __half2float(ptr[d + 64]);
    const float* cr = cosb + (size_t)t * nDH;
    const float* sr = sinb + (size_t)t * nDH;
    ptr[d]      = __float2half_rn(x1 * cr[d]      - x2 * sr[d]);
    ptr[d + 64] = __float2half_rn(x2 * cr[d + 64] + x1 * sr[d + 64]);
}

// ---------------------------------------------------------------------------
// Router (UNROUNDED fp32 input)
// ---------------------------------------------------------------------------
__global__ void router_kernel(const float* __restrict__ rw) {
    __shared__ float xs[nH];
    __shared__ float lg[nE];
    int t = blockIdx.x;
    for (int i = threadIdx.x; i < nH; i += blockDim.x) xs[i] = g_xf[(size_t)t * nH + i];
    __syncthreads();
    int w = threadIdx.x >> 5, lane = threadIdx.x & 31;
    float s = 0.f;
    for (int i = lane; i < nH; i += 32) s += xs[i] * rw[(size_t)i * nE + w];
    s = warpSum(s);
    if (lane == 0) lg[w] = s;
    __syncthreads();
    if (threadIdx.x == 0) {
        float mx = lg[0];
        #pragma unroll
        for (int e = 1; e < nE; e++) mx = fmaxf(mx, lg[e]);
        float p[nE]; float sum = 0.f;
        #pragma unroll
        for (int e = 0; e < nE; e++) { p[e] = expf(lg[e] - mx); sum += p[e]; }
        #pragma unroll
        for (int e = 0; e < nE; e++) p[e] /= sum;
        int i1 = 0;
        #pragma unroll
        for (int e = 1; e < nE; e++) if (p[e] > p[i1]) i1 = e;
        int i2 = (i1 == 0) ? 1 : 0;
        #pragma unroll
        for (int e = 0; e < nE; e++) if (e != i1 && p[e] > p[i2]) i2 = e;
        float s2 = p[i1] + p[i2];
        g_topi[t * 2] = i1; g_topi[t * 2 + 1] = i2;
        g_topw[t * 2] = p[i1] / s2; g_topw[t * 2 + 1] = p[i2] / s2;
    }
}

// ---------------------------------------------------------------------------
// MoE bookkeeping
// ---------------------------------------------------------------------------
__global__ void reset_kernel() {
    int i = threadIdx.x;
    if (i < nE) { g_counts[i] = 0; g_fill[i] = 0; }
}
__global__ void count_kernel() {
    int t = blockIdx.x * blockDim.x + threadIdx.x;
    if (t >= nT) return;
    atomicAdd(&g_counts[g_topi[t * 2]], 1);
    atomicAdd(&g_counts[g_topi[t * 2 + 1]], 1);
}
__global__ void scan_kernel() {
    if (threadIdx.x != 0) return;
    int off = 0, nt = 0;
    for (int e = 0; e < nE; e++) {
        g_coff[e] = off;
        int ne = g_counts[e];
        int ntl = (ne + 127) >> 7;
        for (int i = 0; i < ntl; i++) { g_tileE[nt] = e; g_tileR0[nt] = off + i * 128; nt++; }
        off += ne;
    }
    g_coff[nE] = off;
    for (int i = nt; i < MAXTILE; i++) g_tileE[i] = -1;
}
__global__ void scatter_kernel() {
    int t = blockIdx.x * blockDim.x + threadIdx.x;
    if (t >= nT) return;
    #pragma unroll
    for (int k = 0; k < 2; k++) {
        int e = g_topi[t * 2 + k];
        int pos = g_coff[e] + atomicAdd(&g_fill[e], 1);
        g_toklist[pos] = t;
        g_slotw[pos] = g_topw[t * 2 + k];
    }
}

// ---------------------------------------------------------------------------
// Launch
// ---------------------------------------------------------------------------
static void launch_gemm(const __half* A, long long lda, const __half* B, long long ldb,
                        float* Cf, __half* Ch, long long ldc, const float* resf,
                        int M, int N, int K, int mode, int outHalf, int fuseSilu,
                        int scatter, dim3 grid) {
    GArgs g;
    g.A = A; g.B = B; g.Cf = Cf; g.Ch = Ch; g.resf = resf;
    g.lda = lda; g.ldb = ldb; g.ldc = ldc;
    g.M = M; g.N = N; g.K = K;
    g.mode = mode; g.outHalf = outHalf; g.fuseSilu = fuseSilu; g.scatter = scatter;
    tc_gemm<<<grid, 256, SMEM_BYTES>>>(g);
}

extern "C" void kernel_launch(void* const* d_in, const int* in_sizes, int n_in,
                              void* d_out, int out_size) {
    const float* hs   = (const float*)d_in[0];
    const float* cosb = (const float*)d_in[1];
    const float* sinb = (const float*)d_in[2];
    const float* wq   = (const float*)d_in[3];
    const float* wk   = (const float*)d_in[4];
    const float* wv   = (const float*)d_in[5];
    const float* wo   = (const float*)d_in[6];
    const float* ln1  = (const float*)d_in[7];
    const float* ln2  = (const float*)d_in[8];
    const float* rw   = (const float*)d_in[9];
    const float* gw   = (const float*)d_in[10];
    const float* uw   = (const float*)d_in[11];
    const float* dw   = (const float*)d_in[12];
    float* out = (float*)d_out;

    static bool attr_set = false;
    if (!attr_set) {
        cudaFuncSetAttribute(tc_gemm, cudaFuncAttributeMaxDynamicSharedMemorySize, SMEM_BYTES);
        cudaFuncSetAttribute(flash_kernel, cudaFuncAttributeMaxDynamicSharedMemorySize, FA_BYTES);
        attr_set = true;
    }

    __half* wqkvT; cudaGetSymbolAddress((void**)&wqkvT, g_wqkvT);
    __half* woT; cudaGetSymbolAddress((void**)&woT, g_woT);
    __half* guT; cudaGetSymbolAddress((void**)&guT, g_guT);
    __half* dwT; cudaGetSymbolAddress((void**)&dwT, g_dwT);
    __half* xnh; cudaGetSymbolAddress((void**)&xnh, g_xnh);
    __half* qkv; cudaGetSymbolAddress((void**)&qkv, g_qkv);
    __half* at;  cudaGetSymbolAddress((void**)&at, g_attn);
    float*  hid; cudaGetSymbolAddress((void**)&hid, g_hidden);
    __half* x2h; cudaGetSymbolAddress((void**)&x2h, g_x2h);
    __half* ub;  cudaGetSymbolAddress((void**)&ub, g_ubuf);

    reset_kernel<<<1, 32>>>();

    // Weight transposes -> [N][K] fp16 (64k x 128n tiles)
    transpose_kernel<<<dim3(16, 32, 1), 256>>>(wq, wqkvT, nH, nNH * nDH, 0, 0, -1);
    transpose_kernel<<<dim3(4, 32, 1), 256>>>(wk, wqkvT + (size_t)KOFF * nH, nH, nNKV * nDH, 0, 0, -1);
    transpose_kernel<<<dim3(4, 32, 1), 256>>>(wv, wqkvT + (size_t)VOFF * nH, nH, nNKV * nDH, 0, 0, -1);
    transpose_kernel<<<dim3(16, 32, 1), 256>>>(wo, woT, nH, nH, 0, 0, -1);
    transpose_kernel<<<dim3(11, 32, nE), 256>>>(gw, guT, nH, nMI,
        (long long)nH * nMI, (long long)nGU * nH, 0);
    transpose_kernel<<<dim3(11, 32, nE), 256>>>(uw, guT, nH, nMI,
        (long long)nH * nMI, (long long)nGU * nH, 8);
    transpose_kernel<<<dim3(16, 22, nE), 256>>>(dw, dwT, nMI, nH,
        (long long)nMI * nH, (long long)nMI * nH, -1);

    rmsnorm1_kernel<<<nT, 256>>>(hs, ln1);

    // Fused QKV projection (half out, N=3072)
    launch_gemm(xnh, nH, wqkvT, nH, nullptr, qkv, nQKV, nullptr,
                nT, nQKV, nH, 0, 1, 0, 0, dim3(24, 32, 1));

    rope_kernel<<<(nT * (nNH + nNKV) * 64) / 256, 256>>>(cosb, sinb);
    vtrans_kernel<<<dim3(nS / 32, nDH / 32, nB * nNKV), 256>>>();

    // fused attention
    flash_kernel<<<dim3(nS / 128, nB * nNH), 256, FA_BYTES>>>();

    // hidden = attn @ wo + residual (fp32)
    launch_gemm(at, nH, woT, nH, hid, nullptr, nH, hs,
                nT, nH, nH, 0, 0, 0, 0, dim3(16, 32, 1));

    rmsnorm2_kernel<<<nT, 256>>>(ln2, out);   // also: out = hidden
    router_kernel<<<nT, 256>>>(rw);

    count_kernel<<<nT / 256, 256>>>();
    scan_kernel<<<1, 1>>>();
    scatter_kernel<<<nT / 256, 256>>>();

    // MoE: fused gate+up (interleaved, silu in epilogue) -> ubuf (half)
    launch_gemm(x2h, nH, guT, nH, nullptr, ub, nMI, nullptr,
                GR, nGU, nH, 1, 0, 1, 0, dim3(22, MAXTILE, 1));
    // down: scatter-add into out
    launch_gemm(ub, nMI, dwT, nMI, out, nullptr, nH, nullptr,
                GR, nH, nMI, 2, 0, 0, 1, dim3(16, MAXTILE, 1));
}

// round 12
// speedup vs baseline: 2.2982x; 1.1119x over previous
#include <cuda_runtime.h>
#include <cuda_fp16.h>
#include <math.h>
#include <stdint.h>

// ---------------------------------------------------------------------------
// Problem constants
// ---------------------------------------------------------------------------
namespace {
constexpr int nB = 2, nS = 2048, nH = 2048, nNH = 16, nNKV = 4, nDH = 128;
constexpr int nE = 8, nMI = 1408;
constexpr int nT = nB * nS;          // 4096 tokens
constexpr int GR = nT * 2;           // 8192 gathered (token, expert) rows
constexpr int MAXTILE = 72;
constexpr int nQKV = (nNH + 2 * nNKV) * nDH;       // 3072 fused qkv width
constexpr int KOFF = nNH * nDH;                    // 2048
constexpr int VOFF = KOFF + nNKV * nDH;            // 2560
constexpr int nGU = 2 * nMI;                       // 2816 interleaved gate|up
constexpr float RMS_EPS = 1e-6f;
constexpr float QK_SCALE = 0.088388347648318447f;  // 1/sqrt(128)

// GEMM smem (half indices): 3 stages x (A 128x72 + B 128x72)
constexpr int G_HALFS = 55296;
constexpr int SMEM_BYTES = G_HALFS * 2;            // 110592

// flash smem (half indices)
constexpr int FA_QS = 0;                 // Q  [128][136]
constexpr int FA_KS = 17408;             // K  [64][136]
constexpr int FA_VS = 26112;             // V^T 2 x [128][72]
constexpr int FA_PS = 44544;             // P  [128][72]
constexpr int FA_END = 53760;            // halfs
constexpr int FA_RMf = FA_END / 2;       // float idx: rowmax [128][2]
constexpr int FA_RLf = FA_RMf + 256;     // float idx: rowsum [128][2]
constexpr int FA_BYTES = (FA_RLf + 256) * 4;   // 109568
}

// ---------------------------------------------------------------------------
// Scratch (device globals)
// ---------------------------------------------------------------------------
__device__ __half g_xnh  [(size_t)nT * nH];
__device__ float  g_xf   [(size_t)nT * nH];
__device__ __half g_qkv  [(size_t)nT * nQKV];
__device__ __half g_vT   [(size_t)nB * nNKV * nDH * nS];
__device__ __half g_attn [(size_t)nT * nH];
__device__ float  g_hidden[(size_t)nT * nH];
__device__ __half g_x2h  [(size_t)nT * nH];
__device__ int    g_topi [nT * 2];
__device__ float  g_topw [nT * 2];
__device__ int    g_counts[nE];
__device__ int    g_fill [nE];
__device__ int    g_coff [nE + 1];
__device__ int    g_tileE[MAXTILE];
__device__ int    g_tileR0[MAXTILE];
__device__ int    g_toklist[GR];
__device__ float  g_slotw[GR];
__device__ __half g_ubuf [(size_t)GR * nMI];
// transposed weights [N][K] K-major, fp16
__device__ __half g_wqkvT[(size_t)nQKV * nH];
__device__ __half g_woT [(size_t)nH * nH];
__device__ __half g_guT [(size_t)nE * nGU * nH];
__device__ __half g_dwT [(size_t)nE * nH * nMI];

// ---------------------------------------------------------------------------
// Helpers
// ---------------------------------------------------------------------------
__device__ __forceinline__ uint32_t smem_to_u32(const void* p) {
    uint32_t a;
    asm("{ .reg .u64 t; cvta.to.shared.u64 t, %1; cvt.u32.u64 %0, t; }" : "=r"(a) : "l"(p));
    return a;
}
__device__ __forceinline__ uint32_t pack2h(float x, float y) {
    __half2 h = __floats2half2_rn(x, y);
    return *reinterpret_cast<uint32_t*>(&h);
}
__device__ __forceinline__ void mma_f16(float* d, const uint32_t* a, const uint32_t* b) {
    asm volatile("mma.sync.aligned.m16n8k16.row.col.f32.f16.f16.f32 "
        "{%0,%1,%2,%3}, {%4,%5,%6,%7}, {%8,%9}, {%0,%1,%2,%3};"
        : "+f"(d[0]), "+f"(d[1]), "+f"(d[2]), "+f"(d[3])
        : "r"(a[0]), "r"(a[1]), "r"(a[2]), "r"(a[3]), "r"(b[0]), "r"(b[1]));
}
__device__ __forceinline__ void ldsm4(uint32_t* r, uint32_t addr) {
    asm volatile("ldmatrix.sync.aligned.m8n8.x4.shared.b16 {%0,%1,%2,%3}, [%4];"
        : "=r"(r[0]), "=r"(r[1]), "=r"(r[2]), "=r"(r[3]) : "r"(addr));
}
__device__ __forceinline__ float warpSum(float v) {
    #pragma unroll
    for (int o = 16; o; o >>= 1) v += __shfl_xor_sync(0xffffffffu, v, o);
    return v;
}
__device__ __forceinline__ float siluf(float x) {
    return x * (1.f / (1.f + expf(-x)));
}

// ---------------------------------------------------------------------------
// fp16 mma GEMM with ldmatrix fragment loads.
// C[M,N] = A[M,K](half,K-major) x B[N,K](half,K-major)
// CTA tile 128x128, K-chunks of 64, 3-stage cp.async pipeline, 256 threads.
// ---------------------------------------------------------------------------
struct GArgs {
    const __half* A; const __half* B;
    float* Cf; __half* Ch;
    const float* resf;
    long long lda, ldb, ldc;
    int M, N, K;
    int mode;     // 0 normal, 1 moe gather-A, 2 moe no-gather
    int outHalf;
    int fuseSilu;
    int scatter;
};

__global__ void __launch_bounds__(256) tc_gemm(GArgs g) {
    extern __shared__ __half gsm[];
    const int tid = threadIdx.x, lane = tid & 31, wid = tid >> 5;
    const int wm = wid & 3, wn = wid >> 2;
    const int gq = lane >> 2, qq = lane & 3;
    // ldmatrix lane addressing
    const int l15 = lane & 15, lhi = lane >> 4;            // A: row sel, k-half sel
    const int blr = (lane & 7) + ((lane >> 4) << 3);       // B: row within 16-row pair
    const int bco = ((lane >> 3) & 1) * 8;                 // B: k-half offset (halfs)

    int m0, Mb;
    const __half* Ab = g.A;
    const __half* Bb = g.B;
    if (g.mode >= 1) {
        int e = g_tileE[blockIdx.y];
        if (e < 0) return;
        m0 = g_tileR0[blockIdx.y];
        Mb = g_coff[e + 1];
        Bb += (size_t)e * g.N * g.K;
    } else {
        m0 = blockIdx.y * 128;
        Mb = g.M;
    }
    const int n0 = blockIdx.x * 128;

    __shared__ int rt[128];
    if (tid < 128) {
        int m = m0 + tid;
        int r = (m < Mb) ? m : -1;
        if (g.mode == 1 && r >= 0) r = g_toklist[r];
        rt[tid] = r;
    }
    __syncthreads();

    const uint32_t sbase = smem_to_u32(gsm);
    const int NC = g.K >> 6;

    auto issue = [&](int c, int s) {
        const int k0 = c << 6;
        const uint32_t ao = (uint32_t)(s * 9216);
        const uint32_t bo = (uint32_t)(27648 + s * 9216);
        #pragma unroll
        for (int p = 0; p < 4; p++) {
            int idx = p * 256 + tid;
            int row = idx >> 3, c8 = idx & 7;
            int r = rt[row];
            const __half* src = (r >= 0 ? Ab + (size_t)r * g.lda : Ab) + k0 + c8 * 8;
            uint32_t dst = sbase + (ao + (uint32_t)(row * 72 + c8 * 8)) * 2u;
            int sz = (r >= 0) ? 16 : 0;
            asm volatile("cp.async.cg.shared.global [%0], [%1], 16, %2;"
                         :: "r"(dst), "l"(src), "r"(sz) : "memory");
        }
        #pragma unroll
        for (int p = 0; p < 4; p++) {
            int idx = p * 256 + tid;
            int row = idx >> 3, c8 = idx & 7;
            const __half* src = Bb + (size_t)(n0 + row) * g.ldb + k0 + c8 * 8;
            uint32_t dst = sbase + (bo + (uint32_t)(row * 72 + c8 * 8)) * 2u;
            asm volatile("cp.async.cg.shared.global [%0], [%1], 16, %2;"
                         :: "r"(dst), "l"(src), "r"(16) : "memory");
        }
    };

    float acc[2][8][4] = {};

    issue(0, 0);
    asm volatile("cp.async.commit_group;" ::: "memory");
    issue(1, 1);
    asm volatile("cp.async.commit_group;" ::: "memory");

    // per-lane ldmatrix base offsets (halfs, before stage offset)
    const uint32_t aLane = (uint32_t)((wm * 32 + l15) * 72 + lhi * 8);
    uint32_t bLane[4];
    #pragma unroll
    for (int p = 0; p < 4; p++)
        bLane[p] = (uint32_t)((wn * 64 + p * 16 + blr) * 72 + bco);

    for (int c = 0; c < NC; c++) {
        const int s = c % 3;
        asm volatile("cp.async.wait_group 1;" ::: "memory");
        __syncthreads();
        if (c + 2 < NC) issue(c + 2, (c + 2) % 3);
        asm volatile("cp.async.commit_group;" ::: "memory");

        const uint32_t Aad = sbase + ((uint32_t)(s * 9216) + aLane) * 2u;
        const uint32_t Bad = sbase + (uint32_t)(27648 + s * 9216) * 2u;
        #pragma unroll
        for (int kk = 0; kk < 4; kk++) {
            uint32_t af[2][4], bf[4][4];
            ldsm4(af[0], Aad + kk * 32);
            ldsm4(af[1], Aad + 16 * 144 + kk * 32);
            #pragma unroll
            for (int p = 0; p < 4; p++)
                ldsm4(bf[p], Bad + bLane[p] * 2u + kk * 32);
            #pragma unroll
            for (int mt = 0; mt < 2; mt++)
                #pragma unroll
                for (int p = 0; p < 4; p++) {
                    mma_f16(acc[mt][2 * p],     af[mt], &bf[p][0]);
                    mma_f16(acc[mt][2 * p + 1], af[mt], &bf[p][2]);
                }
        }
    }

    // Epilogue
    #pragma unroll
    for (int mt = 0; mt < 2; mt++) {
        #pragma unroll
        for (int half_ = 0; half_ < 2; half_++) {
            int r = m0 + wm * 32 + mt * 16 + half_ * 8 + gq;
            if (r >= Mb) continue;
            if (g.fuseSilu) {
                #pragma unroll
                for (int nt = 0; nt < 8; nt += 2) {
                    float g0 = acc[mt][nt][half_ * 2 + 0];
                    float g1 = acc[mt][nt][half_ * 2 + 1];
                    float u0 = acc[mt][nt + 1][half_ * 2 + 0];
                    float u1 = acc[mt][nt + 1][half_ * 2 + 1];
                    int cint = n0 + wn * 64 + nt * 8;
                    int L = ((cint) >> 4) * 8 + 2 * qq;
                    *reinterpret_cast<uint32_t*>(g.Ch + (size_t)r * g.ldc + L) =
                        pack2h(siluf(g0) * u0, siluf(g1) * u1);
                }
            } else if (g.scatter) {
                int tok = g_toklist[r];
                float w = g_slotw[r];
                float* orow = g.Cf + (size_t)tok * g.ldc;
                const int cb = n0 + wn * 64 + 2 * qq;
                #pragma unroll
                for (int nt = 0; nt < 8; nt++) {
                    atomicAdd(&orow[cb + nt * 8],     w * acc[mt][nt][half_ * 2 + 0]);
                    atomicAdd(&orow[cb + nt * 8 + 1], w * acc[mt][nt][half_ * 2 + 1]);
                }
            } else {
                const int cb = n0 + wn * 64 + 2 * qq;
                #pragma unroll
                for (int nt = 0; nt < 8; nt++) {
                    float vx = acc[mt][nt][half_ * 2 + 0];
                    float vy = acc[mt][nt][half_ * 2 + 1];
                    int col = cb + nt * 8;
                    if (g.outHalf) {
                        *reinterpret_cast<uint32_t*>(g.Ch + (size_t)r * g.ldc + col) = pack2h(vx, vy);
                    } else {
                        if (g.resf) {
                            float2 rv = *reinterpret_cast<const float2*>(g.resf + (size_t)r * g.ldc + col);
                            vx += rv.x; vy += rv.y;
                        }
                        *reinterpret_cast<float2*>(g.Cf + (size_t)r * g.ldc + col) = make_float2(vx, vy);
                    }
                }
            }
        }
    }
}

// ---------------------------------------------------------------------------
// Fused flash attention, fp16 operands / fp32 softmax+accum, ldmatrix loads.
// ---------------------------------------------------------------------------
__global__ void __launch_bounds__(256) flash_kernel() {
    extern __shared__ __half fh[];
    float* ff = reinterpret_cast<float*>(fh);
    const int tid = threadIdx.x, lane = tid & 31, wid = tid >> 5;
    const int wm = wid & 3, wn = wid >> 2;
    const int gq = lane >> 2, qq = lane & 3;
    const int l15 = lane & 15, lhi = lane >> 4;
    const int blr = (lane & 7) + ((lane >> 4) << 3);
    const int bco = ((lane >> 3) & 1) * 8;
    const int bh = blockIdx.y, b = bh >> 4, h = bh & 15, kh = h >> 2;
    const int q0 = blockIdx.x * 128;

    const __half* Qg = g_qkv + ((size_t)(b * nS + q0)) * nQKV + h * nDH;
    const __half* Kg = g_qkv + (size_t)b * nS * nQKV + KOFF + kh * nDH;
    const __half* Vt = g_vT + ((size_t)(b * nNKV + kh)) * nDH * nS;
    __half* Og = g_attn + ((size_t)(b * nS + q0)) * nH + h * nDH;

    const uint32_t sb = smem_to_u32(fh);

    #pragma unroll
    for (int p = 0; p < 8; p++) {
        int idx = p * 256 + tid;
        int row = idx >> 4, c8 = idx & 15;
        uint32_t dst = sb + (uint32_t)(FA_QS + row * 136 + c8 * 8) * 2u;
        const __half* src = Qg + (size_t)row * nQKV + c8 * 8;
        asm volatile("cp.async.cg.shared.global [%0], [%1], 16;"
                     :: "r"(dst), "l"(src) : "memory");
    }
    asm volatile("cp.async.commit_group;" ::: "memory");

    auto issueKV = [&](int it2) {
        const __half* kg = Kg + (size_t)(it2 * 64) * nQKV;
        const __half* vg = Vt + it2 * 64;
        const int vb = FA_VS + (it2 & 1) * 9216;
        #pragma unroll
        for (int p = 0; p < 4; p++) {
            int idx = p * 256 + tid;
            int row = idx >> 4, c8 = idx & 15;
            uint32_t dk = sb + (uint32_t)(FA_KS + row * 136 + c8 * 8) * 2u;
            asm volatile("cp.async.cg.shared.global [%0], [%1], 16;"
                         :: "r"(dk), "l"(kg + (size_t)row * nQKV + c8 * 8) : "memory");
        }
        #pragma unroll
        for (int p = 0; p < 4; p++) {
            int idx = p * 256 + tid;
            int row = idx >> 3, c8 = idx & 7;
            uint32_t dv = sb + (uint32_t)(vb + row * 72 + c8 * 8) * 2u;
            asm volatile("cp.async.cg.shared.global [%0], [%1], 16;"
                         :: "r"(dv), "l"(vg + (size_t)row * nS + c8 * 8) : "memory");
        }
    };
    issueKV(0);
    asm volatile("cp.async.commit_group;" ::: "memory");

    float accO[2][8][4] = {};
    float rm[2][2] = {{-1e30f, -1e30f}, {-1e30f, -1e30f}};
    float rl[2][2] = {{0.f, 0.f}, {0.f, 0.f}};
    const int PSu = FA_PS / 2;

    // ldmatrix lane bases (bytes)
    const uint32_t QA = sb + (uint32_t)(FA_QS + (wm * 32 + l15) * 136 + lhi * 8) * 2u;
    uint32_t KB[2];
    #pragma unroll
    for (int p = 0; p < 2; p++)
        KB[p] = sb + (uint32_t)(FA_KS + (wn * 32 + p * 16 + blr) * 136 + bco) * 2u;
    const uint32_t PA = sb + (uint32_t)(FA_PS + (wm * 32 + l15) * 72 + lhi * 8) * 2u;
    uint32_t VBl[4];
    #pragma unroll
    for (int p = 0; p < 4; p++)
        VBl[p] = (uint32_t)((wn * 64 + p * 16 + blr) * 72 + bco) * 2u;

    for (int it = 0; it < nS / 64; it++) {
        asm volatile("cp.async.wait_group 0;" ::: "memory");
        __syncthreads();

        // --- S = Q x K^T ---
        float S[2][4][4] = {};
        #pragma unroll
        for (int kc = 0; kc < 8; kc++) {
            uint32_t af[2][4], bf[2][4];
            ldsm4(af[0], QA + kc * 32);
            ldsm4(af[1], QA + 16 * 272 + kc * 32);
            ldsm4(bf[0], KB[0] + kc * 32);
            ldsm4(bf[1], KB[1] + kc * 32);
            #pragma unroll
            for (int mt = 0; mt < 2; mt++)
                #pragma unroll
                for (int p = 0; p < 2; p++) {
                    mma_f16(S[mt][2 * p],     af[mt], &bf[p][0]);
                    mma_f16(S[mt][2 * p + 1], af[mt], &bf[p][2]);
                }
        }
        __syncthreads();
        if (it + 1 < nS / 64) issueKV(it + 1);
        asm volatile("cp.async.commit_group;" ::: "memory");

        float tmax[2][2] = {{-1e30f, -1e30f}, {-1e30f, -1e30f}};
        #pragma unroll
        for (int mt = 0; mt < 2; mt++)
            #pragma unroll
            for (int nt = 0; nt < 4; nt++)
                #pragma unroll
                for (int c = 0; c < 4; c++) {
                    S[mt][nt][c] *= QK_SCALE;
                    tmax[mt][c >> 1] = fmaxf(tmax[mt][c >> 1], S[mt][nt][c]);
                }
        #pragma unroll
        for (int mt = 0; mt < 2; mt++)
            #pragma unroll
            for (int hf = 0; hf < 2; hf++) {
                float v = tmax[mt][hf];
                v = fmaxf(v, __shfl_xor_sync(0xffffffffu, v, 1));
                v = fmaxf(v, __shfl_xor_sync(0xffffffffu, v, 2));
                tmax[mt][hf] = v;
            }
        if (qq == 0) {
            #pragma unroll
            for (int mt = 0; mt < 2; mt++)
                #pragma unroll
                for (int hf = 0; hf < 2; hf++)
                    ff[FA_RMf + (wm * 32 + mt * 16 + hf * 8 + gq) * 2 + wn] = tmax[mt][hf];
        }
        __syncthreads();

        float newm[2][2], sco[2][2];
        #pragma unroll
        for (int mt = 0; mt < 2; mt++)
            #pragma unroll
            for (int hf = 0; hf < 2; hf++) {
                int r = wm * 32 + mt * 16 + hf * 8 + gq;
                float tm = fmaxf(ff[FA_RMf + r * 2], ff[FA_RMf + r * 2 + 1]);
                float nm = fmaxf(rm[mt][hf], tm);
                sco[mt][hf] = __expf(rm[mt][hf] - nm);
                newm[mt][hf] = nm;
                rm[mt][hf] = nm;
            }

        float ps[2][2] = {{0.f, 0.f}, {0.f, 0.f}};
        uint32_t* Pw = reinterpret_cast<uint32_t*>(fh);
        #pragma unroll
        for (int mt = 0; mt < 2; mt++) {
            int r0 = wm * 32 + mt * 16 + gq;
            #pragma unroll
            for (int nt = 0; nt < 4; nt++) {
                int ci = wn * 16 + nt * 4 + qq;
                float p0 = __expf(S[mt][nt][0] - newm[mt][0]);
                float p1 = __expf(S[mt][nt][1] - newm[mt][0]);
                float p2 = __expf(S[mt][nt][2] - newm[mt][1]);
                float p3 = __expf(S[mt][nt][3] - newm[mt][1]);
                ps[mt][0] += p0 + p1;
                ps[mt][1] += p2 + p3;
                Pw[PSu + r0 * 36 + ci] = pack2h(p0, p1);
                Pw[PSu + (r0 + 8) * 36 + ci] = pack2h(p2, p3);
            }
        }
        #pragma unroll
        for (int mt = 0; mt < 2; mt++)
            #pragma unroll
            for (int hf = 0; hf < 2; hf++) {
                float v = ps[mt][hf];
                v += __shfl_xor_sync(0xffffffffu, v, 1);
                v += __shfl_xor_sync(0xffffffffu, v, 2);
                ps[mt][hf] = v;
            }
        if (qq == 0) {
            #pragma unroll
            for (int mt = 0; mt < 2; mt++)
                #pragma unroll
                for (int hf = 0; hf < 2; hf++)
                    ff[FA_RLf + (wm * 32 + mt * 16 + hf * 8 + gq) * 2 + wn] = ps[mt][hf];
        }
        __syncthreads();

        #pragma unroll
        for (int mt = 0; mt < 2; mt++)
            #pragma unroll
            for (int hf = 0; hf < 2; hf++) {
                int r = wm * 32 + mt * 16 + hf * 8 + gq;
                float ts = ff[FA_RLf + r * 2] + ff[FA_RLf + r * 2 + 1];
                rl[mt][hf] = rl[mt][hf] * sco[mt][hf] + ts;
            }
        #pragma unroll
        for (int mt = 0; mt < 2; mt++)
            #pragma unroll
            for (int nt = 0; nt < 8; nt++) {
                accO[mt][nt][0] *= sco[mt][0];
                accO[mt][nt][1] *= sco[mt][0];
                accO[mt][nt][2] *= sco[mt][1];
                accO[mt][nt][3] *= sco[mt][1];
            }

        // --- O += P x V ---
        const uint32_t Vad = sb + (uint32_t)(FA_VS + (it & 1) * 9216) * 2u;
        #pragma unroll
        for (int kc = 0; kc < 4; kc++) {
            uint32_t af[2][4], bf[4][4];
            ldsm4(af[0], PA + kc * 32);
            ldsm4(af[1], PA + 16 * 144 + kc * 32);
            #pragma unroll
            for (int p = 0; p < 4; p++)
                ldsm4(bf[p], Vad + VBl[p] + kc * 32);
            #pragma unroll
            for (int mt = 0; mt < 2; mt++)
                #pragma unroll
                for (int p = 0; p < 4; p++) {
                    mma_f16(accO[mt][2 * p],     af[mt], &bf[p][0]);
                    mma_f16(accO[mt][2 * p + 1], af[mt], &bf[p][2]);
                }
        }
    }

    #pragma unroll
    for (int mt = 0; mt < 2; mt++)
        #pragma unroll
        for (int hf = 0; hf < 2; hf++) {
            int r = wm * 32 + mt * 16 + hf * 8 + gq;
            float inv = 1.f / rl[mt][hf];
            #pragma unroll
            for (int nt = 0; nt < 8; nt++) {
                int col = wn * 64 + nt * 8 + 2 * qq;
                *reinterpret_cast<uint32_t*>(Og + (size_t)r * nH + col) =
                    pack2h(accO[mt][nt][hf * 2 + 0] * inv, accO[mt][nt][hf * 2 + 1] * inv);
            }
        }
}

// ---------------------------------------------------------------------------
// Weight transpose fp32->fp16, 64k x 128n tile, optional gate/up interleave.
// ---------------------------------------------------------------------------
__global__ void __launch_bounds__(256) transpose_kernel(
    const float* __restrict__ in, __half* __restrict__ out, int K, int N,
    long long srcZ, long long dstZ, int remapOfs) {
    __shared__ float t[64][137];
    const float* ip = in + (size_t)blockIdx.z * srcZ;
    __half* op = out + (size_t)blockIdx.z * dstZ;
    const int n0 = blockIdx.x * 128, k0 = blockIdx.y * 64;
    const int tid = threadIdx.x;
    const int rr = tid >> 5, rc = tid & 31;
    #pragma unroll
    for (int p = 0; p < 8; p++) {
        int kk = rr + p * 8;
        float4 v = *reinterpret_cast<const float4*>(ip + (size_t)(k0 + kk) * N + n0 + rc * 4);
        t[kk][rc * 4 + 0] = v.x; t[kk][rc * 4 + 1] = v.y;
        t[kk][rc * 4 + 2] = v.z; t[kk][rc * 4 + 3] = v.w;
    }
    __syncthreads();
    const int wr = tid >> 3, wk8 = (tid & 7) * 8;
    #pragma unroll
    for (int p = 0; p < 4; p++) {
        int nn = wr + p * 32;
        int ng = n0 + nn;
        int nd = (remapOfs < 0) ? ng : ((ng >> 3) << 4) + (ng & 7) + remapOfs;
        __half hv[8];
        #pragma unroll
        for (int j = 0; j < 8; j++) hv[j] = __float2half_rn(t[wk8 + j][nn]);
        *reinterpret_cast<uint4*>(op + (size_t)nd * K + k0 + wk8) =
            *reinterpret_cast<uint4*>(hv);
    }
}

// V transpose (half): g_qkv v-section -> g_vT [(b*4+kh)][dh][S]
__global__ void vtrans_kernel() {
    __shared__ __half t[32][33];
    int z = blockIdx.z, b = z >> 2, kh = z & 3;
    int s0 = blockIdx.x * 32, d0 = blockIdx.y * 32;
    int tx = threadIdx.x & 31, ty = threadIdx.x >> 5;
    #pragma unroll
    for (int i = ty; i < 32; i += 8)
        t[i][tx] = g_qkv[((size_t)(b * nS + s0 + i)) * nQKV + VOFF + kh * nDH + d0 + tx];
    __syncthreads();
    #pragma unroll
    for (int i = ty; i < 32; i += 8)
        g_vT[((size_t)z * nDH + d0 + i) * nS + s0 + tx] = t[tx][i];
}

// ---------------------------------------------------------------------------
// RMSNorm. rmsnorm1 -> half. rmsnorm2 -> half + float (router) + out init.
// ---------------------------------------------------------------------------
template <bool DUAL>
__device__ __forceinline__ void rmsnorm_row(const float* __restrict__ x,
                                            const float* __restrict__ w,
                                            __half* __restrict__ out_h,
                                            float* __restrict__ out_f,
                                            float* __restrict__ out_cp) {
    int row = blockIdx.x;
    const float* xr = x + (size_t)row * nH;
    float ss = 0.f;
    for (int i = threadIdx.x; i < nH; i += blockDim.x) { float v = xr[i]; ss += v * v; }
    __shared__ float sm[8];
    int lane = threadIdx.x & 31, wid = threadIdx.x >> 5;
    ss = warpSum(ss);
    if (lane == 0) sm[wid] = ss;
    __syncthreads();
    if (wid == 0) {
        float v = (lane < 8) ? sm[lane] : 0.f;
        v = warpSum(v);
        if (lane == 0) sm[0] = rsqrtf(v / (float)nH + RMS_EPS);
    }
    __syncthreads();
    float inv = sm[0];
    for (int i = threadIdx.x; i < nH; i += blockDim.x) {
        float xi = xr[i];
        float v = xi * inv * w[i];
        out_h[(size_t)row * nH + i] = __float2half_rn(v);
        if (DUAL) {
            out_f[(size_t)row * nH + i] = v;
            out_cp[(size_t)row * nH + i] = xi;
        }
    }
}
__global__ void rmsnorm1_kernel(const float* __restrict__ hs, const float* __restrict__ w) {
    rmsnorm_row<false>(hs, w, g_xnh, nullptr, nullptr);
}
__global__ void rmsnorm2_kernel(const float* __restrict__ w, float* __restrict__ out) {
    rmsnorm_row<true>(g_hidden, w, g_x2h, g_xf, out);
}

// ---------------------------------------------------------------------------
// RoPE on fused qkv (fp32 math). Only q and k sections.
// ---------------------------------------------------------------------------
__global__ void rope_kernel(const float* __restrict__ cosb, const float* __restrict__ sinb) {
    int i = blockIdx.x * blockDim.x + threadIdx.x;
    if (i >= nT * (nNH + nNKV) * 64) return;
    int d  = i & 63;
    int hh = (i >> 6) % (nNH + nNKV);
    int t  = i / (64 * (nNH + nNKV));
    __half* ptr = g_qkv + (size_t)t * nQKV +
                  (hh < nNH ? hh * nDH : KOFF + (hh - nNH) * nDH);
    float x1 = __half2float(ptr[d]), x2 = __half2float(ptr[d + 64]);
    const float* cr = cosb + (size_t)t * nDH;
    const float* sr = sinb + (size_t)t * nDH;
    ptr[d]      = __float2half_rn(x1 * cr[d]      - x2 * sr[d]);
    ptr[d + 64] = __float2half_rn(x2 * cr[d + 64] + x1 * sr[d + 64]);
}

// ---------------------------------------------------------------------------
// Router (UNROUNDED fp32 input)
// ---------------------------------------------------------------------------
__global__ void router_kernel(const float* __restrict__ rw) {
    __shared__ float xs[nH];
    __shared__ float lg[nE];
    int t = blockIdx.x;
    for (int i = threadIdx.x; i < nH; i += blockDim.x) xs[i] = g_xf[(size_t)t * nH + i];
    __syncthreads();
    int w = threadIdx.x >> 5, lane = threadIdx.x & 31;
    float s = 0.f;
    for (int i = lane; i < nH; i += 32) s += xs[i] * rw[(size_t)i * nE + w];
    s = warpSum(s);
    if (lane == 0) lg[w] = s;
    __syncthreads();
    if (threadIdx.x == 0) {
        float mx = lg[0];
        #pragma unroll
        for (int e = 1; e < nE; e++) mx = fmaxf(mx, lg[e]);
        float p[nE]; float sum = 0.f;
        #pragma unroll
        for (int e = 0; e < nE; e++) { p[e] = expf(lg[e] - mx); sum += p[e]; }
        #pragma unroll
        for (int e = 0; e < nE; e++) p[e] /= sum;
        int i1 = 0;
        #pragma unroll
        for (int e = 1; e < nE; e++) if (p[e] > p[i1]) i1 = e;
        int i2 = (i1 == 0) ? 1 : 0;
        #pragma unroll
        for (int e = 0; e < nE; e++) if (e != i1 && p[e] > p[i2]) i2 = e;
        float s2 = p[i1] + p[i2];
        g_topi[t * 2] = i1; g_topi[t * 2 + 1] = i2;
        g_topw[t * 2] = p[i1] / s2; g_topw[t * 2 + 1] = p[i2] / s2;
    }
}

// ---------------------------------------------------------------------------
// MoE bookkeeping
// ---------------------------------------------------------------------------
__global__ void reset_kernel() {
    int i = threadIdx.x;
    if (i < nE) { g_counts[i] = 0; g_fill[i] = 0; }
}
__global__ void count_kernel() {
    int t = blockIdx.x * blockDim.x + threadIdx.x;
    if (t >= nT) return;
    atomicAdd(&g_counts[g_topi[t * 2]], 1);
    atomicAdd(&g_counts[g_topi[t * 2 + 1]], 1);
}
__global__ void scan_kernel() {
    if (threadIdx.x != 0) return;
    int off = 0, nt = 0;
    for (int e = 0; e < nE; e++) {
        g_coff[e] = off;
        int ne = g_counts[e];
        int ntl = (ne + 127) >> 7;
        for (int i = 0; i < ntl; i++) { g_tileE[nt] = e; g_tileR0[nt] = off + i * 128; nt++; }
        off += ne;
    }
    g_coff[nE] = off;
    for (int i = nt; i < MAXTILE; i++) g_tileE[i] = -1;
}
__global__ void scatter_kernel() {
    int t = blockIdx.x * blockDim.x + threadIdx.x;
    if (t >= nT) return;
    #pragma unroll
    for (int k = 0; k < 2; k++) {
        int e = g_topi[t * 2 + k];
        int pos = g_coff[e] + atomicAdd(&g_fill[e], 1);
        g_toklist[pos] = t;
        g_slotw[pos] = g_topw[t * 2 + k];
    }
}

// ---------------------------------------------------------------------------
// Launch
// ---------------------------------------------------------------------------
static void launch_gemm(const __half* A, long long lda, const __half* B, long long ldb,
                        float* Cf, __half* Ch, long long ldc, const float* resf,
                        int M, int N, int K, int mode, int outHalf, int fuseSilu,
                        int scatter, dim3 grid) {
    GArgs g;
    g.A = A; g.B = B; g.Cf = Cf; g.Ch = Ch; g.resf = resf;
    g.lda = lda; g.ldb = ldb; g.ldc = ldc;
    g.M = M; g.N = N; g.K = K;
    g.mode = mode; g.outHalf = outHalf; g.fuseSilu = fuseSilu; g.scatter = scatter;
    tc_gemm<<<grid, 256, SMEM_BYTES>>>(g);
}

extern "C" void kernel_launch(void* const* d_in, const int* in_sizes, int n_in,
                              void* d_out, int out_size) {
    const float* hs   = (const float*)d_in[0];
    const float* cosb = (const float*)d_in[1];
    const float* sinb = (const float*)d_in[2];
    const float* wq   = (const float*)d_in[3];
    const float* wk   = (const float*)d_in[4];
    const float* wv   = (const float*)d_in[5];
    const float* wo   = (const float*)d_in[6];
    const float* ln1  = (const float*)d_in[7];
    const float* ln2  = (const float*)d_in[8];
    const float* rw   = (const float*)d_in[9];
    const float* gw   = (const float*)d_in[10];
    const float* uw   = (const float*)d_in[11];
    const float* dw   = (const float*)d_in[12];
    float* out = (float*)d_out;

    static bool attr_set = false;
    if (!attr_set) {
        cudaFuncSetAttribute(tc_gemm, cudaFuncAttributeMaxDynamicSharedMemorySize, SMEM_BYTES);
        cudaFuncSetAttribute(flash_kernel, cudaFuncAttributeMaxDynamicSharedMemorySize, FA_BYTES);
        attr_set = true;
    }

    __half* wqkvT; cudaGetSymbolAddress((void**)&wqkvT, g_wqkvT);
    __half* woT; cudaGetSymbolAddress((void**)&woT, g_woT);
    __half* guT; cudaGetSymbolAddress((void**)&guT, g_guT);
    __half* dwT; cudaGetSymbolAddress((void**)&dwT, g_dwT);
    __half* xnh; cudaGetSymbolAddress((void**)&xnh, g_xnh);
    __half* qkv; cudaGetSymbolAddress((void**)&qkv, g_qkv);
    __half* at;  cudaGetSymbolAddress((void**)&at, g_attn);
    float*  hid; cudaGetSymbolAddress((void**)&hid, g_hidden);
    __half* x2h; cudaGetSymbolAddress((void**)&x2h, g_x2h);
    __half* ub;  cudaGetSymbolAddress((void**)&ub, g_ubuf);

    reset_kernel<<<1, 32>>>();

    // Weight transposes -> [N][K] fp16
    transpose_kernel<<<dim3(16, 32, 1), 256>>>(wq, wqkvT, nH, nNH * nDH, 0, 0, -1);
    transpose_kernel<<<dim3(4, 32, 1), 256>>>(wk, wqkvT + (size_t)KOFF * nH, nH, nNKV * nDH, 0, 0, -1);
    transpose_kernel<<<dim3(4, 32, 1), 256>>>(wv, wqkvT + (size_t)VOFF * nH, nH, nNKV * nDH, 0, 0, -1);
    transpose_kernel<<<dim3(16, 32, 1), 256>>>(wo, woT, nH, nH, 0, 0, -1);
    transpose_kernel<<<dim3(11, 32, nE), 256>>>(gw, guT, nH, nMI,
        (long long)nH * nMI, (long long)nGU * nH, 0);
    transpose_kernel<<<dim3(11, 32, nE), 256>>>(uw, guT, nH, nMI,
        (long long)nH * nMI, (long long)nGU * nH, 8);
    transpose_kernel<<<dim3(16, 22, nE), 256>>>(dw, dwT, nMI, nH,
        (long long)nMI * nH, (long long)nMI * nH, -1);

    rmsnorm1_kernel<<<nT, 256>>>(hs, ln1);

    // Fused QKV projection (half out, N=3072)
    launch_gemm(xnh, nH, wqkvT, nH, nullptr, qkv, nQKV, nullptr,
                nT, nQKV, nH, 0, 1, 0, 0, dim3(24, 32, 1));

    rope_kernel<<<(nT * (nNH + nNKV) * 64) / 256, 256>>>(cosb, sinb);
    vtrans_kernel<<<dim3(nS / 32, nDH / 32, nB * nNKV), 256>>>();

    // fused attention
    flash_kernel<<<dim3(nS / 128, nB * nNH), 256, FA_BYTES>>>();

    // hidden = attn @ wo + residual (fp32)
    launch_gemm(at, nH, woT, nH, hid, nullptr, nH, hs,
                nT, nH, nH, 0, 0, 0, 0, dim3(16, 32, 1));

    rmsnorm2_kernel<<<nT, 256>>>(ln2, out);   // also: out = hidden
    router_kernel<<<nT, 256>>>(rw);

    count_kernel<<<nT / 256, 256>>>();
    scan_kernel<<<1, 1>>>();
    scatter_kernel<<<nT / 256, 256>>>();

    // MoE: fused gate+up (interleaved, silu in epilogue) -> ubuf (half)
    launch_gemm(x2h, nH, guT, nH, nullptr, ub, nMI, nullptr,
                GR, nGU, nH, 1, 0, 1, 0, dim3(22, MAXTILE, 1));
    // down: scatter-add into out
    launch_gemm(ub, nMI, dwT, nMI, out, nullptr, nH, nullptr,
                GR, nH, nMI, 2, 0, 0, 1, dim3(16, MAXTILE, 1));
}